// round 4
// baseline (speedup 1.0000x reference)
#include <cuda_runtime.h>
#include <cuda_bf16.h>
#include <math.h>

// Problem constants
#define BB 2
#define TT 4096
#define CC 1024
#define NH 8
#define DD 128
#define CHK 64
#define NCHUNK 64            // T / CHK
#define NCID 1024            // BB*NH*NCHUNK

// ---------------- scratch (device globals; no allocation allowed) ----------------
__device__ float g_qkvz[(size_t)BB*TT*4096];     // x @ W_qkvz      (B,T,8,512)
__device__ float g_ba[(size_t)BB*TT*16];         // x @ W_ba
__device__ float g_conv[(size_t)BB*TT*3072];     // conv+silu [q|k|v]
__device__ float g_g[(size_t)BB*TT*NH];
__device__ float g_beta[(size_t)BB*TT*NH];
__device__ float g_P[(size_t)NCID*64*128];       // qeff - attn@k_cum
__device__ float g_L[(size_t)NCID*64*128];       // attn@v_new
__device__ float g_M[(size_t)NCID*128*128];      // keff^T @ k_cum
__device__ float g_U[(size_t)NCID*128*128];      // keff^T @ v_new
__device__ float g_egl[NCID];                    // exp(g_last)
__device__ float g_core[(size_t)BB*TT*NH*DD];    // delta-rule output
__device__ float g_hbuf[(size_t)BB*TT*1024];     // post-norm, pre out-proj

// ---------------- bf16 mma helpers -----------------------------------------------
#define MMA_BF16(C, Ar, Br)                                                    \
    asm volatile("mma.sync.aligned.m16n8k16.row.col.f32.bf16.bf16.f32 "        \
        "{%0,%1,%2,%3}, {%4,%5,%6,%7}, {%8,%9}, {%0,%1,%2,%3};"                \
        : "+f"((C)[0]), "+f"((C)[1]), "+f"((C)[2]), "+f"((C)[3])               \
        : "r"((Ar)[0]), "r"((Ar)[1]), "r"((Ar)[2]), "r"((Ar)[3]),              \
          "r"((Br)[0]), "r"((Br)[1]))

// ---------------- 3xBF16-split tensor-core GEMM: C = A(MxK)@B(KxN), row-major ---
// M,N multiples of 128; K multiple of 32. Near-fp32 accuracy via hi/lo split:
// C = Ah*Bh + Al*Bh + Ah*Bl  (dropped terms ~2^-16 relative).
#define GK 40                                    // smem k-stride (20 words: conflict-free)
__global__ __launch_bounds__(256, 1) void bf16gemm128(int M, int N, int K,
        const float* __restrict__ A, const float* __restrict__ Bm, float* __restrict__ Cm)
{
    __shared__ __nv_bfloat16 Ah[128][GK], Al[128][GK];    // [m][k]
    __shared__ __nv_bfloat16 Bth[128][GK], Btl[128][GK];  // [n][k] (transposed)

    int tid = threadIdx.x;
    int brow = blockIdx.y * 128, bcol = blockIdx.x * 128;
    int warp = tid >> 5, lane = tid & 31;
    int wm = (warp & 1) * 64, wn = (warp >> 1) * 32;
    int lr = lane >> 2, lc2 = (lane & 3) * 2;

    float c[4][4][4];
#pragma unroll
    for (int mt = 0; mt < 4; mt++)
#pragma unroll
        for (int nt = 0; nt < 4; nt++)
#pragma unroll
            for (int e = 0; e < 4; e++) c[mt][nt][e] = 0.f;

    for (int k0 = 0; k0 < K; k0 += 32) {
        // stage A tile (128x32) as hi/lo bf16
#pragma unroll
        for (int u = 0; u < 4; u++) {
            int idx = tid + u * 256;
            int r = idx >> 3, cg = (idx & 7) * 4;
            float4 v = *(const float4*)(A + (size_t)(brow + r) * K + k0 + cg);
            float f[4] = {v.x, v.y, v.z, v.w};
#pragma unroll
            for (int e = 0; e < 4; e++) {
                __nv_bfloat16 h = __float2bfloat16_rn(f[e]);
                Ah[r][cg + e] = h;
                Al[r][cg + e] = __float2bfloat16_rn(f[e] - __bfloat162float(h));
            }
        }
        // stage B tile (32x128) transposed -> [n][k]
#pragma unroll
        for (int u = 0; u < 4; u++) {
            int idx = tid + u * 256;
            int kR = idx >> 5, n4 = (idx & 31) * 4;
            float4 v = *(const float4*)(Bm + (size_t)(k0 + kR) * N + bcol + n4);
            float f[4] = {v.x, v.y, v.z, v.w};
#pragma unroll
            for (int e = 0; e < 4; e++) {
                __nv_bfloat16 h = __float2bfloat16_rn(f[e]);
                Bth[n4 + e][kR] = h;
                Btl[n4 + e][kR] = __float2bfloat16_rn(f[e] - __bfloat162float(h));
            }
        }
        __syncthreads();

#pragma unroll
        for (int kk = 0; kk < 32; kk += 16) {
            unsigned ah[4][4], al[4][4], bh[4][2], bl[4][2];
#pragma unroll
            for (int mt = 0; mt < 4; mt++) {
                int r0 = wm + mt * 16 + lr;
                ah[mt][0] = *(const unsigned*)(&Ah[r0][kk + lc2]);
                ah[mt][1] = *(const unsigned*)(&Ah[r0 + 8][kk + lc2]);
                ah[mt][2] = *(const unsigned*)(&Ah[r0][kk + lc2 + 8]);
                ah[mt][3] = *(const unsigned*)(&Ah[r0 + 8][kk + lc2 + 8]);
                al[mt][0] = *(const unsigned*)(&Al[r0][kk + lc2]);
                al[mt][1] = *(const unsigned*)(&Al[r0 + 8][kk + lc2]);
                al[mt][2] = *(const unsigned*)(&Al[r0][kk + lc2 + 8]);
                al[mt][3] = *(const unsigned*)(&Al[r0 + 8][kk + lc2 + 8]);
            }
#pragma unroll
            for (int nt = 0; nt < 4; nt++) {
                int cn = wn + nt * 8 + lr;
                bh[nt][0] = *(const unsigned*)(&Bth[cn][kk + lc2]);
                bh[nt][1] = *(const unsigned*)(&Bth[cn][kk + lc2 + 8]);
                bl[nt][0] = *(const unsigned*)(&Btl[cn][kk + lc2]);
                bl[nt][1] = *(const unsigned*)(&Btl[cn][kk + lc2 + 8]);
            }
#pragma unroll
            for (int mt = 0; mt < 4; mt++)
#pragma unroll
                for (int nt = 0; nt < 4; nt++) {
                    MMA_BF16(c[mt][nt], ah[mt], bh[nt]);
                    MMA_BF16(c[mt][nt], al[mt], bh[nt]);
                    MMA_BF16(c[mt][nt], ah[mt], bl[nt]);
                }
        }
        __syncthreads();
    }

    // epilogue (C fragment: rows lr / lr+8, cols 2*(lane&3)+{0,1})
#pragma unroll
    for (int mt = 0; mt < 4; mt++) {
        int r0 = brow + wm + mt * 16 + lr;
#pragma unroll
        for (int nt = 0; nt < 4; nt++) {
            int cn = bcol + wn + nt * 8 + lc2;
            *(float2*)(Cm + (size_t)r0 * N + cn)       = make_float2(c[mt][nt][0], c[mt][nt][1]);
            *(float2*)(Cm + (size_t)(r0 + 8) * N + cn) = make_float2(c[mt][nt][2], c[mt][nt][3]);
        }
    }
}

// ---------------- ba = x @ W_ba (N = 16) ----------------------------------------
__global__ __launch_bounds__(256) void ba_kernel(const float* __restrict__ x,
        const float* __restrict__ Wba, float* __restrict__ out)
{
    int bt = blockIdx.x;
    __shared__ float xs[1024];
    const float* xrow = x + (size_t)bt * 1024;
    for (int i = threadIdx.x; i < 256; i += 256)
        ((float4*)xs)[i] = ((const float4*)xrow)[i];
    __syncthreads();
    int o = threadIdx.x >> 4, p = threadIdx.x & 15;
    float acc = 0.f;
    for (int k = p; k < 1024; k += 16) acc += xs[k] * Wba[(size_t)k * 16 + o];
    acc += __shfl_down_sync(0xffffffffu, acc, 8);
    acc += __shfl_down_sync(0xffffffffu, acc, 4);
    acc += __shfl_down_sync(0xffffffffu, acc, 2);
    acc += __shfl_down_sync(0xffffffffu, acc, 1);
    if (p == 0) out[(size_t)bt * 16 + o] = acc;
}

// ---------------- causal depthwise conv (K=4) + silu ----------------------------
__global__ __launch_bounds__(256) void conv_silu_kernel(const float* __restrict__ qkvz,
        const float* __restrict__ cw, float* __restrict__ out)
{
    int idx = blockIdx.x * 256 + threadIdx.x;
    int ch = idx % 3072;
    int btrow = idx / 3072;
    int t = btrow & (TT - 1);
    int part = ch >> 10;
    int hc = (ch & 1023) >> 7;
    int d = ch & 127;
    int po = (part == 0) ? 0 : (part == 1) ? 128 : 256;
    float acc = 0.f;
#pragma unroll
    for (int j = 0; j < 4; j++) {
        int tt2 = t - 3 + j;
        if (tt2 >= 0) {
            float v = qkvz[(((size_t)(btrow - 3 + j)) * 8 + hc) * 512 + po + d];
            acc += v * cw[ch * 4 + j];
        }
    }
    out[(size_t)idx] = acc / (1.f + __expf(-acc));
}

// ---------------- g, beta --------------------------------------------------------
__global__ __launch_bounds__(256) void gbeta_kernel(const float* __restrict__ ba,
        const float* __restrict__ dtb, const float* __restrict__ Alog,
        float* __restrict__ g, float* __restrict__ beta)
{
    int idx = blockIdx.x * 256 + threadIdx.x;
    int h = idx & 7;
    int bt = idx >> 3;
    float bv = ba[(size_t)bt * 16 + h * 2];
    float av = ba[(size_t)bt * 16 + h * 2 + 1];
    beta[idx] = 1.f / (1.f + expf(-bv));
    float xx = av + dtb[h];
    float sp = (xx > 20.f) ? xx : log1pf(expf(xx));
    g[idx] = -expf(Alog[h]) * sp;
}

// ---------------- Phase A: per-chunk local operators (register-tiled) -----------
#define KST 68                                  // transposed stride for kst/qst
#define PA_SMEM ((128*KST*2 + 64*256 + 64*64 + 256) * 4)

__global__ __launch_bounds__(256) void phaseA_kernel(const float* __restrict__ conv,
        const float* __restrict__ gbuf, const float* __restrict__ betabuf,
        float* __restrict__ Pout, float* __restrict__ Lout,
        float* __restrict__ Mout, float* __restrict__ Uout, float* __restrict__ eglout)
{
    extern __shared__ float sm[];
    float* kst = sm;                  // [128][KST]  kst[d*KST + i] = k_norm[i][d]
    float* qst = kst + 128 * KST;     // [128][KST]  q_norm (incl DK^-0.5)
    float* ws  = qst + 128 * KST;     // [64][256]   [v*beta | k*beta*e^gc] -> v_new|k_cum
    float* As  = ws + 64 * 256;       // [64][64]
    float* gc  = As + 64 * 64;        // 64
    float* egc = gc + 64;
    float* egr = egc + 64;
    float* bts = egr + 64;

    int cid = blockIdx.x;
    int n = cid & 63, bh = cid >> 6, h = bh & 7, b = bh >> 3;
    int tid = threadIdx.x;
    int warp = tid >> 5, lane = tid & 31;
    int t0 = n * 64;

    if (tid < 64) {
        int t = t0 + tid;
        gc[tid]  = gbuf[((size_t)(b * TT + t)) * 8 + h];
        bts[tid] = betabuf[((size_t)(b * TT + t)) * 8 + h];
    }
    __syncthreads();
#pragma unroll
    for (int off = 1; off < 64; off <<= 1) {
        float v = 0.f;
        if (tid < 64 && tid >= off) v = gc[tid - off];
        __syncthreads();
        if (tid < 64 && tid >= off) gc[tid] += v;
        __syncthreads();
    }
    if (tid < 64) {
        egc[tid] = __expf(gc[tid]);
        egr[tid] = __expf(gc[63] - gc[tid]);
    }
    __syncthreads();

    for (int r = warp; r < 64; r += 8) {
        int t = t0 + r;
        const float* base = conv + ((size_t)(b * TT + t)) * 3072 + h * 128;
        float qv[4], kv[4];
        float ssq = 0.f, ssk = 0.f;
#pragma unroll
        for (int u = 0; u < 4; u++) {
            qv[u] = base[lane + u * 32];
            kv[u] = base[1024 + lane + u * 32];
            ssq += qv[u] * qv[u];
            ssk += kv[u] * kv[u];
        }
#pragma unroll
        for (int off = 16; off; off >>= 1) {
            ssq += __shfl_xor_sync(0xffffffffu, ssq, off);
            ssk += __shfl_xor_sync(0xffffffffu, ssk, off);
        }
        float rq = rsqrtf(ssq + 1e-6f) * 0.08838834764831845f;
        float rk = rsqrtf(ssk + 1e-6f);
        float bbv = bts[r], egv = egc[r];
#pragma unroll
        for (int u = 0; u < 4; u++) {
            int d = lane + u * 32;
            qst[d * KST + r] = qv[u] * rq;
            float kn = kv[u] * rk;
            kst[d * KST + r] = kn;
            ws[r * 256 + d]       = base[2048 + d] * bbv;
            ws[r * 256 + 128 + d] = kn * bbv * egv;
        }
    }
    __syncthreads();

    int ti = tid >> 4, tj = tid & 15;

    // A[i][j] = beta_i (k_i . k_j) exp(gc_i - gc_j), j < i; else 0
    {
        float acc[4][4];
#pragma unroll
        for (int r = 0; r < 4; r++)
#pragma unroll
            for (int s = 0; s < 4; s++) acc[r][s] = 0.f;
        const float* ka = kst + ti * 4;
        const float* kb = kst + tj * 4;
#pragma unroll 4
        for (int d = 0; d < 128; d++) {
            float4 a = *(const float4*)(ka + d * KST);
            float4 bq = *(const float4*)(kb + d * KST);
            float ra[4] = {a.x, a.y, a.z, a.w};
            float rb[4] = {bq.x, bq.y, bq.z, bq.w};
#pragma unroll
            for (int r = 0; r < 4; r++)
#pragma unroll
                for (int s = 0; s < 4; s++) acc[r][s] += ra[r] * rb[s];
        }
#pragma unroll
        for (int r = 0; r < 4; r++) {
            int i = ti * 4 + r;
#pragma unroll
            for (int s = 0; s < 4; s++) {
                int j = tj * 4 + s;
                As[i * 64 + j] = (j < i) ? acc[r][s] * bts[i] * __expf(gc[i] - gc[j]) : 0.f;
            }
        }
    }
    __syncthreads();

    // blocked forward substitution: ws <- (I+A)^{-1} ws
    for (int blk = 0; blk < 4; blk++) {
        if (blk) {
            int tr = tid >> 7, tc = tid & 127;
            float acc[8][2];
#pragma unroll
            for (int r = 0; r < 8; r++) { acc[r][0] = 0.f; acc[r][1] = 0.f; }
            for (int j = 0; j < blk * 16; j++) {
                float2 wv = *(const float2*)(ws + j * 256 + tc * 2);
#pragma unroll
                for (int r = 0; r < 8; r++) {
                    float a = As[(blk * 16 + tr * 8 + r) * 64 + j];
                    acc[r][0] += a * wv.x;
                    acc[r][1] += a * wv.y;
                }
            }
#pragma unroll
            for (int r = 0; r < 8; r++) {
                float* w = ws + (blk * 16 + tr * 8 + r) * 256 + tc * 2;
                w[0] -= acc[r][0];
                w[1] -= acc[r][1];
            }
            __syncthreads();
        }
        {
            int c = tid;
            int i0 = blk * 16;
            for (int i = i0 + 1; i < i0 + 16; i++) {
                float acc = 0.f;
                for (int j = i0; j < i; j++) acc += As[i * 64 + j] * ws[j * 256 + c];
                ws[i * 256 + c] -= acc;
            }
        }
        __syncthreads();
    }

    // attn[i][j] = (q_i . k_j) exp(gc_i - gc_j), j <= i; else 0 (overwrite As)
    {
        float acc[4][4];
#pragma unroll
        for (int r = 0; r < 4; r++)
#pragma unroll
            for (int s = 0; s < 4; s++) acc[r][s] = 0.f;
        const float* qa = qst + ti * 4;
        const float* kb = kst + tj * 4;
#pragma unroll 4
        for (int d = 0; d < 128; d++) {
            float4 a = *(const float4*)(qa + d * KST);
            float4 bq = *(const float4*)(kb + d * KST);
            float ra[4] = {a.x, a.y, a.z, a.w};
            float rb[4] = {bq.x, bq.y, bq.z, bq.w};
#pragma unroll
            for (int r = 0; r < 4; r++)
#pragma unroll
                for (int s = 0; s < 4; s++) acc[r][s] += ra[r] * rb[s];
        }
#pragma unroll
        for (int r = 0; r < 4; r++) {
            int i = ti * 4 + r;
#pragma unroll
            for (int s = 0; s < 4; s++) {
                int j = tj * 4 + s;
                As[i * 64 + j] = (j <= i) ? acc[r][s] * __expf(gc[i] - gc[j]) : 0.f;
            }
        }
    }
    __syncthreads();

    // [L | attn@k_cum] = attn @ ws ;  P = q*e^gc - attn@k_cum
    {
        int tr = warp;
        int tc = lane;
        float acc[8][8];
#pragma unroll
        for (int r = 0; r < 8; r++)
#pragma unroll
            for (int u = 0; u < 8; u++) acc[r][u] = 0.f;
        int jmax = tr * 8 + 8;
        for (int j = 0; j < jmax; j++) {
            float av[8];
#pragma unroll
            for (int r = 0; r < 8; r++) av[r] = As[(tr * 8 + r) * 64 + j];
            float4 w0 = *(const float4*)(ws + j * 256 + tc * 8);
            float4 w1 = *(const float4*)(ws + j * 256 + tc * 8 + 4);
            float rb[8] = {w0.x, w0.y, w0.z, w0.w, w1.x, w1.y, w1.z, w1.w};
#pragma unroll
            for (int r = 0; r < 8; r++)
#pragma unroll
                for (int u = 0; u < 8; u++) acc[r][u] += av[r] * rb[u];
        }
        if (tc < 16) {
#pragma unroll
            for (int r = 0; r < 8; r++) {
                int i = tr * 8 + r;
                float* dst = Lout + ((size_t)cid * 64 + i) * 128 + tc * 8;
                *(float4*)(dst)     = make_float4(acc[r][0], acc[r][1], acc[r][2], acc[r][3]);
                *(float4*)(dst + 4) = make_float4(acc[r][4], acc[r][5], acc[r][6], acc[r][7]);
            }
        } else {
            int c0 = tc * 8 - 128;
#pragma unroll
            for (int r = 0; r < 8; r++) {
                int i = tr * 8 + r;
                float eg = egc[i];
                float v[8];
#pragma unroll
                for (int u = 0; u < 8; u++)
                    v[u] = qst[(c0 + u) * KST + i] * eg - acc[r][u];
                float* dst = Pout + ((size_t)cid * 64 + i) * 128 + c0;
                *(float4*)(dst)     = make_float4(v[0], v[1], v[2], v[3]);
                *(float4*)(dst + 4) = make_float4(v[4], v[5], v[6], v[7]);
            }
        }
    }

    // M = keff^T @ k_cum ; U = keff^T @ v_new ; keff[i][a] = k[i][a]*egr[i]
    {
        int ta = tid >> 4;
        int te = tid & 15;
#pragma unroll
        for (int pass = 0; pass < 2; pass++) {
            float acc[8][8];
#pragma unroll
            for (int r = 0; r < 8; r++)
#pragma unroll
                for (int u = 0; u < 8; u++) acc[r][u] = 0.f;
            for (int i = 0; i < 64; i++) {
                float er = egr[i];
                float av[8];
#pragma unroll
                for (int r = 0; r < 8; r++) av[r] = kst[(ta * 8 + r) * KST + i] * er;
                float4 w0 = *(const float4*)(ws + i * 256 + pass * 128 + te * 8);
                float4 w1 = *(const float4*)(ws + i * 256 + pass * 128 + te * 8 + 4);
                float rb[8] = {w0.x, w0.y, w0.z, w0.w, w1.x, w1.y, w1.z, w1.w};
#pragma unroll
                for (int r = 0; r < 8; r++)
#pragma unroll
                    for (int u = 0; u < 8; u++) acc[r][u] += av[r] * rb[u];
            }
            float* dstb = pass ? Mout : Uout;
#pragma unroll
            for (int r = 0; r < 8; r++) {
                float* dst = dstb + ((size_t)cid * 128 + ta * 8 + r) * 128 + te * 8;
                *(float4*)(dst)     = make_float4(acc[r][0], acc[r][1], acc[r][2], acc[r][3]);
                *(float4*)(dst + 4) = make_float4(acc[r][4], acc[r][5], acc[r][6], acc[r][7]);
            }
        }
    }
    if (tid == 0) eglout[cid] = __expf(gc[63]);
}

// ---------------- Phase B: sequential scan over chunks, DV split ----------------
#define PB_SMEM ((128*128 + 64*128 + 128*16) * 4)

__global__ __launch_bounds__(256) void phaseB_kernel(const float* __restrict__ Pm,
        const float* __restrict__ Lm, const float* __restrict__ Mm,
        const float* __restrict__ Um, const float* __restrict__ eglv,
        float* __restrict__ core)
{
    extern __shared__ float sm[];
    float* Ms = sm;                 // 128 x 128
    float* Ps = Ms + 128 * 128;     // 64 x 128
    float* Ss = Ps + 64 * 128;      // 128 x 16 (S slice)

    int bh = blockIdx.x, gg = blockIdx.y;
    int b = bh >> 3, h = bh & 7;
    int tid = threadIdx.x;
    int c4g = tid & 3;
    int a0 = tid >> 2;
    int c0 = gg * 16;

    for (int i = tid; i < 128 * 16; i += 256) Ss[i] = 0.f;
    __syncthreads();

    for (int n = 0; n < 64; n++) {
        size_t cid = (size_t)bh * 64 + n;
        const float4* Mg = (const float4*)(Mm + cid * 16384);
        float4* Ms4 = (float4*)Ms;
        for (int i = tid; i < 4096; i += 256) Ms4[i] = Mg[i];
        const float4* Pg = (const float4*)(Pm + cid * 8192);
        float4* Ps4 = (float4*)Ps;
        for (int i = tid; i < 2048; i += 256) Ps4[i] = Pg[i];
        __syncthreads();

        {
            float4 acc = *(const float4*)(Lm + cid * 8192 + a0 * 128 + c0 + c4g * 4);
            for (int a = 0; a < 128; a++) {
                float p = Ps[a0 * 128 + a];
                float4 s = *(const float4*)(Ss + a * 16 + c4g * 4);
                acc.x += p * s.x; acc.y += p * s.y; acc.z += p * s.z; acc.w += p * s.w;
            }
            int t = n * 64 + a0;
            *(float4*)(core + (((size_t)(b * TT + t)) * 8 + h) * 128 + c0 + c4g * 4) = acc;
        }

        float eg = eglv[cid];
        float4 s0 = *(const float4*)(Ss + a0 * 16 + c4g * 4);
        float4 s1 = *(const float4*)(Ss + (a0 + 64) * 16 + c4g * 4);
        float4 ns0 = *(const float4*)(Um + cid * 16384 + (size_t)a0 * 128 + c0 + c4g * 4);
        float4 ns1 = *(const float4*)(Um + cid * 16384 + (size_t)(a0 + 64) * 128 + c0 + c4g * 4);
        ns0.x += eg * s0.x; ns0.y += eg * s0.y; ns0.z += eg * s0.z; ns0.w += eg * s0.w;
        ns1.x += eg * s1.x; ns1.y += eg * s1.y; ns1.z += eg * s1.z; ns1.w += eg * s1.w;
        for (int ap = 0; ap < 128; ap++) {
            float4 s = *(const float4*)(Ss + ap * 16 + c4g * 4);
            float m0 = Ms[a0 * 128 + ap];
            float m1 = Ms[(a0 + 64) * 128 + ap];
            ns0.x -= m0 * s.x; ns0.y -= m0 * s.y; ns0.z -= m0 * s.z; ns0.w -= m0 * s.w;
            ns1.x -= m1 * s.x; ns1.y -= m1 * s.y; ns1.z -= m1 * s.z; ns1.w -= m1 * s.w;
        }
        __syncthreads();
        *(float4*)(Ss + a0 * 16 + c4g * 4) = ns0;
        *(float4*)(Ss + (a0 + 64) * 16 + c4g * 4) = ns1;
        __syncthreads();
    }
}

// ---------------- gated RMSNorm * silu(z) ---------------------------------------
__global__ __launch_bounds__(128) void norm_kernel(const float* __restrict__ core,
        const float* __restrict__ qkvz, const float* __restrict__ nw,
        float* __restrict__ hbuf)
{
    int bth = blockIdx.x;
    int d = threadIdx.x;
    float cv = core[(size_t)bth * 128 + d];
    float ss = cv * cv;
#pragma unroll
    for (int o = 16; o; o >>= 1) ss += __shfl_xor_sync(0xffffffffu, ss, o);
    __shared__ float red[4];
    if ((d & 31) == 0) red[d >> 5] = ss;
    __syncthreads();
    float tot = red[0] + red[1] + red[2] + red[3];
    float r = rsqrtf(tot * (1.f / 128.f) + 1e-6f);
    float zz = qkvz[(size_t)bth * 512 + 384 + d];
    float sz = zz / (1.f + __expf(-zz));
    hbuf[(size_t)bth * 128 + d] = nw[d] * cv * r * sz;
}

// ---------------- launch ---------------------------------------------------------
extern "C" void kernel_launch(void* const* d_in, const int* in_sizes, int n_in,
                              void* d_out, int out_size)
{
    (void)in_sizes; (void)n_in; (void)out_size;
    const float* x    = (const float*)d_in[0];
    const float* Wq   = (const float*)d_in[1];
    const float* Wba  = (const float*)d_in[2];
    const float* cw   = (const float*)d_in[3];
    const float* dtb  = (const float*)d_in[4];
    const float* Alog = (const float*)d_in[5];
    const float* nw   = (const float*)d_in[6];
    const float* Wout = (const float*)d_in[7];
    float* out = (float*)d_out;

    float *qkvz, *bab, *convb, *gb, *betab, *Pb, *Lb, *Mb, *Ub, *eglb, *coreb, *hb;
    cudaGetSymbolAddress((void**)&qkvz,  g_qkvz);
    cudaGetSymbolAddress((void**)&bab,   g_ba);
    cudaGetSymbolAddress((void**)&convb, g_conv);
    cudaGetSymbolAddress((void**)&gb,    g_g);
    cudaGetSymbolAddress((void**)&betab, g_beta);
    cudaGetSymbolAddress((void**)&Pb,    g_P);
    cudaGetSymbolAddress((void**)&Lb,    g_L);
    cudaGetSymbolAddress((void**)&Mb,    g_M);
    cudaGetSymbolAddress((void**)&Ub,    g_U);
    cudaGetSymbolAddress((void**)&eglb,  g_egl);
    cudaGetSymbolAddress((void**)&coreb, g_core);
    cudaGetSymbolAddress((void**)&hb,    g_hbuf);

    cudaFuncSetAttribute(phaseA_kernel, cudaFuncAttributeMaxDynamicSharedMemorySize, PA_SMEM);
    cudaFuncSetAttribute(phaseB_kernel, cudaFuncAttributeMaxDynamicSharedMemorySize, PB_SMEM);

    dim3 g1(4096 / 128, 8192 / 128);
    bf16gemm128<<<g1, 256>>>(BB * TT, 4096, CC, x, Wq, qkvz);
    ba_kernel<<<BB * TT, 256>>>(x, Wba, bab);
    conv_silu_kernel<<<(BB * TT * 3072) / 256, 256>>>(qkvz, cw, convb);
    gbeta_kernel<<<(BB * TT * NH) / 256, 256>>>(bab, dtb, Alog, gb, betab);
    phaseA_kernel<<<NCID, 256, PA_SMEM>>>(convb, gb, betab, Pb, Lb, Mb, Ub, eglb);
    dim3 gB(16, 8);
    phaseB_kernel<<<gB, 256, PB_SMEM>>>(Pb, Lb, Mb, Ub, eglb, coreb);
    norm_kernel<<<BB * TT * NH, 128>>>(coreb, qkvz, nw, hb);
    dim3 g2(1024 / 128, 8192 / 128);
    bf16gemm128<<<g2, 256>>>(BB * TT, 1024, CC, hb, Wout, out);
}

// round 5
// speedup vs baseline: 1.6018x; 1.6018x over previous
#include <cuda_runtime.h>
#include <cuda_bf16.h>
#include <math.h>

// Problem constants
#define BB 2
#define TT 4096
#define CC 1024
#define NH 8
#define DD 128
#define CHK 64
#define NCHUNK 64            // T / CHK
#define NCID 1024            // BB*NH*NCHUNK

// ---------------- scratch (device globals; no allocation allowed) ----------------
__device__ float g_qkvz[(size_t)BB*TT*4096];     // x @ W_qkvz      (B,T,8,512)
__device__ float g_ba[(size_t)BB*TT*16];         // x @ W_ba
__device__ float g_conv[(size_t)BB*TT*3072];     // conv+silu [q|k|v]
__device__ float g_g[(size_t)BB*TT*NH];
__device__ float g_beta[(size_t)BB*TT*NH];
__device__ float g_P[(size_t)NCID*64*128];       // qeff - attn@k_cum
__device__ float g_L[(size_t)NCID*64*128];       // attn@v_new
__device__ float g_M[(size_t)NCID*128*128];      // keff^T @ k_cum
__device__ float g_U[(size_t)NCID*128*128];      // keff^T @ v_new
__device__ float g_egl[NCID];                    // exp(g_last)
__device__ float g_core[(size_t)BB*TT*NH*DD];    // delta-rule output

// bf16 hi/lo split operands for the two big GEMMs
__device__ __nv_bfloat16 g_xh[(size_t)BB*TT*CC],  g_xl[(size_t)BB*TT*CC];
__device__ __nv_bfloat16 g_w1h[(size_t)4096*CC],  g_w1l[(size_t)4096*CC];   // W_qkvz^T [N][K]
__device__ __nv_bfloat16 g_w2h[(size_t)1024*CC],  g_w2l[(size_t)1024*CC];   // W_out^T  [N][K]
__device__ __nv_bfloat16 g_hh[(size_t)BB*TT*1024], g_hl[(size_t)BB*TT*1024];

// ---------------- split/transpose conversion kernels ----------------------------
__global__ __launch_bounds__(256) void cvt_split_kernel(const float* __restrict__ in,
        __nv_bfloat16* __restrict__ oh, __nv_bfloat16* __restrict__ ol)
{
    int i = blockIdx.x * 256 + threadIdx.x;            // indexes float4
    float4 v = ((const float4*)in)[i];
    float f[4] = {v.x, v.y, v.z, v.w};
    __nv_bfloat16 h[4], l[4];
#pragma unroll
    for (int e = 0; e < 4; e++) {
        h[e] = __float2bfloat16_rn(f[e]);
        l[e] = __float2bfloat16_rn(f[e] - __bfloat162float(h[e]));
    }
    __nv_bfloat162 h0; h0.x = h[0]; h0.y = h[1];
    __nv_bfloat162 h1; h1.x = h[2]; h1.y = h[3];
    __nv_bfloat162 l0; l0.x = l[0]; l0.y = l[1];
    __nv_bfloat162 l1; l1.x = l[2]; l1.y = l[3];
    ((__nv_bfloat162*)oh)[i * 2]     = h0;
    ((__nv_bfloat162*)oh)[i * 2 + 1] = h1;
    ((__nv_bfloat162*)ol)[i * 2]     = l0;
    ((__nv_bfloat162*)ol)[i * 2 + 1] = l1;
}

// W [K][N] f32 -> Wt [N][K] bf16 hi/lo
__global__ __launch_bounds__(256) void transpose_split_kernel(const float* __restrict__ W,
        __nv_bfloat16* __restrict__ oh, __nv_bfloat16* __restrict__ ol, int K, int N)
{
    __shared__ float tile[32][33];
    int n0 = blockIdx.x * 32, k0 = blockIdx.y * 32;
    int tx = threadIdx.x & 31, ty0 = threadIdx.x >> 5;
#pragma unroll
    for (int ty = ty0; ty < 32; ty += 8)
        tile[ty][tx] = W[(size_t)(k0 + ty) * N + n0 + tx];
    __syncthreads();
#pragma unroll
    for (int ty = ty0; ty < 32; ty += 8) {
        float v = tile[tx][ty];                       // = W[k0+tx][n0+ty]
        __nv_bfloat16 h = __float2bfloat16_rn(v);
        size_t o = (size_t)(n0 + ty) * K + k0 + tx;
        oh[o] = h;
        ol[o] = __float2bfloat16_rn(v - __bfloat162float(h));
    }
}

// ---------------- bf16 mma helper ------------------------------------------------
#define MMA_BF16(C, Ar, Br)                                                    \
    asm volatile("mma.sync.aligned.m16n8k16.row.col.f32.bf16.bf16.f32 "        \
        "{%0,%1,%2,%3}, {%4,%5,%6,%7}, {%8,%9}, {%0,%1,%2,%3};"                \
        : "+f"((C)[0]), "+f"((C)[1]), "+f"((C)[2]), "+f"((C)[3])               \
        : "r"((Ar)[0]), "r"((Ar)[1]), "r"((Ar)[2]), "r"((Ar)[3]),              \
          "r"((Br)[0]), "r"((Br)[1]))

// ---------------- 3xBF16-split GEMM: C = A(MxK)@B^T(NxK), pre-split bf16 --------
// A hi/lo: [M][K] bf16 row-major; Bt hi/lo: [N][K] bf16; C: [M][N] f32.
#define GKS 40                                   // bf16 k-stride (20 words, conflict-free)
__global__ __launch_bounds__(256) void bf16gemm128(int M, int N, int K,
        const __nv_bfloat16* __restrict__ Ah_, const __nv_bfloat16* __restrict__ Al_,
        const __nv_bfloat16* __restrict__ Bth_, const __nv_bfloat16* __restrict__ Btl_,
        float* __restrict__ Cm)
{
    __shared__ __nv_bfloat16 sAh[128][GKS], sAl[128][GKS];
    __shared__ __nv_bfloat16 sBh[128][GKS], sBl[128][GKS];

    int tid = threadIdx.x;
    int brow = blockIdx.y * 128, bcol = blockIdx.x * 128;
    int warp = tid >> 5, lane = tid & 31;
    int wm = (warp & 1) * 64, wn = (warp >> 1) * 32;
    int lr = lane >> 2, lc2 = (lane & 3) * 2;

    float c[4][4][4];
#pragma unroll
    for (int mt = 0; mt < 4; mt++)
#pragma unroll
        for (int nt = 0; nt < 4; nt++)
#pragma unroll
            for (int e = 0; e < 4; e++) c[mt][nt][e] = 0.f;

    for (int k0 = 0; k0 < K; k0 += 32) {
        // stage: pure LDG.128 -> STS.128, no conversion
#pragma unroll
        for (int u = 0; u < 2; u++) {
            int idx = tid + u * 256;
            int r = idx >> 2, kg = (idx & 3) * 8;
            *(uint4*)(&sAh[r][kg]) = *(const uint4*)(Ah_  + (size_t)(brow + r) * K + k0 + kg);
            *(uint4*)(&sAl[r][kg]) = *(const uint4*)(Al_  + (size_t)(brow + r) * K + k0 + kg);
            *(uint4*)(&sBh[r][kg]) = *(const uint4*)(Bth_ + (size_t)(bcol + r) * K + k0 + kg);
            *(uint4*)(&sBl[r][kg]) = *(const uint4*)(Btl_ + (size_t)(bcol + r) * K + k0 + kg);
        }
        __syncthreads();

#pragma unroll
        for (int kk = 0; kk < 32; kk += 16) {
            unsigned ah[4][4], al[4][4], bh[4][2], bl[4][2];
#pragma unroll
            for (int mt = 0; mt < 4; mt++) {
                int r0 = wm + mt * 16 + lr;
                ah[mt][0] = *(const unsigned*)(&sAh[r0][kk + lc2]);
                ah[mt][1] = *(const unsigned*)(&sAh[r0 + 8][kk + lc2]);
                ah[mt][2] = *(const unsigned*)(&sAh[r0][kk + lc2 + 8]);
                ah[mt][3] = *(const unsigned*)(&sAh[r0 + 8][kk + lc2 + 8]);
                al[mt][0] = *(const unsigned*)(&sAl[r0][kk + lc2]);
                al[mt][1] = *(const unsigned*)(&sAl[r0 + 8][kk + lc2]);
                al[mt][2] = *(const unsigned*)(&sAl[r0][kk + lc2 + 8]);
                al[mt][3] = *(const unsigned*)(&sAl[r0 + 8][kk + lc2 + 8]);
            }
#pragma unroll
            for (int nt = 0; nt < 4; nt++) {
                int cn = wn + nt * 8 + lr;
                bh[nt][0] = *(const unsigned*)(&sBh[cn][kk + lc2]);
                bh[nt][1] = *(const unsigned*)(&sBh[cn][kk + lc2 + 8]);
                bl[nt][0] = *(const unsigned*)(&sBl[cn][kk + lc2]);
                bl[nt][1] = *(const unsigned*)(&sBl[cn][kk + lc2 + 8]);
            }
#pragma unroll
            for (int mt = 0; mt < 4; mt++)
#pragma unroll
                for (int nt = 0; nt < 4; nt++) {
                    MMA_BF16(c[mt][nt], ah[mt], bh[nt]);
                    MMA_BF16(c[mt][nt], al[mt], bh[nt]);
                    MMA_BF16(c[mt][nt], ah[mt], bl[nt]);
                }
        }
        __syncthreads();
    }

#pragma unroll
    for (int mt = 0; mt < 4; mt++) {
        int r0 = brow + wm + mt * 16 + lr;
#pragma unroll
        for (int nt = 0; nt < 4; nt++) {
            int cn = bcol + wn + nt * 8 + lc2;
            *(float2*)(Cm + (size_t)r0 * N + cn)       = make_float2(c[mt][nt][0], c[mt][nt][1]);
            *(float2*)(Cm + (size_t)(r0 + 8) * N + cn) = make_float2(c[mt][nt][2], c[mt][nt][3]);
        }
    }
}

// ---------------- ba = x @ W_ba (N = 16) ----------------------------------------
__global__ __launch_bounds__(256) void ba_kernel(const float* __restrict__ x,
        const float* __restrict__ Wba, float* __restrict__ out)
{
    int bt = blockIdx.x;
    __shared__ float xs[1024];
    const float* xrow = x + (size_t)bt * 1024;
    for (int i = threadIdx.x; i < 256; i += 256)
        ((float4*)xs)[i] = ((const float4*)xrow)[i];
    __syncthreads();
    int o = threadIdx.x >> 4, p = threadIdx.x & 15;
    float acc = 0.f;
    for (int k = p; k < 1024; k += 16) acc += xs[k] * Wba[(size_t)k * 16 + o];
    acc += __shfl_down_sync(0xffffffffu, acc, 8);
    acc += __shfl_down_sync(0xffffffffu, acc, 4);
    acc += __shfl_down_sync(0xffffffffu, acc, 2);
    acc += __shfl_down_sync(0xffffffffu, acc, 1);
    if (p == 0) out[(size_t)bt * 16 + o] = acc;
}

// ---------------- causal depthwise conv (K=4) + silu ----------------------------
__global__ __launch_bounds__(256) void conv_silu_kernel(const float* __restrict__ qkvz,
        const float* __restrict__ cw, float* __restrict__ out)
{
    int idx = blockIdx.x * 256 + threadIdx.x;
    int ch = idx % 3072;
    int btrow = idx / 3072;
    int t = btrow & (TT - 1);
    int part = ch >> 10;
    int hc = (ch & 1023) >> 7;
    int d = ch & 127;
    int po = (part == 0) ? 0 : (part == 1) ? 128 : 256;
    float acc = 0.f;
#pragma unroll
    for (int j = 0; j < 4; j++) {
        int tt2 = t - 3 + j;
        if (tt2 >= 0) {
            float v = qkvz[(((size_t)(btrow - 3 + j)) * 8 + hc) * 512 + po + d];
            acc += v * cw[ch * 4 + j];
        }
    }
    out[(size_t)idx] = acc / (1.f + __expf(-acc));
}

// ---------------- g, beta --------------------------------------------------------
__global__ __launch_bounds__(256) void gbeta_kernel(const float* __restrict__ ba,
        const float* __restrict__ dtb, const float* __restrict__ Alog,
        float* __restrict__ g, float* __restrict__ beta)
{
    int idx = blockIdx.x * 256 + threadIdx.x;
    int h = idx & 7;
    int bt = idx >> 3;
    float bv = ba[(size_t)bt * 16 + h * 2];
    float av = ba[(size_t)bt * 16 + h * 2 + 1];
    beta[idx] = 1.f / (1.f + expf(-bv));
    float xx = av + dtb[h];
    float sp = (xx > 20.f) ? xx : log1pf(expf(xx));
    g[idx] = -expf(Alog[h]) * sp;
}

// ---------------- Phase A: per-chunk local operators (register-tiled) -----------
#define KST 68
#define PA_SMEM ((128*KST*2 + 64*256 + 64*64 + 256) * 4)

__global__ __launch_bounds__(256) void phaseA_kernel(const float* __restrict__ conv,
        const float* __restrict__ gbuf, const float* __restrict__ betabuf,
        float* __restrict__ Pout, float* __restrict__ Lout,
        float* __restrict__ Mout, float* __restrict__ Uout, float* __restrict__ eglout)
{
    extern __shared__ float sm[];
    float* kst = sm;
    float* qst = kst + 128 * KST;
    float* ws  = qst + 128 * KST;
    float* As  = ws + 64 * 256;
    float* gc  = As + 64 * 64;
    float* egc = gc + 64;
    float* egr = egc + 64;
    float* bts = egr + 64;

    int cid = blockIdx.x;
    int n = cid & 63, bh = cid >> 6, h = bh & 7, b = bh >> 3;
    int tid = threadIdx.x;
    int warp = tid >> 5, lane = tid & 31;
    int t0 = n * 64;

    if (tid < 64) {
        int t = t0 + tid;
        gc[tid]  = gbuf[((size_t)(b * TT + t)) * 8 + h];
        bts[tid] = betabuf[((size_t)(b * TT + t)) * 8 + h];
    }
    __syncthreads();
#pragma unroll
    for (int off = 1; off < 64; off <<= 1) {
        float v = 0.f;
        if (tid < 64 && tid >= off) v = gc[tid - off];
        __syncthreads();
        if (tid < 64 && tid >= off) gc[tid] += v;
        __syncthreads();
    }
    if (tid < 64) {
        egc[tid] = __expf(gc[tid]);
        egr[tid] = __expf(gc[63] - gc[tid]);
    }
    __syncthreads();

    for (int r = warp; r < 64; r += 8) {
        int t = t0 + r;
        const float* base = conv + ((size_t)(b * TT + t)) * 3072 + h * 128;
        float qv[4], kv[4];
        float ssq = 0.f, ssk = 0.f;
#pragma unroll
        for (int u = 0; u < 4; u++) {
            qv[u] = base[lane + u * 32];
            kv[u] = base[1024 + lane + u * 32];
            ssq += qv[u] * qv[u];
            ssk += kv[u] * kv[u];
        }
#pragma unroll
        for (int off = 16; off; off >>= 1) {
            ssq += __shfl_xor_sync(0xffffffffu, ssq, off);
            ssk += __shfl_xor_sync(0xffffffffu, ssk, off);
        }
        float rq = rsqrtf(ssq + 1e-6f) * 0.08838834764831845f;
        float rk = rsqrtf(ssk + 1e-6f);
        float bbv = bts[r], egv = egc[r];
#pragma unroll
        for (int u = 0; u < 4; u++) {
            int d = lane + u * 32;
            qst[d * KST + r] = qv[u] * rq;
            float kn = kv[u] * rk;
            kst[d * KST + r] = kn;
            ws[r * 256 + d]       = base[2048 + d] * bbv;
            ws[r * 256 + 128 + d] = kn * bbv * egv;
        }
    }
    __syncthreads();

    int ti = tid >> 4, tj = tid & 15;

    {
        float acc[4][4];
#pragma unroll
        for (int r = 0; r < 4; r++)
#pragma unroll
            for (int s = 0; s < 4; s++) acc[r][s] = 0.f;
        const float* ka = kst + ti * 4;
        const float* kb = kst + tj * 4;
#pragma unroll 4
        for (int d = 0; d < 128; d++) {
            float4 a = *(const float4*)(ka + d * KST);
            float4 bq = *(const float4*)(kb + d * KST);
            float ra[4] = {a.x, a.y, a.z, a.w};
            float rb[4] = {bq.x, bq.y, bq.z, bq.w};
#pragma unroll
            for (int r = 0; r < 4; r++)
#pragma unroll
                for (int s = 0; s < 4; s++) acc[r][s] += ra[r] * rb[s];
        }
#pragma unroll
        for (int r = 0; r < 4; r++) {
            int i = ti * 4 + r;
#pragma unroll
            for (int s = 0; s < 4; s++) {
                int j = tj * 4 + s;
                As[i * 64 + j] = (j < i) ? acc[r][s] * bts[i] * __expf(gc[i] - gc[j]) : 0.f;
            }
        }
    }
    __syncthreads();

    for (int blk = 0; blk < 4; blk++) {
        if (blk) {
            int tr = tid >> 7, tc = tid & 127;
            float acc[8][2];
#pragma unroll
            for (int r = 0; r < 8; r++) { acc[r][0] = 0.f; acc[r][1] = 0.f; }
            for (int j = 0; j < blk * 16; j++) {
                float2 wv = *(const float2*)(ws + j * 256 + tc * 2);
#pragma unroll
                for (int r = 0; r < 8; r++) {
                    float a = As[(blk * 16 + tr * 8 + r) * 64 + j];
                    acc[r][0] += a * wv.x;
                    acc[r][1] += a * wv.y;
                }
            }
#pragma unroll
            for (int r = 0; r < 8; r++) {
                float* w = ws + (blk * 16 + tr * 8 + r) * 256 + tc * 2;
                w[0] -= acc[r][0];
                w[1] -= acc[r][1];
            }
            __syncthreads();
        }
        {
            int c = tid;
            int i0 = blk * 16;
            for (int i = i0 + 1; i < i0 + 16; i++) {
                float acc = 0.f;
                for (int j = i0; j < i; j++) acc += As[i * 64 + j] * ws[j * 256 + c];
                ws[i * 256 + c] -= acc;
            }
        }
        __syncthreads();
    }

    {
        float acc[4][4];
#pragma unroll
        for (int r = 0; r < 4; r++)
#pragma unroll
            for (int s = 0; s < 4; s++) acc[r][s] = 0.f;
        const float* qa = qst + ti * 4;
        const float* kb = kst + tj * 4;
#pragma unroll 4
        for (int d = 0; d < 128; d++) {
            float4 a = *(const float4*)(qa + d * KST);
            float4 bq = *(const float4*)(kb + d * KST);
            float ra[4] = {a.x, a.y, a.z, a.w};
            float rb[4] = {bq.x, bq.y, bq.z, bq.w};
#pragma unroll
            for (int r = 0; r < 4; r++)
#pragma unroll
                for (int s = 0; s < 4; s++) acc[r][s] += ra[r] * rb[s];
        }
#pragma unroll
        for (int r = 0; r < 4; r++) {
            int i = ti * 4 + r;
#pragma unroll
            for (int s = 0; s < 4; s++) {
                int j = tj * 4 + s;
                As[i * 64 + j] = (j <= i) ? acc[r][s] * __expf(gc[i] - gc[j]) : 0.f;
            }
        }
    }
    __syncthreads();

    {
        int tr = warp;
        int tc = lane;
        float acc[8][8];
#pragma unroll
        for (int r = 0; r < 8; r++)
#pragma unroll
            for (int u = 0; u < 8; u++) acc[r][u] = 0.f;
        int jmax = tr * 8 + 8;
        for (int j = 0; j < jmax; j++) {
            float av[8];
#pragma unroll
            for (int r = 0; r < 8; r++) av[r] = As[(tr * 8 + r) * 64 + j];
            float4 w0 = *(const float4*)(ws + j * 256 + tc * 8);
            float4 w1 = *(const float4*)(ws + j * 256 + tc * 8 + 4);
            float rb[8] = {w0.x, w0.y, w0.z, w0.w, w1.x, w1.y, w1.z, w1.w};
#pragma unroll
            for (int r = 0; r < 8; r++)
#pragma unroll
                for (int u = 0; u < 8; u++) acc[r][u] += av[r] * rb[u];
        }
        if (tc < 16) {
#pragma unroll
            for (int r = 0; r < 8; r++) {
                int i = tr * 8 + r;
                float* dst = Lout + ((size_t)cid * 64 + i) * 128 + tc * 8;
                *(float4*)(dst)     = make_float4(acc[r][0], acc[r][1], acc[r][2], acc[r][3]);
                *(float4*)(dst + 4) = make_float4(acc[r][4], acc[r][5], acc[r][6], acc[r][7]);
            }
        } else {
            int c0 = tc * 8 - 128;
#pragma unroll
            for (int r = 0; r < 8; r++) {
                int i = tr * 8 + r;
                float eg = egc[i];
                float v[8];
#pragma unroll
                for (int u = 0; u < 8; u++)
                    v[u] = qst[(c0 + u) * KST + i] * eg - acc[r][u];
                float* dst = Pout + ((size_t)cid * 64 + i) * 128 + c0;
                *(float4*)(dst)     = make_float4(v[0], v[1], v[2], v[3]);
                *(float4*)(dst + 4) = make_float4(v[4], v[5], v[6], v[7]);
            }
        }
    }

    {
        int ta = tid >> 4;
        int te = tid & 15;
#pragma unroll
        for (int pass = 0; pass < 2; pass++) {
            float acc[8][8];
#pragma unroll
            for (int r = 0; r < 8; r++)
#pragma unroll
                for (int u = 0; u < 8; u++) acc[r][u] = 0.f;
            for (int i = 0; i < 64; i++) {
                float er = egr[i];
                float av[8];
#pragma unroll
                for (int r = 0; r < 8; r++) av[r] = kst[(ta * 8 + r) * KST + i] * er;
                float4 w0 = *(const float4*)(ws + i * 256 + pass * 128 + te * 8);
                float4 w1 = *(const float4*)(ws + i * 256 + pass * 128 + te * 8 + 4);
                float rb[8] = {w0.x, w0.y, w0.z, w0.w, w1.x, w1.y, w1.z, w1.w};
#pragma unroll
                for (int r = 0; r < 8; r++)
#pragma unroll
                    for (int u = 0; u < 8; u++) acc[r][u] += av[r] * rb[u];
            }
            float* dstb = pass ? Mout : Uout;
#pragma unroll
            for (int r = 0; r < 8; r++) {
                float* dst = dstb + ((size_t)cid * 128 + ta * 8 + r) * 128 + te * 8;
                *(float4*)(dst)     = make_float4(acc[r][0], acc[r][1], acc[r][2], acc[r][3]);
                *(float4*)(dst + 4) = make_float4(acc[r][4], acc[r][5], acc[r][6], acc[r][7]);
            }
        }
    }
    if (tid == 0) eglout[cid] = __expf(gc[63]);
}

// ---------------- Phase B: sequential scan over chunks, DV split ----------------
#define PB_SMEM ((128*128 + 64*128 + 128*16) * 4)

__global__ __launch_bounds__(256) void phaseB_kernel(const float* __restrict__ Pm,
        const float* __restrict__ Lm, const float* __restrict__ Mm,
        const float* __restrict__ Um, const float* __restrict__ eglv,
        float* __restrict__ core)
{
    extern __shared__ float sm[];
    float* Ms = sm;
    float* Ps = Ms + 128 * 128;
    float* Ss = Ps + 64 * 128;

    int bh = blockIdx.x, gg = blockIdx.y;
    int b = bh >> 3, h = bh & 7;
    int tid = threadIdx.x;
    int c4g = tid & 3;
    int a0 = tid >> 2;
    int c0 = gg * 16;

    for (int i = tid; i < 128 * 16; i += 256) Ss[i] = 0.f;
    __syncthreads();

    for (int n = 0; n < 64; n++) {
        size_t cid = (size_t)bh * 64 + n;
        const float4* Mg = (const float4*)(Mm + cid * 16384);
        float4* Ms4 = (float4*)Ms;
        for (int i = tid; i < 4096; i += 256) Ms4[i] = Mg[i];
        const float4* Pg = (const float4*)(Pm + cid * 8192);
        float4* Ps4 = (float4*)Ps;
        for (int i = tid; i < 2048; i += 256) Ps4[i] = Pg[i];
        __syncthreads();

        {
            float4 acc = *(const float4*)(Lm + cid * 8192 + a0 * 128 + c0 + c4g * 4);
            for (int a = 0; a < 128; a++) {
                float p = Ps[a0 * 128 + a];
                float4 s = *(const float4*)(Ss + a * 16 + c4g * 4);
                acc.x += p * s.x; acc.y += p * s.y; acc.z += p * s.z; acc.w += p * s.w;
            }
            int t = n * 64 + a0;
            *(float4*)(core + (((size_t)(b * TT + t)) * 8 + h) * 128 + c0 + c4g * 4) = acc;
        }

        float eg = eglv[cid];
        float4 s0 = *(const float4*)(Ss + a0 * 16 + c4g * 4);
        float4 s1 = *(const float4*)(Ss + (a0 + 64) * 16 + c4g * 4);
        float4 ns0 = *(const float4*)(Um + cid * 16384 + (size_t)a0 * 128 + c0 + c4g * 4);
        float4 ns1 = *(const float4*)(Um + cid * 16384 + (size_t)(a0 + 64) * 128 + c0 + c4g * 4);
        ns0.x += eg * s0.x; ns0.y += eg * s0.y; ns0.z += eg * s0.z; ns0.w += eg * s0.w;
        ns1.x += eg * s1.x; ns1.y += eg * s1.y; ns1.z += eg * s1.z; ns1.w += eg * s1.w;
        for (int ap = 0; ap < 128; ap++) {
            float4 s = *(const float4*)(Ss + ap * 16 + c4g * 4);
            float m0 = Ms[a0 * 128 + ap];
            float m1 = Ms[(a0 + 64) * 128 + ap];
            ns0.x -= m0 * s.x; ns0.y -= m0 * s.y; ns0.z -= m0 * s.z; ns0.w -= m0 * s.w;
            ns1.x -= m1 * s.x; ns1.y -= m1 * s.y; ns1.z -= m1 * s.z; ns1.w -= m1 * s.w;
        }
        __syncthreads();
        *(float4*)(Ss + a0 * 16 + c4g * 4) = ns0;
        *(float4*)(Ss + (a0 + 64) * 16 + c4g * 4) = ns1;
        __syncthreads();
    }
}

// ---------------- gated RMSNorm * silu(z) -> bf16 hi/lo --------------------------
__global__ __launch_bounds__(128) void norm_kernel(const float* __restrict__ core,
        const float* __restrict__ qkvz, const float* __restrict__ nw,
        __nv_bfloat16* __restrict__ hh, __nv_bfloat16* __restrict__ hl)
{
    int bth = blockIdx.x;
    int d = threadIdx.x;
    float cv = core[(size_t)bth * 128 + d];
    float ss = cv * cv;
#pragma unroll
    for (int o = 16; o; o >>= 1) ss += __shfl_xor_sync(0xffffffffu, ss, o);
    __shared__ float red[4];
    if ((d & 31) == 0) red[d >> 5] = ss;
    __syncthreads();
    float tot = red[0] + red[1] + red[2] + red[3];
    float r = rsqrtf(tot * (1.f / 128.f) + 1e-6f);
    float zz = qkvz[(size_t)bth * 512 + 384 + d];
    float sz = zz / (1.f + __expf(-zz));
    float hv = nw[d] * cv * r * sz;
    __nv_bfloat16 h = __float2bfloat16_rn(hv);
    size_t o = (size_t)bth * 128 + d;
    hh[o] = h;
    hl[o] = __float2bfloat16_rn(hv - __bfloat162float(h));
}

// ---------------- launch ---------------------------------------------------------
extern "C" void kernel_launch(void* const* d_in, const int* in_sizes, int n_in,
                              void* d_out, int out_size)
{
    (void)in_sizes; (void)n_in; (void)out_size;
    const float* x    = (const float*)d_in[0];
    const float* Wq   = (const float*)d_in[1];
    const float* Wba  = (const float*)d_in[2];
    const float* cw   = (const float*)d_in[3];
    const float* dtb  = (const float*)d_in[4];
    const float* Alog = (const float*)d_in[5];
    const float* nw   = (const float*)d_in[6];
    const float* Wout = (const float*)d_in[7];
    float* out = (float*)d_out;

    float *qkvz, *bab, *convb, *gb, *betab, *Pb, *Lb, *Mb, *Ub, *eglb, *coreb;
    __nv_bfloat16 *xh, *xl, *w1h, *w1l, *w2h, *w2l, *hh, *hl;
    cudaGetSymbolAddress((void**)&qkvz,  g_qkvz);
    cudaGetSymbolAddress((void**)&bab,   g_ba);
    cudaGetSymbolAddress((void**)&convb, g_conv);
    cudaGetSymbolAddress((void**)&gb,    g_g);
    cudaGetSymbolAddress((void**)&betab, g_beta);
    cudaGetSymbolAddress((void**)&Pb,    g_P);
    cudaGetSymbolAddress((void**)&Lb,    g_L);
    cudaGetSymbolAddress((void**)&Mb,    g_M);
    cudaGetSymbolAddress((void**)&Ub,    g_U);
    cudaGetSymbolAddress((void**)&eglb,  g_egl);
    cudaGetSymbolAddress((void**)&coreb, g_core);
    cudaGetSymbolAddress((void**)&xh,  g_xh);
    cudaGetSymbolAddress((void**)&xl,  g_xl);
    cudaGetSymbolAddress((void**)&w1h, g_w1h);
    cudaGetSymbolAddress((void**)&w1l, g_w1l);
    cudaGetSymbolAddress((void**)&w2h, g_w2h);
    cudaGetSymbolAddress((void**)&w2l, g_w2l);
    cudaGetSymbolAddress((void**)&hh,  g_hh);
    cudaGetSymbolAddress((void**)&hl,  g_hl);

    cudaFuncSetAttribute(phaseA_kernel, cudaFuncAttributeMaxDynamicSharedMemorySize, PA_SMEM);
    cudaFuncSetAttribute(phaseB_kernel, cudaFuncAttributeMaxDynamicSharedMemorySize, PB_SMEM);

    // 0. operand conversion (bandwidth-bound, ~40us total)
    cvt_split_kernel<<<(BB * TT * CC / 4) / 256, 256>>>(x, xh, xl);
    transpose_split_kernel<<<dim3(4096 / 32, CC / 32), 256>>>(Wq, w1h, w1l, CC, 4096);
    transpose_split_kernel<<<dim3(1024 / 32, CC / 32), 256>>>(Wout, w2h, w2l, CC, 1024);

    // 1. qkvz = x @ W_qkvz  (3xbf16-split tensor-core)
    dim3 g1(4096 / 128, 8192 / 128);
    bf16gemm128<<<g1, 256>>>(BB * TT, 4096, CC, xh, xl, w1h, w1l, qkvz);
    // 2. ba = x @ W_ba
    ba_kernel<<<BB * TT, 256>>>(x, Wba, bab);
    // 3. conv + silu
    conv_silu_kernel<<<(BB * TT * 3072) / 256, 256>>>(qkvz, cw, convb);
    // 4. g, beta
    gbeta_kernel<<<(BB * TT * NH) / 256, 256>>>(bab, dtb, Alog, gb, betab);
    // 5. phase A
    phaseA_kernel<<<NCID, 256, PA_SMEM>>>(convb, gb, betab, Pb, Lb, Mb, Ub, eglb);
    // 6. phase B
    dim3 gB(16, 8);
    phaseB_kernel<<<gB, 256, PB_SMEM>>>(Pb, Lb, Mb, Ub, eglb, coreb);
    // 7. gated RMSNorm * silu(z) -> bf16 hi/lo
    norm_kernel<<<BB * TT * NH, 128>>>(coreb, qkvz, nw, hh, hl);
    // 8. final projection (3xbf16-split tensor-core)
    dim3 g2(1024 / 128, 8192 / 128);
    bf16gemm128<<<g2, 256>>>(BB * TT, 1024, CC, hh, hl, w2h, w2l, out);
}

// round 6
// speedup vs baseline: 1.6254x; 1.0147x over previous
#include <cuda_runtime.h>
#include <cuda_bf16.h>
#include <math.h>

// Problem constants
#define BB 2
#define TT 4096
#define CC 1024
#define NH 8
#define DD 128
#define CHK 64
#define NCHUNK 64            // T / CHK
#define NCID 1024            // BB*NH*NCHUNK

// ---------------- scratch (device globals; no allocation allowed) ----------------
__device__ float g_qkvz[(size_t)BB*TT*4096];     // x @ W_qkvz      (B,T,8,512)
__device__ float g_ba[(size_t)BB*TT*16];         // x @ W_ba
__device__ float g_conv[(size_t)BB*TT*3072];     // conv+silu [q|k|v]
__device__ float g_g[(size_t)BB*TT*NH];
__device__ float g_beta[(size_t)BB*TT*NH];
__device__ float g_P[(size_t)NCID*64*128];       // qeff - attn@k_cum
__device__ float g_L[(size_t)NCID*64*128];       // attn@v_new
__device__ float g_M[(size_t)NCID*128*128];      // keff^T @ k_cum
__device__ float g_U[(size_t)NCID*128*128];      // keff^T @ v_new
__device__ float g_egl[NCID];                    // exp(g_last)
__device__ float g_core[(size_t)BB*TT*NH*DD];    // delta-rule output

// bf16 hi/lo split operands for the two big GEMMs
__device__ __nv_bfloat16 g_xh[(size_t)BB*TT*CC],  g_xl[(size_t)BB*TT*CC];
__device__ __nv_bfloat16 g_w1h[(size_t)4096*CC],  g_w1l[(size_t)4096*CC];   // W_qkvz^T [N][K]
__device__ __nv_bfloat16 g_w2h[(size_t)1024*CC],  g_w2l[(size_t)1024*CC];   // W_out^T  [N][K]
__device__ __nv_bfloat16 g_hh[(size_t)BB*TT*1024], g_hl[(size_t)BB*TT*1024];

// ---------------- split/transpose conversion kernels ----------------------------
__global__ __launch_bounds__(256) void cvt_split_kernel(const float* __restrict__ in,
        __nv_bfloat16* __restrict__ oh, __nv_bfloat16* __restrict__ ol)
{
    int i = blockIdx.x * 256 + threadIdx.x;            // indexes float4
    float4 v = ((const float4*)in)[i];
    float f[4] = {v.x, v.y, v.z, v.w};
    __nv_bfloat16 h[4], l[4];
#pragma unroll
    for (int e = 0; e < 4; e++) {
        h[e] = __float2bfloat16_rn(f[e]);
        l[e] = __float2bfloat16_rn(f[e] - __bfloat162float(h[e]));
    }
    __nv_bfloat162 h0; h0.x = h[0]; h0.y = h[1];
    __nv_bfloat162 h1; h1.x = h[2]; h1.y = h[3];
    __nv_bfloat162 l0; l0.x = l[0]; l0.y = l[1];
    __nv_bfloat162 l1; l1.x = l[2]; l1.y = l[3];
    ((__nv_bfloat162*)oh)[i * 2]     = h0;
    ((__nv_bfloat162*)oh)[i * 2 + 1] = h1;
    ((__nv_bfloat162*)ol)[i * 2]     = l0;
    ((__nv_bfloat162*)ol)[i * 2 + 1] = l1;
}

// W [K][N] f32 -> Wt [N][K] bf16 hi/lo
__global__ __launch_bounds__(256) void transpose_split_kernel(const float* __restrict__ W,
        __nv_bfloat16* __restrict__ oh, __nv_bfloat16* __restrict__ ol, int K, int N)
{
    __shared__ float tile[32][33];
    int n0 = blockIdx.x * 32, k0 = blockIdx.y * 32;
    int tx = threadIdx.x & 31, ty0 = threadIdx.x >> 5;
#pragma unroll
    for (int ty = ty0; ty < 32; ty += 8)
        tile[ty][tx] = W[(size_t)(k0 + ty) * N + n0 + tx];
    __syncthreads();
#pragma unroll
    for (int ty = ty0; ty < 32; ty += 8) {
        float v = tile[tx][ty];
        __nv_bfloat16 h = __float2bfloat16_rn(v);
        size_t o = (size_t)(n0 + ty) * K + k0 + tx;
        oh[o] = h;
        ol[o] = __float2bfloat16_rn(v - __bfloat162float(h));
    }
}

// ---------------- asm helpers ----------------------------------------------------
#define MMA_BF16(C, Ar, Br)                                                    \
    asm volatile("mma.sync.aligned.m16n8k16.row.col.f32.bf16.bf16.f32 "        \
        "{%0,%1,%2,%3}, {%4,%5,%6,%7}, {%8,%9}, {%0,%1,%2,%3};"                \
        : "+f"((C)[0]), "+f"((C)[1]), "+f"((C)[2]), "+f"((C)[3])               \
        : "r"((Ar)[0]), "r"((Ar)[1]), "r"((Ar)[2]), "r"((Ar)[3]),              \
          "r"((Br)[0]), "r"((Br)[1]))

#define LDSM4(R0, R1, R2, R3, ADDR)                                            \
    asm volatile("ldmatrix.sync.aligned.m8n8.x4.shared.b16 {%0,%1,%2,%3}, [%4];" \
        : "=r"(R0), "=r"(R1), "=r"(R2), "=r"(R3) : "r"(ADDR))

#define CP_ASYNC16(DST, SRC)                                                   \
    asm volatile("cp.async.cg.shared.global [%0], [%1], 16;" :: "r"(DST), "l"(SRC))
#define CP_COMMIT() asm volatile("cp.async.commit_group;" ::: "memory")
#define CP_WAIT0()  asm volatile("cp.async.wait_group 0;" ::: "memory")
#define CP_WAIT1()  asm volatile("cp.async.wait_group 1;" ::: "memory")

// ---------------- 3xBF16-split GEMM: C = A(MxK)@B^T(NxK), pre-split bf16 --------
// ldmatrix fragment loads + cp.async double-buffered staging.
#define GKS 40                                   // bf16 k-stride (80B rows, conflict-free)
#define STG_ELEM (4 * 128 * GKS)                 // elements per stage (4 arrays)
#define STG_BYTES (STG_ELEM * 2)                 // 40960 bytes
#define ARR_BYTES (128 * GKS * 2)                // 10240 bytes per array
#define GEMM_SMEM (2 * STG_BYTES)                // 81920 bytes

__global__ __launch_bounds__(256) void bf16gemm128(int M, int N, int K,
        const __nv_bfloat16* __restrict__ Ah_, const __nv_bfloat16* __restrict__ Al_,
        const __nv_bfloat16* __restrict__ Bth_, const __nv_bfloat16* __restrict__ Btl_,
        float* __restrict__ Cm)
{
    extern __shared__ __nv_bfloat16 gsm[];
    unsigned smemBase = (unsigned)__cvta_generic_to_shared(gsm);

    int tid = threadIdx.x;
    int brow = blockIdx.y * 128, bcol = blockIdx.x * 128;
    int warp = tid >> 5, lane = tid & 31;
    int wm = (warp & 1) * 64, wn = (warp >> 1) * 32;
    int lr = lane >> 2, lc2 = (lane & 3) * 2;

    // staging indices: 2 chunks per thread per array
    int r0s = tid >> 2, kg0 = (tid & 3) * 8;             // u = 0
    int r1s = (tid + 256) >> 2, kg1 = (tid & 3) * 8;     // u = 1 (same kg)
    unsigned d0 = (unsigned)(r0s * GKS + kg0) * 2;
    unsigned d1 = (unsigned)(r1s * GKS + kg1) * 2;
    const __nv_bfloat16* srcA0h = Ah_  + (size_t)(brow + r0s) * K + kg0;
    const __nv_bfloat16* srcA1h = Ah_  + (size_t)(brow + r1s) * K + kg1;
    const __nv_bfloat16* srcA0l = Al_  + (size_t)(brow + r0s) * K + kg0;
    const __nv_bfloat16* srcA1l = Al_  + (size_t)(brow + r1s) * K + kg1;
    const __nv_bfloat16* srcB0h = Bth_ + (size_t)(bcol + r0s) * K + kg0;
    const __nv_bfloat16* srcB1h = Bth_ + (size_t)(bcol + r1s) * K + kg1;
    const __nv_bfloat16* srcB0l = Btl_ + (size_t)(bcol + r0s) * K + kg0;
    const __nv_bfloat16* srcB1l = Btl_ + (size_t)(bcol + r1s) * K + kg1;

    // ldmatrix per-lane byte offsets (within an array)
    unsigned aoff = (unsigned)(((wm + (lane & 15)) * GKS) + ((lane >> 4) * 8)) * 2;
    unsigned boff = (unsigned)(((wn + (lane & 7) + (((lane >> 4) & 1) * 8)) * GKS)
                               + (((lane >> 3) & 1) * 8)) * 2;

    float c[4][4][4];
#pragma unroll
    for (int mt = 0; mt < 4; mt++)
#pragma unroll
        for (int nt = 0; nt < 4; nt++)
#pragma unroll
            for (int e = 0; e < 4; e++) c[mt][nt][e] = 0.f;

    // prologue: stage k0 = 0 into buffer 0
    {
        unsigned sb = smemBase;
        CP_ASYNC16(sb + d0,                 srcA0h);
        CP_ASYNC16(sb + d1,                 srcA1h);
        CP_ASYNC16(sb + ARR_BYTES + d0,     srcA0l);
        CP_ASYNC16(sb + ARR_BYTES + d1,     srcA1l);
        CP_ASYNC16(sb + 2 * ARR_BYTES + d0, srcB0h);
        CP_ASYNC16(sb + 2 * ARR_BYTES + d1, srcB1h);
        CP_ASYNC16(sb + 3 * ARR_BYTES + d0, srcB0l);
        CP_ASYNC16(sb + 3 * ARR_BYTES + d1, srcB1l);
        CP_COMMIT();
    }

    int buf = 0;
    for (int k0 = 0; k0 < K; k0 += 32) {
        bool hasNext = (k0 + 32) < K;
        if (hasNext) {
            unsigned sb = smemBase + (buf ^ 1) * STG_BYTES;
            int kn = k0 + 32;
            CP_ASYNC16(sb + d0,                 srcA0h + kn);
            CP_ASYNC16(sb + d1,                 srcA1h + kn);
            CP_ASYNC16(sb + ARR_BYTES + d0,     srcA0l + kn);
            CP_ASYNC16(sb + ARR_BYTES + d1,     srcA1l + kn);
            CP_ASYNC16(sb + 2 * ARR_BYTES + d0, srcB0h + kn);
            CP_ASYNC16(sb + 2 * ARR_BYTES + d1, srcB1h + kn);
            CP_ASYNC16(sb + 3 * ARR_BYTES + d0, srcB0l + kn);
            CP_ASYNC16(sb + 3 * ARR_BYTES + d1, srcB1l + kn);
            CP_COMMIT();
            CP_WAIT1();
        } else {
            CP_WAIT0();
        }
        __syncthreads();

        unsigned aBh = smemBase + buf * STG_BYTES;
        unsigned aBl = aBh + ARR_BYTES;
        unsigned bBh = aBh + 2 * ARR_BYTES;
        unsigned bBl = aBh + 3 * ARR_BYTES;

#pragma unroll
        for (int kk = 0; kk < 32; kk += 16) {
            unsigned ah[4][4], al[4][4], bh[2][4], bl[2][4];
#pragma unroll
            for (int mt = 0; mt < 4; mt++) {
                unsigned off = aoff + (unsigned)(mt * 16 * GKS + kk) * 2;
                LDSM4(ah[mt][0], ah[mt][1], ah[mt][2], ah[mt][3], aBh + off);
                LDSM4(al[mt][0], al[mt][1], al[mt][2], al[mt][3], aBl + off);
            }
#pragma unroll
            for (int p = 0; p < 2; p++) {
                unsigned off = boff + (unsigned)(p * 16 * GKS + kk) * 2;
                LDSM4(bh[p][0], bh[p][1], bh[p][2], bh[p][3], bBh + off);
                LDSM4(bl[p][0], bl[p][1], bl[p][2], bl[p][3], bBl + off);
            }
#pragma unroll
            for (int mt = 0; mt < 4; mt++)
#pragma unroll
                for (int nt = 0; nt < 4; nt++) {
                    unsigned* bhp = &bh[nt >> 1][(nt & 1) * 2];
                    unsigned* blp = &bl[nt >> 1][(nt & 1) * 2];
                    MMA_BF16(c[mt][nt], ah[mt], bhp);
                    MMA_BF16(c[mt][nt], al[mt], bhp);
                    MMA_BF16(c[mt][nt], ah[mt], blp);
                }
        }
        __syncthreads();
        buf ^= 1;
    }

#pragma unroll
    for (int mt = 0; mt < 4; mt++) {
        int r0 = brow + wm + mt * 16 + lr;
#pragma unroll
        for (int nt = 0; nt < 4; nt++) {
            int cn = bcol + wn + nt * 8 + lc2;
            *(float2*)(Cm + (size_t)r0 * N + cn)       = make_float2(c[mt][nt][0], c[mt][nt][1]);
            *(float2*)(Cm + (size_t)(r0 + 8) * N + cn) = make_float2(c[mt][nt][2], c[mt][nt][3]);
        }
    }
}

// ---------------- ba = x @ W_ba (N = 16) ----------------------------------------
__global__ __launch_bounds__(256) void ba_kernel(const float* __restrict__ x,
        const float* __restrict__ Wba, float* __restrict__ out)
{
    int bt = blockIdx.x;
    __shared__ float xs[1024];
    const float* xrow = x + (size_t)bt * 1024;
    for (int i = threadIdx.x; i < 256; i += 256)
        ((float4*)xs)[i] = ((const float4*)xrow)[i];
    __syncthreads();
    int o = threadIdx.x >> 4, p = threadIdx.x & 15;
    float acc = 0.f;
    for (int k = p; k < 1024; k += 16) acc += xs[k] * Wba[(size_t)k * 16 + o];
    acc += __shfl_down_sync(0xffffffffu, acc, 8);
    acc += __shfl_down_sync(0xffffffffu, acc, 4);
    acc += __shfl_down_sync(0xffffffffu, acc, 2);
    acc += __shfl_down_sync(0xffffffffu, acc, 1);
    if (p == 0) out[(size_t)bt * 16 + o] = acc;
}

// ---------------- causal depthwise conv (K=4) + silu ----------------------------
__global__ __launch_bounds__(256) void conv_silu_kernel(const float* __restrict__ qkvz,
        const float* __restrict__ cw, float* __restrict__ out)
{
    int idx = blockIdx.x * 256 + threadIdx.x;
    int ch = idx % 3072;
    int btrow = idx / 3072;
    int t = btrow & (TT - 1);
    int part = ch >> 10;
    int hc = (ch & 1023) >> 7;
    int d = ch & 127;
    int po = (part == 0) ? 0 : (part == 1) ? 128 : 256;
    float acc = 0.f;
#pragma unroll
    for (int j = 0; j < 4; j++) {
        int tt2 = t - 3 + j;
        if (tt2 >= 0) {
            float v = qkvz[(((size_t)(btrow - 3 + j)) * 8 + hc) * 512 + po + d];
            acc += v * cw[ch * 4 + j];
        }
    }
    out[(size_t)idx] = acc / (1.f + __expf(-acc));
}

// ---------------- g, beta --------------------------------------------------------
__global__ __launch_bounds__(256) void gbeta_kernel(const float* __restrict__ ba,
        const float* __restrict__ dtb, const float* __restrict__ Alog,
        float* __restrict__ g, float* __restrict__ beta)
{
    int idx = blockIdx.x * 256 + threadIdx.x;
    int h = idx & 7;
    int bt = idx >> 3;
    float bv = ba[(size_t)bt * 16 + h * 2];
    float av = ba[(size_t)bt * 16 + h * 2 + 1];
    beta[idx] = 1.f / (1.f + expf(-bv));
    float xx = av + dtb[h];
    float sp = (xx > 20.f) ? xx : log1pf(expf(xx));
    g[idx] = -expf(Alog[h]) * sp;
}

// ---------------- Phase A: per-chunk local operators (register-tiled) -----------
#define KST 68
#define PA_SMEM ((128*KST*2 + 64*256 + 64*64 + 256) * 4)

__global__ __launch_bounds__(256) void phaseA_kernel(const float* __restrict__ conv,
        const float* __restrict__ gbuf, const float* __restrict__ betabuf,
        float* __restrict__ Pout, float* __restrict__ Lout,
        float* __restrict__ Mout, float* __restrict__ Uout, float* __restrict__ eglout)
{
    extern __shared__ float sm[];
    float* kst = sm;
    float* qst = kst + 128 * KST;
    float* ws  = qst + 128 * KST;
    float* As  = ws + 64 * 256;
    float* gc  = As + 64 * 64;
    float* egc = gc + 64;
    float* egr = egc + 64;
    float* bts = egr + 64;

    int cid = blockIdx.x;
    int n = cid & 63, bh = cid >> 6, h = bh & 7, b = bh >> 3;
    int tid = threadIdx.x;
    int warp = tid >> 5, lane = tid & 31;
    int t0 = n * 64;

    if (tid < 64) {
        int t = t0 + tid;
        gc[tid]  = gbuf[((size_t)(b * TT + t)) * 8 + h];
        bts[tid] = betabuf[((size_t)(b * TT + t)) * 8 + h];
    }
    __syncthreads();
#pragma unroll
    for (int off = 1; off < 64; off <<= 1) {
        float v = 0.f;
        if (tid < 64 && tid >= off) v = gc[tid - off];
        __syncthreads();
        if (tid < 64 && tid >= off) gc[tid] += v;
        __syncthreads();
    }
    if (tid < 64) {
        egc[tid] = __expf(gc[tid]);
        egr[tid] = __expf(gc[63] - gc[tid]);
    }
    __syncthreads();

    for (int r = warp; r < 64; r += 8) {
        int t = t0 + r;
        const float* base = conv + ((size_t)(b * TT + t)) * 3072 + h * 128;
        float qv[4], kv[4];
        float ssq = 0.f, ssk = 0.f;
#pragma unroll
        for (int u = 0; u < 4; u++) {
            qv[u] = base[lane + u * 32];
            kv[u] = base[1024 + lane + u * 32];
            ssq += qv[u] * qv[u];
            ssk += kv[u] * kv[u];
        }
#pragma unroll
        for (int off = 16; off; off >>= 1) {
            ssq += __shfl_xor_sync(0xffffffffu, ssq, off);
            ssk += __shfl_xor_sync(0xffffffffu, ssk, off);
        }
        float rq = rsqrtf(ssq + 1e-6f) * 0.08838834764831845f;
        float rk = rsqrtf(ssk + 1e-6f);
        float bbv = bts[r], egv = egc[r];
#pragma unroll
        for (int u = 0; u < 4; u++) {
            int d = lane + u * 32;
            qst[d * KST + r] = qv[u] * rq;
            float kn = kv[u] * rk;
            kst[d * KST + r] = kn;
            ws[r * 256 + d]       = base[2048 + d] * bbv;
            ws[r * 256 + 128 + d] = kn * bbv * egv;
        }
    }
    __syncthreads();

    int ti = tid >> 4, tj = tid & 15;

    {
        float acc[4][4];
#pragma unroll
        for (int r = 0; r < 4; r++)
#pragma unroll
            for (int s = 0; s < 4; s++) acc[r][s] = 0.f;
        const float* ka = kst + ti * 4;
        const float* kb = kst + tj * 4;
#pragma unroll 4
        for (int d = 0; d < 128; d++) {
            float4 a = *(const float4*)(ka + d * KST);
            float4 bq = *(const float4*)(kb + d * KST);
            float ra[4] = {a.x, a.y, a.z, a.w};
            float rb[4] = {bq.x, bq.y, bq.z, bq.w};
#pragma unroll
            for (int r = 0; r < 4; r++)
#pragma unroll
                for (int s = 0; s < 4; s++) acc[r][s] += ra[r] * rb[s];
        }
#pragma unroll
        for (int r = 0; r < 4; r++) {
            int i = ti * 4 + r;
#pragma unroll
            for (int s = 0; s < 4; s++) {
                int j = tj * 4 + s;
                As[i * 64 + j] = (j < i) ? acc[r][s] * bts[i] * __expf(gc[i] - gc[j]) : 0.f;
            }
        }
    }
    __syncthreads();

    for (int blk = 0; blk < 4; blk++) {
        if (blk) {
            int tr = tid >> 7, tc = tid & 127;
            float acc[8][2];
#pragma unroll
            for (int r = 0; r < 8; r++) { acc[r][0] = 0.f; acc[r][1] = 0.f; }
            for (int j = 0; j < blk * 16; j++) {
                float2 wv = *(const float2*)(ws + j * 256 + tc * 2);
#pragma unroll
                for (int r = 0; r < 8; r++) {
                    float a = As[(blk * 16 + tr * 8 + r) * 64 + j];
                    acc[r][0] += a * wv.x;
                    acc[r][1] += a * wv.y;
                }
            }
#pragma unroll
            for (int r = 0; r < 8; r++) {
                float* w = ws + (blk * 16 + tr * 8 + r) * 256 + tc * 2;
                w[0] -= acc[r][0];
                w[1] -= acc[r][1];
            }
            __syncthreads();
        }
        {
            int c = tid;
            int i0 = blk * 16;
            for (int i = i0 + 1; i < i0 + 16; i++) {
                float acc = 0.f;
                for (int j = i0; j < i; j++) acc += As[i * 64 + j] * ws[j * 256 + c];
                ws[i * 256 + c] -= acc;
            }
        }
        __syncthreads();
    }

    {
        float acc[4][4];
#pragma unroll
        for (int r = 0; r < 4; r++)
#pragma unroll
            for (int s = 0; s < 4; s++) acc[r][s] = 0.f;
        const float* qa = qst + ti * 4;
        const float* kb = kst + tj * 4;
#pragma unroll 4
        for (int d = 0; d < 128; d++) {
            float4 a = *(const float4*)(qa + d * KST);
            float4 bq = *(const float4*)(kb + d * KST);
            float ra[4] = {a.x, a.y, a.z, a.w};
            float rb[4] = {bq.x, bq.y, bq.z, bq.w};
#pragma unroll
            for (int r = 0; r < 4; r++)
#pragma unroll
                for (int s = 0; s < 4; s++) acc[r][s] += ra[r] * rb[s];
        }
#pragma unroll
        for (int r = 0; r < 4; r++) {
            int i = ti * 4 + r;
#pragma unroll
            for (int s = 0; s < 4; s++) {
                int j = tj * 4 + s;
                As[i * 64 + j] = (j <= i) ? acc[r][s] * __expf(gc[i] - gc[j]) : 0.f;
            }
        }
    }
    __syncthreads();

    {
        int tr = warp;
        int tc = lane;
        float acc[8][8];
#pragma unroll
        for (int r = 0; r < 8; r++)
#pragma unroll
            for (int u = 0; u < 8; u++) acc[r][u] = 0.f;
        int jmax = tr * 8 + 8;
        for (int j = 0; j < jmax; j++) {
            float av[8];
#pragma unroll
            for (int r = 0; r < 8; r++) av[r] = As[(tr * 8 + r) * 64 + j];
            float4 w0 = *(const float4*)(ws + j * 256 + tc * 8);
            float4 w1 = *(const float4*)(ws + j * 256 + tc * 8 + 4);
            float rb[8] = {w0.x, w0.y, w0.z, w0.w, w1.x, w1.y, w1.z, w1.w};
#pragma unroll
            for (int r = 0; r < 8; r++)
#pragma unroll
                for (int u = 0; u < 8; u++) acc[r][u] += av[r] * rb[u];
        }
        if (tc < 16) {
#pragma unroll
            for (int r = 0; r < 8; r++) {
                int i = tr * 8 + r;
                float* dst = Lout + ((size_t)cid * 64 + i) * 128 + tc * 8;
                *(float4*)(dst)     = make_float4(acc[r][0], acc[r][1], acc[r][2], acc[r][3]);
                *(float4*)(dst + 4) = make_float4(acc[r][4], acc[r][5], acc[r][6], acc[r][7]);
            }
        } else {
            int c0 = tc * 8 - 128;
#pragma unroll
            for (int r = 0; r < 8; r++) {
                int i = tr * 8 + r;
                float eg = egc[i];
                float v[8];
#pragma unroll
                for (int u = 0; u < 8; u++)
                    v[u] = qst[(c0 + u) * KST + i] * eg - acc[r][u];
                float* dst = Pout + ((size_t)cid * 64 + i) * 128 + c0;
                *(float4*)(dst)     = make_float4(v[0], v[1], v[2], v[3]);
                *(float4*)(dst + 4) = make_float4(v[4], v[5], v[6], v[7]);
            }
        }
    }

    {
        int ta = tid >> 4;
        int te = tid & 15;
#pragma unroll
        for (int pass = 0; pass < 2; pass++) {
            float acc[8][8];
#pragma unroll
            for (int r = 0; r < 8; r++)
#pragma unroll
                for (int u = 0; u < 8; u++) acc[r][u] = 0.f;
            for (int i = 0; i < 64; i++) {
                float er = egr[i];
                float av[8];
#pragma unroll
                for (int r = 0; r < 8; r++) av[r] = kst[(ta * 8 + r) * KST + i] * er;
                float4 w0 = *(const float4*)(ws + i * 256 + pass * 128 + te * 8);
                float4 w1 = *(const float4*)(ws + i * 256 + pass * 128 + te * 8 + 4);
                float rb[8] = {w0.x, w0.y, w0.z, w0.w, w1.x, w1.y, w1.z, w1.w};
#pragma unroll
                for (int r = 0; r < 8; r++)
#pragma unroll
                    for (int u = 0; u < 8; u++) acc[r][u] += av[r] * rb[u];
            }
            float* dstb = pass ? Mout : Uout;
#pragma unroll
            for (int r = 0; r < 8; r++) {
                float* dst = dstb + ((size_t)cid * 128 + ta * 8 + r) * 128 + te * 8;
                *(float4*)(dst)     = make_float4(acc[r][0], acc[r][1], acc[r][2], acc[r][3]);
                *(float4*)(dst + 4) = make_float4(acc[r][4], acc[r][5], acc[r][6], acc[r][7]);
            }
        }
    }
    if (tid == 0) eglout[cid] = __expf(gc[63]);
}

// ---------------- Phase B: sequential scan over chunks, DV split ----------------
#define PB_SMEM ((128*128 + 64*128 + 128*16) * 4)

__global__ __launch_bounds__(256) void phaseB_kernel(const float* __restrict__ Pm,
        const float* __restrict__ Lm, const float* __restrict__ Mm,
        const float* __restrict__ Um, const float* __restrict__ eglv,
        float* __restrict__ core)
{
    extern __shared__ float sm[];
    float* Ms = sm;
    float* Ps = Ms + 128 * 128;
    float* Ss = Ps + 64 * 128;

    int bh = blockIdx.x, gg = blockIdx.y;
    int b = bh >> 3, h = bh & 7;
    int tid = threadIdx.x;
    int c4g = tid & 3;
    int a0 = tid >> 2;
    int c0 = gg * 16;

    for (int i = tid; i < 128 * 16; i += 256) Ss[i] = 0.f;
    __syncthreads();

    for (int n = 0; n < 64; n++) {
        size_t cid = (size_t)bh * 64 + n;
        const float4* Mg = (const float4*)(Mm + cid * 16384);
        float4* Ms4 = (float4*)Ms;
        for (int i = tid; i < 4096; i += 256) Ms4[i] = Mg[i];
        const float4* Pg = (const float4*)(Pm + cid * 8192);
        float4* Ps4 = (float4*)Ps;
        for (int i = tid; i < 2048; i += 256) Ps4[i] = Pg[i];
        __syncthreads();

        {
            float4 acc = *(const float4*)(Lm + cid * 8192 + a0 * 128 + c0 + c4g * 4);
            for (int a = 0; a < 128; a++) {
                float p = Ps[a0 * 128 + a];
                float4 s = *(const float4*)(Ss + a * 16 + c4g * 4);
                acc.x += p * s.x; acc.y += p * s.y; acc.z += p * s.z; acc.w += p * s.w;
            }
            int t = n * 64 + a0;
            *(float4*)(core + (((size_t)(b * TT + t)) * 8 + h) * 128 + c0 + c4g * 4) = acc;
        }

        float eg = eglv[cid];
        float4 s0 = *(const float4*)(Ss + a0 * 16 + c4g * 4);
        float4 s1 = *(const float4*)(Ss + (a0 + 64) * 16 + c4g * 4);
        float4 ns0 = *(const float4*)(Um + cid * 16384 + (size_t)a0 * 128 + c0 + c4g * 4);
        float4 ns1 = *(const float4*)(Um + cid * 16384 + (size_t)(a0 + 64) * 128 + c0 + c4g * 4);
        ns0.x += eg * s0.x; ns0.y += eg * s0.y; ns0.z += eg * s0.z; ns0.w += eg * s0.w;
        ns1.x += eg * s1.x; ns1.y += eg * s1.y; ns1.z += eg * s1.z; ns1.w += eg * s1.w;
        for (int ap = 0; ap < 128; ap++) {
            float4 s = *(const float4*)(Ss + ap * 16 + c4g * 4);
            float m0 = Ms[a0 * 128 + ap];
            float m1 = Ms[(a0 + 64) * 128 + ap];
            ns0.x -= m0 * s.x; ns0.y -= m0 * s.y; ns0.z -= m0 * s.z; ns0.w -= m0 * s.w;
            ns1.x -= m1 * s.x; ns1.y -= m1 * s.y; ns1.z -= m1 * s.z; ns1.w -= m1 * s.w;
        }
        __syncthreads();
        *(float4*)(Ss + a0 * 16 + c4g * 4) = ns0;
        *(float4*)(Ss + (a0 + 64) * 16 + c4g * 4) = ns1;
        __syncthreads();
    }
}

// ---------------- gated RMSNorm * silu(z) -> bf16 hi/lo --------------------------
__global__ __launch_bounds__(128) void norm_kernel(const float* __restrict__ core,
        const float* __restrict__ qkvz, const float* __restrict__ nw,
        __nv_bfloat16* __restrict__ hh, __nv_bfloat16* __restrict__ hl)
{
    int bth = blockIdx.x;
    int d = threadIdx.x;
    float cv = core[(size_t)bth * 128 + d];
    float ss = cv * cv;
#pragma unroll
    for (int o = 16; o; o >>= 1) ss += __shfl_xor_sync(0xffffffffu, ss, o);
    __shared__ float red[4];
    if ((d & 31) == 0) red[d >> 5] = ss;
    __syncthreads();
    float tot = red[0] + red[1] + red[2] + red[3];
    float r = rsqrtf(tot * (1.f / 128.f) + 1e-6f);
    float zz = qkvz[(size_t)bth * 512 + 384 + d];
    float sz = zz / (1.f + __expf(-zz));
    float hv = nw[d] * cv * r * sz;
    __nv_bfloat16 h = __float2bfloat16_rn(hv);
    size_t o = (size_t)bth * 128 + d;
    hh[o] = h;
    hl[o] = __float2bfloat16_rn(hv - __bfloat162float(h));
}

// ---------------- launch ---------------------------------------------------------
extern "C" void kernel_launch(void* const* d_in, const int* in_sizes, int n_in,
                              void* d_out, int out_size)
{
    (void)in_sizes; (void)n_in; (void)out_size;
    const float* x    = (const float*)d_in[0];
    const float* Wq   = (const float*)d_in[1];
    const float* Wba  = (const float*)d_in[2];
    const float* cw   = (const float*)d_in[3];
    const float* dtb  = (const float*)d_in[4];
    const float* Alog = (const float*)d_in[5];
    const float* nw   = (const float*)d_in[6];
    const float* Wout = (const float*)d_in[7];
    float* out = (float*)d_out;

    float *qkvz, *bab, *convb, *gb, *betab, *Pb, *Lb, *Mb, *Ub, *eglb, *coreb;
    __nv_bfloat16 *xh, *xl, *w1h, *w1l, *w2h, *w2l, *hh, *hl;
    cudaGetSymbolAddress((void**)&qkvz,  g_qkvz);
    cudaGetSymbolAddress((void**)&bab,   g_ba);
    cudaGetSymbolAddress((void**)&convb, g_conv);
    cudaGetSymbolAddress((void**)&gb,    g_g);
    cudaGetSymbolAddress((void**)&betab, g_beta);
    cudaGetSymbolAddress((void**)&Pb,    g_P);
    cudaGetSymbolAddress((void**)&Lb,    g_L);
    cudaGetSymbolAddress((void**)&Mb,    g_M);
    cudaGetSymbolAddress((void**)&Ub,    g_U);
    cudaGetSymbolAddress((void**)&eglb,  g_egl);
    cudaGetSymbolAddress((void**)&coreb, g_core);
    cudaGetSymbolAddress((void**)&xh,  g_xh);
    cudaGetSymbolAddress((void**)&xl,  g_xl);
    cudaGetSymbolAddress((void**)&w1h, g_w1h);
    cudaGetSymbolAddress((void**)&w1l, g_w1l);
    cudaGetSymbolAddress((void**)&w2h, g_w2h);
    cudaGetSymbolAddress((void**)&w2l, g_w2l);
    cudaGetSymbolAddress((void**)&hh,  g_hh);
    cudaGetSymbolAddress((void**)&hl,  g_hl);

    cudaFuncSetAttribute(phaseA_kernel, cudaFuncAttributeMaxDynamicSharedMemorySize, PA_SMEM);
    cudaFuncSetAttribute(phaseB_kernel, cudaFuncAttributeMaxDynamicSharedMemorySize, PB_SMEM);
    cudaFuncSetAttribute(bf16gemm128, cudaFuncAttributeMaxDynamicSharedMemorySize, GEMM_SMEM);

    // 0. operand conversion (bandwidth-bound)
    cvt_split_kernel<<<(BB * TT * CC / 4) / 256, 256>>>(x, xh, xl);
    transpose_split_kernel<<<dim3(4096 / 32, CC / 32), 256>>>(Wq, w1h, w1l, CC, 4096);
    transpose_split_kernel<<<dim3(1024 / 32, CC / 32), 256>>>(Wout, w2h, w2l, CC, 1024);

    // 1. qkvz = x @ W_qkvz
    dim3 g1(4096 / 128, 8192 / 128);
    bf16gemm128<<<g1, 256, GEMM_SMEM>>>(BB * TT, 4096, CC, xh, xl, w1h, w1l, qkvz);
    // 2. ba = x @ W_ba
    ba_kernel<<<BB * TT, 256>>>(x, Wba, bab);
    // 3. conv + silu
    conv_silu_kernel<<<(BB * TT * 3072) / 256, 256>>>(qkvz, cw, convb);
    // 4. g, beta
    gbeta_kernel<<<(BB * TT * NH) / 256, 256>>>(bab, dtb, Alog, gb, betab);
    // 5. phase A
    phaseA_kernel<<<NCID, 256, PA_SMEM>>>(convb, gb, betab, Pb, Lb, Mb, Ub, eglb);
    // 6. phase B
    dim3 gB(16, 8);
    phaseB_kernel<<<gB, 256, PB_SMEM>>>(Pb, Lb, Mb, Ub, eglb, coreb);
    // 7. gated RMSNorm * silu(z) -> bf16 hi/lo
    norm_kernel<<<BB * TT * NH, 128>>>(coreb, qkvz, nw, hh, hl);
    // 8. final projection
    dim3 g2(1024 / 128, 8192 / 128);
    bf16gemm128<<<g2, 256, GEMM_SMEM>>>(BB * TT, 1024, CC, hh, hl, w2h, w2l, out);
}

// round 8
// speedup vs baseline: 1.7102x; 1.0522x over previous
#include <cuda_runtime.h>
#include <cuda_bf16.h>
#include <math.h>

// Problem constants
#define BB 2
#define TT 4096
#define CC 1024
#define NH 8
#define DD 128
#define CHK 64
#define NCHUNK 64            // T / CHK
#define NCID 1024            // BB*NH*NCHUNK

// ---------------- scratch (device globals; no allocation allowed) ----------------
__device__ float g_qkvz[(size_t)BB*TT*4096];     // x @ W_qkvz      (B,T,8,512)
__device__ float g_ba[(size_t)BB*TT*16];         // x @ W_ba
__device__ float g_conv[(size_t)BB*TT*3072];     // conv+silu [q|k|v]
__device__ float g_g[(size_t)BB*TT*NH];
__device__ float g_beta[(size_t)BB*TT*NH];
__device__ float g_P[(size_t)NCID*64*128];       // qeff - attn@k_cum
__device__ float g_L[(size_t)NCID*64*128];       // attn@v_new
__device__ float g_M[(size_t)NCID*128*128];      // keff^T @ k_cum
__device__ float g_U[(size_t)NCID*128*128];      // keff^T @ v_new
__device__ float g_egl[NCID];                    // exp(g_last)
__device__ float g_core[(size_t)BB*TT*NH*DD];    // delta-rule output

// bf16 hi/lo split operands for the two big GEMMs
__device__ __nv_bfloat16 g_xh[(size_t)BB*TT*CC],  g_xl[(size_t)BB*TT*CC];
__device__ __nv_bfloat16 g_w1h[(size_t)4096*CC],  g_w1l[(size_t)4096*CC];   // W_qkvz^T [N][K]
__device__ __nv_bfloat16 g_w2h[(size_t)1024*CC],  g_w2l[(size_t)1024*CC];   // W_out^T  [N][K]
__device__ __nv_bfloat16 g_hh[(size_t)BB*TT*1024], g_hl[(size_t)BB*TT*1024];

// ---------------- split/transpose conversion kernels ----------------------------
__global__ __launch_bounds__(256) void cvt_split_kernel(const float* __restrict__ in,
        __nv_bfloat16* __restrict__ oh, __nv_bfloat16* __restrict__ ol)
{
    int i = blockIdx.x * 256 + threadIdx.x;            // indexes float4
    float4 v = ((const float4*)in)[i];
    float f[4] = {v.x, v.y, v.z, v.w};
    __nv_bfloat16 h[4], l[4];
#pragma unroll
    for (int e = 0; e < 4; e++) {
        h[e] = __float2bfloat16_rn(f[e]);
        l[e] = __float2bfloat16_rn(f[e] - __bfloat162float(h[e]));
    }
    __nv_bfloat162 h0; h0.x = h[0]; h0.y = h[1];
    __nv_bfloat162 h1; h1.x = h[2]; h1.y = h[3];
    __nv_bfloat162 l0; l0.x = l[0]; l0.y = l[1];
    __nv_bfloat162 l1; l1.x = l[2]; l1.y = l[3];
    ((__nv_bfloat162*)oh)[i * 2]     = h0;
    ((__nv_bfloat162*)oh)[i * 2 + 1] = h1;
    ((__nv_bfloat162*)ol)[i * 2]     = l0;
    ((__nv_bfloat162*)ol)[i * 2 + 1] = l1;
}

// W [K][N] f32 -> Wt [N][K] bf16 hi/lo
__global__ __launch_bounds__(256) void transpose_split_kernel(const float* __restrict__ W,
        __nv_bfloat16* __restrict__ oh, __nv_bfloat16* __restrict__ ol, int K, int N)
{
    __shared__ float tile[32][33];
    int n0 = blockIdx.x * 32, k0 = blockIdx.y * 32;
    int tx = threadIdx.x & 31, ty0 = threadIdx.x >> 5;
#pragma unroll
    for (int ty = ty0; ty < 32; ty += 8)
        tile[ty][tx] = W[(size_t)(k0 + ty) * N + n0 + tx];
    __syncthreads();
#pragma unroll
    for (int ty = ty0; ty < 32; ty += 8) {
        float v = tile[tx][ty];
        __nv_bfloat16 h = __float2bfloat16_rn(v);
        size_t o = (size_t)(n0 + ty) * K + k0 + tx;
        oh[o] = h;
        ol[o] = __float2bfloat16_rn(v - __bfloat162float(h));
    }
}

// ---------------- asm helpers ----------------------------------------------------
#define MMA_BF16(C, Ar, Br)                                                    \
    asm volatile("mma.sync.aligned.m16n8k16.row.col.f32.bf16.bf16.f32 "        \
        "{%0,%1,%2,%3}, {%4,%5,%6,%7}, {%8,%9}, {%0,%1,%2,%3};"                \
        : "+f"((C)[0]), "+f"((C)[1]), "+f"((C)[2]), "+f"((C)[3])               \
        : "r"((Ar)[0]), "r"((Ar)[1]), "r"((Ar)[2]), "r"((Ar)[3]),              \
          "r"((Br)[0]), "r"((Br)[1]))

#define LDSM4(R0, R1, R2, R3, ADDR)                                            \
    asm volatile("ldmatrix.sync.aligned.m8n8.x4.shared.b16 {%0,%1,%2,%3}, [%4];" \
        : "=r"(R0), "=r"(R1), "=r"(R2), "=r"(R3) : "r"(ADDR))

#define CP_ASYNC16(DST, SRC)                                                   \
    asm volatile("cp.async.cg.shared.global [%0], [%1], 16;" :: "r"(DST), "l"(SRC))
#define CP_COMMIT() asm volatile("cp.async.commit_group;" ::: "memory")
#define CP_WAIT0()  asm volatile("cp.async.wait_group 0;" ::: "memory")
#define CP_WAIT1()  asm volatile("cp.async.wait_group 1;" ::: "memory")

// ---------------- 3xBF16-split GEMM: C = A(MxK)@B^T(NxK), pre-split bf16 --------
// ldmatrix fragment loads + cp.async double-buffered staging, 2 blocks/SM.
#define GKS 40                                   // bf16 k-stride (80B rows, conflict-free)
#define STG_ELEM (4 * 128 * GKS)                 // elements per stage (4 arrays)
#define STG_BYTES (STG_ELEM * 2)                 // 40960 bytes
#define ARR_BYTES (128 * GKS * 2)                // 10240 bytes per array
#define GEMM_SMEM (2 * STG_BYTES)                // 81920 bytes

__global__ __launch_bounds__(256, 2) void bf16gemm128(int M, int N, int K,
        const __nv_bfloat16* __restrict__ Ah_, const __nv_bfloat16* __restrict__ Al_,
        const __nv_bfloat16* __restrict__ Bth_, const __nv_bfloat16* __restrict__ Btl_,
        float* __restrict__ Cm)
{
    extern __shared__ __nv_bfloat16 gsm[];
    unsigned smemBase = (unsigned)__cvta_generic_to_shared(gsm);

    int tid = threadIdx.x;
    int brow = blockIdx.y * 128, bcol = blockIdx.x * 128;
    int warp = tid >> 5, lane = tid & 31;
    int wm = (warp & 1) * 64, wn = (warp >> 1) * 32;
    int lr = lane >> 2, lc2 = (lane & 3) * 2;

    // staging indices: 2 chunks per thread per array
    int r0s = tid >> 2, kg0 = (tid & 3) * 8;             // u = 0
    int r1s = (tid + 256) >> 2, kg1 = (tid & 3) * 8;     // u = 1 (same kg)
    unsigned d0 = (unsigned)(r0s * GKS + kg0) * 2;
    unsigned d1 = (unsigned)(r1s * GKS + kg1) * 2;
    const __nv_bfloat16* srcA0h = Ah_  + (size_t)(brow + r0s) * K + kg0;
    const __nv_bfloat16* srcA1h = Ah_  + (size_t)(brow + r1s) * K + kg1;
    const __nv_bfloat16* srcA0l = Al_  + (size_t)(brow + r0s) * K + kg0;
    const __nv_bfloat16* srcA1l = Al_  + (size_t)(brow + r1s) * K + kg1;
    const __nv_bfloat16* srcB0h = Bth_ + (size_t)(bcol + r0s) * K + kg0;
    const __nv_bfloat16* srcB1h = Bth_ + (size_t)(bcol + r1s) * K + kg1;
    const __nv_bfloat16* srcB0l = Btl_ + (size_t)(bcol + r0s) * K + kg0;
    const __nv_bfloat16* srcB1l = Btl_ + (size_t)(bcol + r1s) * K + kg1;

    // ldmatrix per-lane byte offsets (within an array)
    unsigned aoff = (unsigned)(((wm + (lane & 15)) * GKS) + ((lane >> 4) * 8)) * 2;
    unsigned boff = (unsigned)(((wn + (lane & 7) + (((lane >> 4) & 1) * 8)) * GKS)
                               + (((lane >> 3) & 1) * 8)) * 2;

    float c[4][4][4];
#pragma unroll
    for (int mt = 0; mt < 4; mt++)
#pragma unroll
        for (int nt = 0; nt < 4; nt++)
#pragma unroll
            for (int e = 0; e < 4; e++) c[mt][nt][e] = 0.f;

    // prologue: stage k0 = 0 into buffer 0
    {
        unsigned sb = smemBase;
        CP_ASYNC16(sb + d0,                 srcA0h);
        CP_ASYNC16(sb + d1,                 srcA1h);
        CP_ASYNC16(sb + ARR_BYTES + d0,     srcA0l);
        CP_ASYNC16(sb + ARR_BYTES + d1,     srcA1l);
        CP_ASYNC16(sb + 2 * ARR_BYTES + d0, srcB0h);
        CP_ASYNC16(sb + 2 * ARR_BYTES + d1, srcB1h);
        CP_ASYNC16(sb + 3 * ARR_BYTES + d0, srcB0l);
        CP_ASYNC16(sb + 3 * ARR_BYTES + d1, srcB1l);
        CP_COMMIT();
    }

    int buf = 0;
    for (int k0 = 0; k0 < K; k0 += 32) {
        bool hasNext = (k0 + 32) < K;
        if (hasNext) {
            unsigned sb = smemBase + (buf ^ 1) * STG_BYTES;
            int kn = k0 + 32;
            CP_ASYNC16(sb + d0,                 srcA0h + kn);
            CP_ASYNC16(sb + d1,                 srcA1h + kn);
            CP_ASYNC16(sb + ARR_BYTES + d0,     srcA0l + kn);
            CP_ASYNC16(sb + ARR_BYTES + d1,     srcA1l + kn);
            CP_ASYNC16(sb + 2 * ARR_BYTES + d0, srcB0h + kn);
            CP_ASYNC16(sb + 2 * ARR_BYTES + d1, srcB1h + kn);
            CP_ASYNC16(sb + 3 * ARR_BYTES + d0, srcB0l + kn);
            CP_ASYNC16(sb + 3 * ARR_BYTES + d1, srcB1l + kn);
            CP_COMMIT();
            CP_WAIT1();
        } else {
            CP_WAIT0();
        }
        __syncthreads();

        unsigned aBh = smemBase + buf * STG_BYTES;
        unsigned aBl = aBh + ARR_BYTES;
        unsigned bBh = aBh + 2 * ARR_BYTES;
        unsigned bBl = aBh + 3 * ARR_BYTES;

#pragma unroll
        for (int kk = 0; kk < 32; kk += 16) {
            unsigned ah[4][4], al[4][4], bh[2][4], bl[2][4];
#pragma unroll
            for (int mt = 0; mt < 4; mt++) {
                unsigned off = aoff + (unsigned)(mt * 16 * GKS + kk) * 2;
                LDSM4(ah[mt][0], ah[mt][1], ah[mt][2], ah[mt][3], aBh + off);
                LDSM4(al[mt][0], al[mt][1], al[mt][2], al[mt][3], aBl + off);
            }
#pragma unroll
            for (int p = 0; p < 2; p++) {
                unsigned off = boff + (unsigned)(p * 16 * GKS + kk) * 2;
                LDSM4(bh[p][0], bh[p][1], bh[p][2], bh[p][3], bBh + off);
                LDSM4(bl[p][0], bl[p][1], bl[p][2], bl[p][3], bBl + off);
            }
#pragma unroll
            for (int mt = 0; mt < 4; mt++)
#pragma unroll
                for (int nt = 0; nt < 4; nt++) {
                    unsigned* bhp = &bh[nt >> 1][(nt & 1) * 2];
                    unsigned* blp = &bl[nt >> 1][(nt & 1) * 2];
                    MMA_BF16(c[mt][nt], ah[mt], bhp);
                    MMA_BF16(c[mt][nt], al[mt], bhp);
                    MMA_BF16(c[mt][nt], ah[mt], blp);
                }
        }
        __syncthreads();
        buf ^= 1;
    }

#pragma unroll
    for (int mt = 0; mt < 4; mt++) {
        int r0 = brow + wm + mt * 16 + lr;
#pragma unroll
        for (int nt = 0; nt < 4; nt++) {
            int cn = bcol + wn + nt * 8 + lc2;
            *(float2*)(Cm + (size_t)r0 * N + cn)       = make_float2(c[mt][nt][0], c[mt][nt][1]);
            *(float2*)(Cm + (size_t)(r0 + 8) * N + cn) = make_float2(c[mt][nt][2], c[mt][nt][3]);
        }
    }
}

// ---------------- ba = x @ W_ba (N = 16) ----------------------------------------
__global__ __launch_bounds__(256) void ba_kernel(const float* __restrict__ x,
        const float* __restrict__ Wba, float* __restrict__ out)
{
    int bt = blockIdx.x;
    __shared__ float xs[1024];
    const float* xrow = x + (size_t)bt * 1024;
    for (int i = threadIdx.x; i < 256; i += 256)
        ((float4*)xs)[i] = ((const float4*)xrow)[i];
    __syncthreads();
    int o = threadIdx.x >> 4, p = threadIdx.x & 15;
    float acc = 0.f;
    for (int k = p; k < 1024; k += 16) acc += xs[k] * Wba[(size_t)k * 16 + o];
    acc += __shfl_down_sync(0xffffffffu, acc, 8);
    acc += __shfl_down_sync(0xffffffffu, acc, 4);
    acc += __shfl_down_sync(0xffffffffu, acc, 2);
    acc += __shfl_down_sync(0xffffffffu, acc, 1);
    if (p == 0) out[(size_t)bt * 16 + o] = acc;
}

// ---------------- causal depthwise conv (K=4) + silu ----------------------------
__global__ __launch_bounds__(256) void conv_silu_kernel(const float* __restrict__ qkvz,
        const float* __restrict__ cw, float* __restrict__ out)
{
    int idx = blockIdx.x * 256 + threadIdx.x;
    int ch = idx % 3072;
    int btrow = idx / 3072;
    int t = btrow & (TT - 1);
    int part = ch >> 10;
    int hc = (ch & 1023) >> 7;
    int d = ch & 127;
    int po = (part == 0) ? 0 : (part == 1) ? 128 : 256;
    float acc = 0.f;
#pragma unroll
    for (int j = 0; j < 4; j++) {
        int tt2 = t - 3 + j;
        if (tt2 >= 0) {
            float v = qkvz[(((size_t)(btrow - 3 + j)) * 8 + hc) * 512 + po + d];
            acc += v * cw[ch * 4 + j];
        }
    }
    out[(size_t)idx] = acc / (1.f + __expf(-acc));
}

// ---------------- g, beta --------------------------------------------------------
__global__ __launch_bounds__(256) void gbeta_kernel(const float* __restrict__ ba,
        const float* __restrict__ dtb, const float* __restrict__ Alog,
        float* __restrict__ g, float* __restrict__ beta)
{
    int idx = blockIdx.x * 256 + threadIdx.x;
    int h = idx & 7;
    int bt = idx >> 3;
    float bv = ba[(size_t)bt * 16 + h * 2];
    float av = ba[(size_t)bt * 16 + h * 2 + 1];
    beta[idx] = 1.f / (1.f + expf(-bv));
    float xx = av + dtb[h];
    float sp = (xx > 20.f) ? xx : log1pf(expf(xx));
    g[idx] = -expf(Alog[h]) * sp;
}

// ---------------- Phase A: per-chunk local operators (register-tiled) -----------
#define KST 68
#define PA_SMEM ((128*KST*2 + 64*256 + 64*64 + 256) * 4)

__global__ __launch_bounds__(256) void phaseA_kernel(const float* __restrict__ conv,
        const float* __restrict__ gbuf, const float* __restrict__ betabuf,
        float* __restrict__ Pout, float* __restrict__ Lout,
        float* __restrict__ Mout, float* __restrict__ Uout, float* __restrict__ eglout)
{
    extern __shared__ float sm[];
    float* kst = sm;
    float* qst = kst + 128 * KST;
    float* ws  = qst + 128 * KST;
    float* As  = ws + 64 * 256;
    float* gc  = As + 64 * 64;
    float* egc = gc + 64;
    float* egr = egc + 64;
    float* bts = egr + 64;

    int cid = blockIdx.x;
    int n = cid & 63, bh = cid >> 6, h = bh & 7, b = bh >> 3;
    int tid = threadIdx.x;
    int warp = tid >> 5, lane = tid & 31;
    int t0 = n * 64;

    if (tid < 64) {
        int t = t0 + tid;
        gc[tid]  = gbuf[((size_t)(b * TT + t)) * 8 + h];
        bts[tid] = betabuf[((size_t)(b * TT + t)) * 8 + h];
    }
    __syncthreads();
#pragma unroll
    for (int off = 1; off < 64; off <<= 1) {
        float v = 0.f;
        if (tid < 64 && tid >= off) v = gc[tid - off];
        __syncthreads();
        if (tid < 64 && tid >= off) gc[tid] += v;
        __syncthreads();
    }
    if (tid < 64) {
        egc[tid] = __expf(gc[tid]);
        egr[tid] = __expf(gc[63] - gc[tid]);
    }
    __syncthreads();

    for (int r = warp; r < 64; r += 8) {
        int t = t0 + r;
        const float* base = conv + ((size_t)(b * TT + t)) * 3072 + h * 128;
        float qv[4], kv[4];
        float ssq = 0.f, ssk = 0.f;
#pragma unroll
        for (int u = 0; u < 4; u++) {
            qv[u] = base[lane + u * 32];
            kv[u] = base[1024 + lane + u * 32];
            ssq += qv[u] * qv[u];
            ssk += kv[u] * kv[u];
        }
#pragma unroll
        for (int off = 16; off; off >>= 1) {
            ssq += __shfl_xor_sync(0xffffffffu, ssq, off);
            ssk += __shfl_xor_sync(0xffffffffu, ssk, off);
        }
        float rq = rsqrtf(ssq + 1e-6f) * 0.08838834764831845f;
        float rk = rsqrtf(ssk + 1e-6f);
        float bbv = bts[r], egv = egc[r];
#pragma unroll
        for (int u = 0; u < 4; u++) {
            int d = lane + u * 32;
            qst[d * KST + r] = qv[u] * rq;
            float kn = kv[u] * rk;
            kst[d * KST + r] = kn;
            ws[r * 256 + d]       = base[2048 + d] * bbv;
            ws[r * 256 + 128 + d] = kn * bbv * egv;
        }
    }
    __syncthreads();

    int ti = tid >> 4, tj = tid & 15;

    {
        float acc[4][4];
#pragma unroll
        for (int r = 0; r < 4; r++)
#pragma unroll
            for (int s = 0; s < 4; s++) acc[r][s] = 0.f;
        const float* ka = kst + ti * 4;
        const float* kb = kst + tj * 4;
#pragma unroll 4
        for (int d = 0; d < 128; d++) {
            float4 a = *(const float4*)(ka + d * KST);
            float4 bq = *(const float4*)(kb + d * KST);
            float ra[4] = {a.x, a.y, a.z, a.w};
            float rb[4] = {bq.x, bq.y, bq.z, bq.w};
#pragma unroll
            for (int r = 0; r < 4; r++)
#pragma unroll
                for (int s = 0; s < 4; s++) acc[r][s] += ra[r] * rb[s];
        }
#pragma unroll
        for (int r = 0; r < 4; r++) {
            int i = ti * 4 + r;
#pragma unroll
            for (int s = 0; s < 4; s++) {
                int j = tj * 4 + s;
                As[i * 64 + j] = (j < i) ? acc[r][s] * bts[i] * __expf(gc[i] - gc[j]) : 0.f;
            }
        }
    }
    __syncthreads();

    for (int blk = 0; blk < 4; blk++) {
        if (blk) {
            int tr = tid >> 7, tc = tid & 127;
            float acc[8][2];
#pragma unroll
            for (int r = 0; r < 8; r++) { acc[r][0] = 0.f; acc[r][1] = 0.f; }
            for (int j = 0; j < blk * 16; j++) {
                float2 wv = *(const float2*)(ws + j * 256 + tc * 2);
#pragma unroll
                for (int r = 0; r < 8; r++) {
                    float a = As[(blk * 16 + tr * 8 + r) * 64 + j];
                    acc[r][0] += a * wv.x;
                    acc[r][1] += a * wv.y;
                }
            }
#pragma unroll
            for (int r = 0; r < 8; r++) {
                float* w = ws + (blk * 16 + tr * 8 + r) * 256 + tc * 2;
                w[0] -= acc[r][0];
                w[1] -= acc[r][1];
            }
            __syncthreads();
        }
        {
            int c = tid;
            int i0 = blk * 16;
            for (int i = i0 + 1; i < i0 + 16; i++) {
                float acc = 0.f;
                for (int j = i0; j < i; j++) acc += As[i * 64 + j] * ws[j * 256 + c];
                ws[i * 256 + c] -= acc;
            }
        }
        __syncthreads();
    }

    {
        float acc[4][4];
#pragma unroll
        for (int r = 0; r < 4; r++)
#pragma unroll
            for (int s = 0; s < 4; s++) acc[r][s] = 0.f;
        const float* qa = qst + ti * 4;
        const float* kb = kst + tj * 4;
#pragma unroll 4
        for (int d = 0; d < 128; d++) {
            float4 a = *(const float4*)(qa + d * KST);
            float4 bq = *(const float4*)(kb + d * KST);
            float ra[4] = {a.x, a.y, a.z, a.w};
            float rb[4] = {bq.x, bq.y, bq.z, bq.w};
#pragma unroll
            for (int r = 0; r < 4; r++)
#pragma unroll
                for (int s = 0; s < 4; s++) acc[r][s] += ra[r] * rb[s];
        }
#pragma unroll
        for (int r = 0; r < 4; r++) {
            int i = ti * 4 + r;
#pragma unroll
            for (int s = 0; s < 4; s++) {
                int j = tj * 4 + s;
                As[i * 64 + j] = (j <= i) ? acc[r][s] * __expf(gc[i] - gc[j]) : 0.f;
            }
        }
    }
    __syncthreads();

    {
        int tr = warp;
        int tc = lane;
        float acc[8][8];
#pragma unroll
        for (int r = 0; r < 8; r++)
#pragma unroll
            for (int u = 0; u < 8; u++) acc[r][u] = 0.f;
        int jmax = tr * 8 + 8;
        for (int j = 0; j < jmax; j++) {
            float av[8];
#pragma unroll
            for (int r = 0; r < 8; r++) av[r] = As[(tr * 8 + r) * 64 + j];
            float4 w0 = *(const float4*)(ws + j * 256 + tc * 8);
            float4 w1 = *(const float4*)(ws + j * 256 + tc * 8 + 4);
            float rb[8] = {w0.x, w0.y, w0.z, w0.w, w1.x, w1.y, w1.z, w1.w};
#pragma unroll
            for (int r = 0; r < 8; r++)
#pragma unroll
                for (int u = 0; u < 8; u++) acc[r][u] += av[r] * rb[u];
        }
        if (tc < 16) {
#pragma unroll
            for (int r = 0; r < 8; r++) {
                int i = tr * 8 + r;
                float* dst = Lout + ((size_t)cid * 64 + i) * 128 + tc * 8;
                *(float4*)(dst)     = make_float4(acc[r][0], acc[r][1], acc[r][2], acc[r][3]);
                *(float4*)(dst + 4) = make_float4(acc[r][4], acc[r][5], acc[r][6], acc[r][7]);
            }
        } else {
            int c0 = tc * 8 - 128;
#pragma unroll
            for (int r = 0; r < 8; r++) {
                int i = tr * 8 + r;
                float eg = egc[i];
                float v[8];
#pragma unroll
                for (int u = 0; u < 8; u++)
                    v[u] = qst[(c0 + u) * KST + i] * eg - acc[r][u];
                float* dst = Pout + ((size_t)cid * 64 + i) * 128 + c0;
                *(float4*)(dst)     = make_float4(v[0], v[1], v[2], v[3]);
                *(float4*)(dst + 4) = make_float4(v[4], v[5], v[6], v[7]);
            }
        }
    }

    {
        int ta = tid >> 4;
        int te = tid & 15;
#pragma unroll
        for (int pass = 0; pass < 2; pass++) {
            float acc[8][8];
#pragma unroll
            for (int r = 0; r < 8; r++)
#pragma unroll
                for (int u = 0; u < 8; u++) acc[r][u] = 0.f;
            for (int i = 0; i < 64; i++) {
                float er = egr[i];
                float av[8];
#pragma unroll
                for (int r = 0; r < 8; r++) av[r] = kst[(ta * 8 + r) * KST + i] * er;
                float4 w0 = *(const float4*)(ws + i * 256 + pass * 128 + te * 8);
                float4 w1 = *(const float4*)(ws + i * 256 + pass * 128 + te * 8 + 4);
                float rb[8] = {w0.x, w0.y, w0.z, w0.w, w1.x, w1.y, w1.z, w1.w};
#pragma unroll
                for (int r = 0; r < 8; r++)
#pragma unroll
                    for (int u = 0; u < 8; u++) acc[r][u] += av[r] * rb[u];
            }
            float* dstb = pass ? Mout : Uout;
#pragma unroll
            for (int r = 0; r < 8; r++) {
                float* dst = dstb + ((size_t)cid * 128 + ta * 8 + r) * 128 + te * 8;
                *(float4*)(dst)     = make_float4(acc[r][0], acc[r][1], acc[r][2], acc[r][3]);
                *(float4*)(dst + 4) = make_float4(acc[r][4], acc[r][5], acc[r][6], acc[r][7]);
            }
        }
    }
    if (tid == 0) eglout[cid] = __expf(gc[63]);
}

// ---------------- Phase B: sequential scan over chunks, DV split ----------------
#define PB_SMEM ((128*128 + 64*128 + 128*16) * 4)

__global__ __launch_bounds__(256) void phaseB_kernel(const float* __restrict__ Pm,
        const float* __restrict__ Lm, const float* __restrict__ Mm,
        const float* __restrict__ Um, const float* __restrict__ eglv,
        float* __restrict__ core)
{
    extern __shared__ float sm[];
    float* Ms = sm;
    float* Ps = Ms + 128 * 128;
    float* Ss = Ps + 64 * 128;

    int bh = blockIdx.x, gg = blockIdx.y;
    int b = bh >> 3, h = bh & 7;
    int tid = threadIdx.x;
    int c4g = tid & 3;
    int a0 = tid >> 2;
    int c0 = gg * 16;

    for (int i = tid; i < 128 * 16; i += 256) Ss[i] = 0.f;
    __syncthreads();

    for (int n = 0; n < 64; n++) {
        size_t cid = (size_t)bh * 64 + n;
        const float4* Mg = (const float4*)(Mm + cid * 16384);
        float4* Ms4 = (float4*)Ms;
        for (int i = tid; i < 4096; i += 256) Ms4[i] = Mg[i];
        const float4* Pg = (const float4*)(Pm + cid * 8192);
        float4* Ps4 = (float4*)Ps;
        for (int i = tid; i < 2048; i += 256) Ps4[i] = Pg[i];
        __syncthreads();

        {
            float4 acc = *(const float4*)(Lm + cid * 8192 + a0 * 128 + c0 + c4g * 4);
            for (int a = 0; a < 128; a++) {
                float p = Ps[a0 * 128 + a];
                float4 s = *(const float4*)(Ss + a * 16 + c4g * 4);
                acc.x += p * s.x; acc.y += p * s.y; acc.z += p * s.z; acc.w += p * s.w;
            }
            int t = n * 64 + a0;
            *(float4*)(core + (((size_t)(b * TT + t)) * 8 + h) * 128 + c0 + c4g * 4) = acc;
        }

        float eg = eglv[cid];
        float4 s0 = *(const float4*)(Ss + a0 * 16 + c4g * 4);
        float4 s1 = *(const float4*)(Ss + (a0 + 64) * 16 + c4g * 4);
        float4 ns0 = *(const float4*)(Um + cid * 16384 + (size_t)a0 * 128 + c0 + c4g * 4);
        float4 ns1 = *(const float4*)(Um + cid * 16384 + (size_t)(a0 + 64) * 128 + c0 + c4g * 4);
        ns0.x += eg * s0.x; ns0.y += eg * s0.y; ns0.z += eg * s0.z; ns0.w += eg * s0.w;
        ns1.x += eg * s1.x; ns1.y += eg * s1.y; ns1.z += eg * s1.z; ns1.w += eg * s1.w;
        for (int ap = 0; ap < 128; ap++) {
            float4 s = *(const float4*)(Ss + ap * 16 + c4g * 4);
            float m0 = Ms[a0 * 128 + ap];
            float m1 = Ms[(a0 + 64) * 128 + ap];
            ns0.x -= m0 * s.x; ns0.y -= m0 * s.y; ns0.z -= m0 * s.z; ns0.w -= m0 * s.w;
            ns1.x -= m1 * s.x; ns1.y -= m1 * s.y; ns1.z -= m1 * s.z; ns1.w -= m1 * s.w;
        }
        __syncthreads();
        *(float4*)(Ss + a0 * 16 + c4g * 4) = ns0;
        *(float4*)(Ss + (a0 + 64) * 16 + c4g * 4) = ns1;
        __syncthreads();
    }
}

// ---------------- gated RMSNorm * silu(z) -> bf16 hi/lo --------------------------
__global__ __launch_bounds__(128) void norm_kernel(const float* __restrict__ core,
        const float* __restrict__ qkvz, const float* __restrict__ nw,
        __nv_bfloat16* __restrict__ hh, __nv_bfloat16* __restrict__ hl)
{
    int bth = blockIdx.x;
    int d = threadIdx.x;
    float cv = core[(size_t)bth * 128 + d];
    float ss = cv * cv;
#pragma unroll
    for (int o = 16; o; o >>= 1) ss += __shfl_xor_sync(0xffffffffu, ss, o);
    __shared__ float red[4];
    if ((d & 31) == 0) red[d >> 5] = ss;
    __syncthreads();
    float tot = red[0] + red[1] + red[2] + red[3];
    float r = rsqrtf(tot * (1.f / 128.f) + 1e-6f);
    float zz = qkvz[(size_t)bth * 512 + 384 + d];
    float sz = zz / (1.f + __expf(-zz));
    float hv = nw[d] * cv * r * sz;
    __nv_bfloat16 h = __float2bfloat16_rn(hv);
    size_t o = (size_t)bth * 128 + d;
    hh[o] = h;
    hl[o] = __float2bfloat16_rn(hv - __bfloat162float(h));
}

// ---------------- launch ---------------------------------------------------------
extern "C" void kernel_launch(void* const* d_in, const int* in_sizes, int n_in,
                              void* d_out, int out_size)
{
    (void)in_sizes; (void)n_in; (void)out_size;
    const float* x    = (const float*)d_in[0];
    const float* Wq   = (const float*)d_in[1];
    const float* Wba  = (const float*)d_in[2];
    const float* cw   = (const float*)d_in[3];
    const float* dtb  = (const float*)d_in[4];
    const float* Alog = (const float*)d_in[5];
    const float* nw   = (const float*)d_in[6];
    const float* Wout = (const float*)d_in[7];
    float* out = (float*)d_out;

    float *qkvz, *bab, *convb, *gb, *betab, *Pb, *Lb, *Mb, *Ub, *eglb, *coreb;
    __nv_bfloat16 *xh, *xl, *w1h, *w1l, *w2h, *w2l, *hh, *hl;
    cudaGetSymbolAddress((void**)&qkvz,  g_qkvz);
    cudaGetSymbolAddress((void**)&bab,   g_ba);
    cudaGetSymbolAddress((void**)&convb, g_conv);
    cudaGetSymbolAddress((void**)&gb,    g_g);
    cudaGetSymbolAddress((void**)&betab, g_beta);
    cudaGetSymbolAddress((void**)&Pb,    g_P);
    cudaGetSymbolAddress((void**)&Lb,    g_L);
    cudaGetSymbolAddress((void**)&Mb,    g_M);
    cudaGetSymbolAddress((void**)&Ub,    g_U);
    cudaGetSymbolAddress((void**)&eglb,  g_egl);
    cudaGetSymbolAddress((void**)&coreb, g_core);
    cudaGetSymbolAddress((void**)&xh,  g_xh);
    cudaGetSymbolAddress((void**)&xl,  g_xl);
    cudaGetSymbolAddress((void**)&w1h, g_w1h);
    cudaGetSymbolAddress((void**)&w1l, g_w1l);
    cudaGetSymbolAddress((void**)&w2h, g_w2h);
    cudaGetSymbolAddress((void**)&w2l, g_w2l);
    cudaGetSymbolAddress((void**)&hh,  g_hh);
    cudaGetSymbolAddress((void**)&hl,  g_hl);

    cudaFuncSetAttribute(phaseA_kernel, cudaFuncAttributeMaxDynamicSharedMemorySize, PA_SMEM);
    cudaFuncSetAttribute(phaseB_kernel, cudaFuncAttributeMaxDynamicSharedMemorySize, PB_SMEM);
    cudaFuncSetAttribute(bf16gemm128, cudaFuncAttributeMaxDynamicSharedMemorySize, GEMM_SMEM);

    // 0. operand conversion (bandwidth-bound)
    cvt_split_kernel<<<(BB * TT * CC / 4) / 256, 256>>>(x, xh, xl);
    transpose_split_kernel<<<dim3(4096 / 32, CC / 32), 256>>>(Wq, w1h, w1l, CC, 4096);
    transpose_split_kernel<<<dim3(1024 / 32, CC / 32), 256>>>(Wout, w2h, w2l, CC, 1024);

    // 1. qkvz = x @ W_qkvz
    dim3 g1(4096 / 128, 8192 / 128);
    bf16gemm128<<<g1, 256, GEMM_SMEM>>>(BB * TT, 4096, CC, xh, xl, w1h, w1l, qkvz);
    // 2. ba = x @ W_ba
    ba_kernel<<<BB * TT, 256>>>(x, Wba, bab);
    // 3. conv + silu
    conv_silu_kernel<<<(BB * TT * 3072) / 256, 256>>>(qkvz, cw, convb);
    // 4. g, beta
    gbeta_kernel<<<(BB * TT * NH) / 256, 256>>>(bab, dtb, Alog, gb, betab);
    // 5. phase A
    phaseA_kernel<<<NCID, 256, PA_SMEM>>>(convb, gb, betab, Pb, Lb, Mb, Ub, eglb);
    // 6. phase B
    dim3 gB(16, 8);
    phaseB_kernel<<<gB, 256, PB_SMEM>>>(Pb, Lb, Mb, Ub, eglb, coreb);
    // 7. gated RMSNorm * silu(z) -> bf16 hi/lo
    norm_kernel<<<BB * TT * NH, 128>>>(coreb, qkvz, nw, hh, hl);
    // 8. final projection
    dim3 g2(1024 / 128, 8192 / 128);
    bf16gemm128<<<g2, 256, GEMM_SMEM>>>(BB * TT, 1024, CC, hh, hl, w2h, w2l, out);
}

// round 9
// speedup vs baseline: 1.8725x; 1.0949x over previous
#include <cuda_runtime.h>
#include <cuda_bf16.h>
#include <math.h>

// Problem constants
#define BB 2
#define TT 4096
#define CC 1024
#define NH 8
#define DD 128
#define CHK 64
#define NCHUNK 64            // T / CHK
#define NCID 1024            // BB*NH*NCHUNK

// ---------------- scratch (device globals; no allocation allowed) ----------------
__device__ float g_qkvz[(size_t)BB*TT*4096];     // x @ W_qkvz      (B,T,8,512)
__device__ float g_ba[(size_t)BB*TT*16];         // x @ W_ba
__device__ float g_conv[(size_t)BB*TT*3072];     // conv+silu [q|k|v]
__device__ float g_g[(size_t)BB*TT*NH];
__device__ float g_beta[(size_t)BB*TT*NH];
__device__ float g_P[(size_t)NCID*64*128];       // qeff - attn@k_cum
__device__ float g_L[(size_t)NCID*64*128];       // attn@v_new
__device__ float g_M[(size_t)NCID*128*128];      // keff^T @ k_cum
__device__ float g_U[(size_t)NCID*128*128];      // keff^T @ v_new
__device__ float g_egl[NCID];                    // exp(g_last)
__device__ float g_core[(size_t)BB*TT*NH*DD];    // delta-rule output

// bf16 hi/lo split operands for the two big GEMMs
__device__ __nv_bfloat16 g_xh[(size_t)BB*TT*CC],  g_xl[(size_t)BB*TT*CC];
__device__ __nv_bfloat16 g_w1h[(size_t)4096*CC],  g_w1l[(size_t)4096*CC];   // W_qkvz^T [N][K]
__device__ __nv_bfloat16 g_w2h[(size_t)1024*CC],  g_w2l[(size_t)1024*CC];   // W_out^T  [N][K]
__device__ __nv_bfloat16 g_hh[(size_t)BB*TT*1024], g_hl[(size_t)BB*TT*1024];

// ---------------- split/transpose conversion kernels ----------------------------
__global__ __launch_bounds__(256) void cvt_split_kernel(const float* __restrict__ in,
        __nv_bfloat16* __restrict__ oh, __nv_bfloat16* __restrict__ ol)
{
    int i = blockIdx.x * 256 + threadIdx.x;            // indexes float4
    float4 v = ((const float4*)in)[i];
    float f[4] = {v.x, v.y, v.z, v.w};
    __nv_bfloat16 h[4], l[4];
#pragma unroll
    for (int e = 0; e < 4; e++) {
        h[e] = __float2bfloat16_rn(f[e]);
        l[e] = __float2bfloat16_rn(f[e] - __bfloat162float(h[e]));
    }
    __nv_bfloat162 h0; h0.x = h[0]; h0.y = h[1];
    __nv_bfloat162 h1; h1.x = h[2]; h1.y = h[3];
    __nv_bfloat162 l0; l0.x = l[0]; l0.y = l[1];
    __nv_bfloat162 l1; l1.x = l[2]; l1.y = l[3];
    ((__nv_bfloat162*)oh)[i * 2]     = h0;
    ((__nv_bfloat162*)oh)[i * 2 + 1] = h1;
    ((__nv_bfloat162*)ol)[i * 2]     = l0;
    ((__nv_bfloat162*)ol)[i * 2 + 1] = l1;
}

// W [K][N] f32 -> Wt [N][K] bf16 hi/lo
__global__ __launch_bounds__(256) void transpose_split_kernel(const float* __restrict__ W,
        __nv_bfloat16* __restrict__ oh, __nv_bfloat16* __restrict__ ol, int K, int N)
{
    __shared__ float tile[32][33];
    int n0 = blockIdx.x * 32, k0 = blockIdx.y * 32;
    int tx = threadIdx.x & 31, ty0 = threadIdx.x >> 5;
#pragma unroll
    for (int ty = ty0; ty < 32; ty += 8)
        tile[ty][tx] = W[(size_t)(k0 + ty) * N + n0 + tx];
    __syncthreads();
#pragma unroll
    for (int ty = ty0; ty < 32; ty += 8) {
        float v = tile[tx][ty];
        __nv_bfloat16 h = __float2bfloat16_rn(v);
        size_t o = (size_t)(n0 + ty) * K + k0 + tx;
        oh[o] = h;
        ol[o] = __float2bfloat16_rn(v - __bfloat162float(h));
    }
}

// ---------------- asm helpers ----------------------------------------------------
#define MMA_BF16(C, Ar, Br)                                                    \
    asm volatile("mma.sync.aligned.m16n8k16.row.col.f32.bf16.bf16.f32 "        \
        "{%0,%1,%2,%3}, {%4,%5,%6,%7}, {%8,%9}, {%0,%1,%2,%3};"                \
        : "+f"((C)[0]), "+f"((C)[1]), "+f"((C)[2]), "+f"((C)[3])               \
        : "r"((Ar)[0]), "r"((Ar)[1]), "r"((Ar)[2]), "r"((Ar)[3]),              \
          "r"((Br)[0]), "r"((Br)[1]))

#define LDSM4(R0, R1, R2, R3, ADDR)                                            \
    asm volatile("ldmatrix.sync.aligned.m8n8.x4.shared.b16 {%0,%1,%2,%3}, [%4];" \
        : "=r"(R0), "=r"(R1), "=r"(R2), "=r"(R3) : "r"(ADDR))

#define CP_ASYNC16(DST, SRC)                                                   \
    asm volatile("cp.async.cg.shared.global [%0], [%1], 16;" :: "r"(DST), "l"(SRC))
#define CP_COMMIT() asm volatile("cp.async.commit_group;" ::: "memory")
#define CP_WAIT0()  asm volatile("cp.async.wait_group 0;" ::: "memory")
#define CP_WAIT1()  asm volatile("cp.async.wait_group 1;" ::: "memory")

// ---------------- 3xBF16-split GEMM: C = A(MxK)@B^T(NxK), pre-split bf16 --------
// ldmatrix fragment loads + cp.async double-buffered staging, 2 blocks/SM.
#define GKS 40                                   // bf16 k-stride (80B rows, conflict-free)
#define STG_ELEM (4 * 128 * GKS)                 // elements per stage (4 arrays)
#define STG_BYTES (STG_ELEM * 2)                 // 40960 bytes
#define ARR_BYTES (128 * GKS * 2)                // 10240 bytes per array
#define GEMM_SMEM (2 * STG_BYTES)                // 81920 bytes

__global__ __launch_bounds__(256, 2) void bf16gemm128(int M, int N, int K,
        const __nv_bfloat16* __restrict__ Ah_, const __nv_bfloat16* __restrict__ Al_,
        const __nv_bfloat16* __restrict__ Bth_, const __nv_bfloat16* __restrict__ Btl_,
        float* __restrict__ Cm)
{
    extern __shared__ __nv_bfloat16 gsm[];
    unsigned smemBase = (unsigned)__cvta_generic_to_shared(gsm);

    int tid = threadIdx.x;
    int brow = blockIdx.y * 128, bcol = blockIdx.x * 128;
    int warp = tid >> 5, lane = tid & 31;
    int wm = (warp & 1) * 64, wn = (warp >> 1) * 32;
    int lr = lane >> 2, lc2 = (lane & 3) * 2;

    // staging indices: 2 chunks per thread per array
    int r0s = tid >> 2, kg0 = (tid & 3) * 8;             // u = 0
    int r1s = (tid + 256) >> 2, kg1 = (tid & 3) * 8;     // u = 1 (same kg)
    unsigned d0 = (unsigned)(r0s * GKS + kg0) * 2;
    unsigned d1 = (unsigned)(r1s * GKS + kg1) * 2;
    const __nv_bfloat16* srcA0h = Ah_  + (size_t)(brow + r0s) * K + kg0;
    const __nv_bfloat16* srcA1h = Ah_  + (size_t)(brow + r1s) * K + kg1;
    const __nv_bfloat16* srcA0l = Al_  + (size_t)(brow + r0s) * K + kg0;
    const __nv_bfloat16* srcA1l = Al_  + (size_t)(brow + r1s) * K + kg1;
    const __nv_bfloat16* srcB0h = Bth_ + (size_t)(bcol + r0s) * K + kg0;
    const __nv_bfloat16* srcB1h = Bth_ + (size_t)(bcol + r1s) * K + kg1;
    const __nv_bfloat16* srcB0l = Btl_ + (size_t)(bcol + r0s) * K + kg0;
    const __nv_bfloat16* srcB1l = Btl_ + (size_t)(bcol + r1s) * K + kg1;

    // ldmatrix per-lane byte offsets (within an array)
    unsigned aoff = (unsigned)(((wm + (lane & 15)) * GKS) + ((lane >> 4) * 8)) * 2;
    unsigned boff = (unsigned)(((wn + (lane & 7) + (((lane >> 4) & 1) * 8)) * GKS)
                               + (((lane >> 3) & 1) * 8)) * 2;

    float c[4][4][4];
#pragma unroll
    for (int mt = 0; mt < 4; mt++)
#pragma unroll
        for (int nt = 0; nt < 4; nt++)
#pragma unroll
            for (int e = 0; e < 4; e++) c[mt][nt][e] = 0.f;

    // prologue: stage k0 = 0 into buffer 0
    {
        unsigned sb = smemBase;
        CP_ASYNC16(sb + d0,                 srcA0h);
        CP_ASYNC16(sb + d1,                 srcA1h);
        CP_ASYNC16(sb + ARR_BYTES + d0,     srcA0l);
        CP_ASYNC16(sb + ARR_BYTES + d1,     srcA1l);
        CP_ASYNC16(sb + 2 * ARR_BYTES + d0, srcB0h);
        CP_ASYNC16(sb + 2 * ARR_BYTES + d1, srcB1h);
        CP_ASYNC16(sb + 3 * ARR_BYTES + d0, srcB0l);
        CP_ASYNC16(sb + 3 * ARR_BYTES + d1, srcB1l);
        CP_COMMIT();
    }

    int buf = 0;
    for (int k0 = 0; k0 < K; k0 += 32) {
        bool hasNext = (k0 + 32) < K;
        if (hasNext) {
            unsigned sb = smemBase + (buf ^ 1) * STG_BYTES;
            int kn = k0 + 32;
            CP_ASYNC16(sb + d0,                 srcA0h + kn);
            CP_ASYNC16(sb + d1,                 srcA1h + kn);
            CP_ASYNC16(sb + ARR_BYTES + d0,     srcA0l + kn);
            CP_ASYNC16(sb + ARR_BYTES + d1,     srcA1l + kn);
            CP_ASYNC16(sb + 2 * ARR_BYTES + d0, srcB0h + kn);
            CP_ASYNC16(sb + 2 * ARR_BYTES + d1, srcB1h + kn);
            CP_ASYNC16(sb + 3 * ARR_BYTES + d0, srcB0l + kn);
            CP_ASYNC16(sb + 3 * ARR_BYTES + d1, srcB1l + kn);
            CP_COMMIT();
            CP_WAIT1();
        } else {
            CP_WAIT0();
        }
        __syncthreads();

        unsigned aBh = smemBase + buf * STG_BYTES;
        unsigned aBl = aBh + ARR_BYTES;
        unsigned bBh = aBh + 2 * ARR_BYTES;
        unsigned bBl = aBh + 3 * ARR_BYTES;

#pragma unroll
        for (int kk = 0; kk < 32; kk += 16) {
            unsigned ah[4][4], al[4][4], bh[2][4], bl[2][4];
#pragma unroll
            for (int mt = 0; mt < 4; mt++) {
                unsigned off = aoff + (unsigned)(mt * 16 * GKS + kk) * 2;
                LDSM4(ah[mt][0], ah[mt][1], ah[mt][2], ah[mt][3], aBh + off);
                LDSM4(al[mt][0], al[mt][1], al[mt][2], al[mt][3], aBl + off);
            }
#pragma unroll
            for (int p = 0; p < 2; p++) {
                unsigned off = boff + (unsigned)(p * 16 * GKS + kk) * 2;
                LDSM4(bh[p][0], bh[p][1], bh[p][2], bh[p][3], bBh + off);
                LDSM4(bl[p][0], bl[p][1], bl[p][2], bl[p][3], bBl + off);
            }
#pragma unroll
            for (int mt = 0; mt < 4; mt++)
#pragma unroll
                for (int nt = 0; nt < 4; nt++) {
                    unsigned* bhp = &bh[nt >> 1][(nt & 1) * 2];
                    unsigned* blp = &bl[nt >> 1][(nt & 1) * 2];
                    MMA_BF16(c[mt][nt], ah[mt], bhp);
                    MMA_BF16(c[mt][nt], al[mt], bhp);
                    MMA_BF16(c[mt][nt], ah[mt], blp);
                }
        }
        __syncthreads();
        buf ^= 1;
    }

#pragma unroll
    for (int mt = 0; mt < 4; mt++) {
        int r0 = brow + wm + mt * 16 + lr;
#pragma unroll
        for (int nt = 0; nt < 4; nt++) {
            int cn = bcol + wn + nt * 8 + lc2;
            *(float2*)(Cm + (size_t)r0 * N + cn)       = make_float2(c[mt][nt][0], c[mt][nt][1]);
            *(float2*)(Cm + (size_t)(r0 + 8) * N + cn) = make_float2(c[mt][nt][2], c[mt][nt][3]);
        }
    }
}

// ---------------- ba = x @ W_ba (N = 16) ----------------------------------------
__global__ __launch_bounds__(256) void ba_kernel(const float* __restrict__ x,
        const float* __restrict__ Wba, float* __restrict__ out)
{
    int bt = blockIdx.x;
    __shared__ float xs[1024];
    const float* xrow = x + (size_t)bt * 1024;
    for (int i = threadIdx.x; i < 256; i += 256)
        ((float4*)xs)[i] = ((const float4*)xrow)[i];
    __syncthreads();
    int o = threadIdx.x >> 4, p = threadIdx.x & 15;
    float acc = 0.f;
    for (int k = p; k < 1024; k += 16) acc += xs[k] * Wba[(size_t)k * 16 + o];
    acc += __shfl_down_sync(0xffffffffu, acc, 8);
    acc += __shfl_down_sync(0xffffffffu, acc, 4);
    acc += __shfl_down_sync(0xffffffffu, acc, 2);
    acc += __shfl_down_sync(0xffffffffu, acc, 1);
    if (p == 0) out[(size_t)bt * 16 + o] = acc;
}

// ---------------- causal depthwise conv (K=4) + silu ----------------------------
__global__ __launch_bounds__(256) void conv_silu_kernel(const float* __restrict__ qkvz,
        const float* __restrict__ cw, float* __restrict__ out)
{
    int idx = blockIdx.x * 256 + threadIdx.x;
    int ch = idx % 3072;
    int btrow = idx / 3072;
    int t = btrow & (TT - 1);
    int part = ch >> 10;
    int hc = (ch & 1023) >> 7;
    int d = ch & 127;
    int po = (part == 0) ? 0 : (part == 1) ? 128 : 256;
    float acc = 0.f;
#pragma unroll
    for (int j = 0; j < 4; j++) {
        int tt2 = t - 3 + j;
        if (tt2 >= 0) {
            float v = qkvz[(((size_t)(btrow - 3 + j)) * 8 + hc) * 512 + po + d];
            acc += v * cw[ch * 4 + j];
        }
    }
    out[(size_t)idx] = acc / (1.f + __expf(-acc));
}

// ---------------- g, beta --------------------------------------------------------
__global__ __launch_bounds__(256) void gbeta_kernel(const float* __restrict__ ba,
        const float* __restrict__ dtb, const float* __restrict__ Alog,
        float* __restrict__ g, float* __restrict__ beta)
{
    int idx = blockIdx.x * 256 + threadIdx.x;
    int h = idx & 7;
    int bt = idx >> 3;
    float bv = ba[(size_t)bt * 16 + h * 2];
    float av = ba[(size_t)bt * 16 + h * 2 + 1];
    beta[idx] = 1.f / (1.f + expf(-bv));
    float xx = av + dtb[h];
    float sp = (xx > 20.f) ? xx : log1pf(expf(xx));
    g[idx] = -expf(Alog[h]) * sp;
}

// ---------------- Phase A: per-chunk local operators (register-tiled) -----------
// As padded to stride 65 (65 % 32 == 1) so 8-consecutive-row scalar reads hit
// 8 distinct banks instead of one (was stride 64 -> 8-way conflicts).
#define KST 68
#define ASD 65
#define PA_SMEM ((128*KST*2 + 64*256 + 64*ASD + 256) * 4)

__global__ __launch_bounds__(256) void phaseA_kernel(const float* __restrict__ conv,
        const float* __restrict__ gbuf, const float* __restrict__ betabuf,
        float* __restrict__ Pout, float* __restrict__ Lout,
        float* __restrict__ Mout, float* __restrict__ Uout, float* __restrict__ eglout)
{
    extern __shared__ float sm[];
    float* kst = sm;
    float* qst = kst + 128 * KST;
    float* ws  = qst + 128 * KST;
    float* As  = ws + 64 * 256;          // 64 x ASD
    float* gc  = As + 64 * ASD;
    float* egc = gc + 64;
    float* egr = egc + 64;
    float* bts = egr + 64;

    int cid = blockIdx.x;
    int n = cid & 63, bh = cid >> 6, h = bh & 7, b = bh >> 3;
    int tid = threadIdx.x;
    int warp = tid >> 5, lane = tid & 31;
    int t0 = n * 64;

    if (tid < 64) {
        int t = t0 + tid;
        gc[tid]  = gbuf[((size_t)(b * TT + t)) * 8 + h];
        bts[tid] = betabuf[((size_t)(b * TT + t)) * 8 + h];
    }
    __syncthreads();
#pragma unroll
    for (int off = 1; off < 64; off <<= 1) {
        float v = 0.f;
        if (tid < 64 && tid >= off) v = gc[tid - off];
        __syncthreads();
        if (tid < 64 && tid >= off) gc[tid] += v;
        __syncthreads();
    }
    if (tid < 64) {
        egc[tid] = __expf(gc[tid]);
        egr[tid] = __expf(gc[63] - gc[tid]);
    }
    __syncthreads();

    for (int r = warp; r < 64; r += 8) {
        int t = t0 + r;
        const float* base = conv + ((size_t)(b * TT + t)) * 3072 + h * 128;
        float qv[4], kv[4];
        float ssq = 0.f, ssk = 0.f;
#pragma unroll
        for (int u = 0; u < 4; u++) {
            qv[u] = base[lane + u * 32];
            kv[u] = base[1024 + lane + u * 32];
            ssq += qv[u] * qv[u];
            ssk += kv[u] * kv[u];
        }
#pragma unroll
        for (int off = 16; off; off >>= 1) {
            ssq += __shfl_xor_sync(0xffffffffu, ssq, off);
            ssk += __shfl_xor_sync(0xffffffffu, ssk, off);
        }
        float rq = rsqrtf(ssq + 1e-6f) * 0.08838834764831845f;
        float rk = rsqrtf(ssk + 1e-6f);
        float bbv = bts[r], egv = egc[r];
#pragma unroll
        for (int u = 0; u < 4; u++) {
            int d = lane + u * 32;
            qst[d * KST + r] = qv[u] * rq;
            float kn = kv[u] * rk;
            kst[d * KST + r] = kn;
            ws[r * 256 + d]       = base[2048 + d] * bbv;
            ws[r * 256 + 128 + d] = kn * bbv * egv;
        }
    }
    __syncthreads();

    int ti = tid >> 4, tj = tid & 15;

    // A[i][j] = beta_i (k_i . k_j) exp(gc_i - gc_j), j < i; else 0
    {
        float acc[4][4];
#pragma unroll
        for (int r = 0; r < 4; r++)
#pragma unroll
            for (int s = 0; s < 4; s++) acc[r][s] = 0.f;
        const float* ka = kst + ti * 4;
        const float* kb = kst + tj * 4;
#pragma unroll 4
        for (int d = 0; d < 128; d++) {
            float4 a = *(const float4*)(ka + d * KST);
            float4 bq = *(const float4*)(kb + d * KST);
            float ra[4] = {a.x, a.y, a.z, a.w};
            float rb[4] = {bq.x, bq.y, bq.z, bq.w};
#pragma unroll
            for (int r = 0; r < 4; r++)
#pragma unroll
                for (int s = 0; s < 4; s++) acc[r][s] += ra[r] * rb[s];
        }
#pragma unroll
        for (int r = 0; r < 4; r++) {
            int i = ti * 4 + r;
#pragma unroll
            for (int s = 0; s < 4; s++) {
                int j = tj * 4 + s;
                As[i * ASD + j] = (j < i) ? acc[r][s] * bts[i] * __expf(gc[i] - gc[j]) : 0.f;
            }
        }
    }
    __syncthreads();

    // blocked forward substitution: ws <- (I+A)^{-1} ws
    for (int blk = 0; blk < 4; blk++) {
        if (blk) {
            int tr = tid >> 7, tc = tid & 127;
            float acc[8][2];
#pragma unroll
            for (int r = 0; r < 8; r++) { acc[r][0] = 0.f; acc[r][1] = 0.f; }
            for (int j = 0; j < blk * 16; j++) {
                float2 wv = *(const float2*)(ws + j * 256 + tc * 2);
#pragma unroll
                for (int r = 0; r < 8; r++) {
                    float a = As[(blk * 16 + tr * 8 + r) * ASD + j];
                    acc[r][0] += a * wv.x;
                    acc[r][1] += a * wv.y;
                }
            }
#pragma unroll
            for (int r = 0; r < 8; r++) {
                float* w = ws + (blk * 16 + tr * 8 + r) * 256 + tc * 2;
                w[0] -= acc[r][0];
                w[1] -= acc[r][1];
            }
            __syncthreads();
        }
        {
            int c = tid;
            int i0 = blk * 16;
            for (int i = i0 + 1; i < i0 + 16; i++) {
                float acc = 0.f;
                for (int j = i0; j < i; j++) acc += As[i * ASD + j] * ws[j * 256 + c];
                ws[i * 256 + c] -= acc;
            }
        }
        __syncthreads();
    }

    // attn[i][j] = (q_i . k_j) exp(gc_i - gc_j), j <= i; else 0 (overwrite As)
    {
        float acc[4][4];
#pragma unroll
        for (int r = 0; r < 4; r++)
#pragma unroll
            for (int s = 0; s < 4; s++) acc[r][s] = 0.f;
        const float* qa = qst + ti * 4;
        const float* kb = kst + tj * 4;
#pragma unroll 4
        for (int d = 0; d < 128; d++) {
            float4 a = *(const float4*)(qa + d * KST);
            float4 bq = *(const float4*)(kb + d * KST);
            float ra[4] = {a.x, a.y, a.z, a.w};
            float rb[4] = {bq.x, bq.y, bq.z, bq.w};
#pragma unroll
            for (int r = 0; r < 4; r++)
#pragma unroll
                for (int s = 0; s < 4; s++) acc[r][s] += ra[r] * rb[s];
        }
#pragma unroll
        for (int r = 0; r < 4; r++) {
            int i = ti * 4 + r;
#pragma unroll
            for (int s = 0; s < 4; s++) {
                int j = tj * 4 + s;
                As[i * ASD + j] = (j <= i) ? acc[r][s] * __expf(gc[i] - gc[j]) : 0.f;
            }
        }
    }
    __syncthreads();

    // [L | attn@k_cum] = attn @ ws ;  P = q*e^gc - attn@k_cum
    {
        int tr = warp;
        int tc = lane;
        float acc[8][8];
#pragma unroll
        for (int r = 0; r < 8; r++)
#pragma unroll
            for (int u = 0; u < 8; u++) acc[r][u] = 0.f;
        int jmax = tr * 8 + 8;
        for (int j = 0; j < jmax; j++) {
            float av[8];
#pragma unroll
            for (int r = 0; r < 8; r++) av[r] = As[(tr * 8 + r) * ASD + j];
            float4 w0 = *(const float4*)(ws + j * 256 + tc * 8);
            float4 w1 = *(const float4*)(ws + j * 256 + tc * 8 + 4);
            float rb[8] = {w0.x, w0.y, w0.z, w0.w, w1.x, w1.y, w1.z, w1.w};
#pragma unroll
            for (int r = 0; r < 8; r++)
#pragma unroll
                for (int u = 0; u < 8; u++) acc[r][u] += av[r] * rb[u];
        }
        if (tc < 16) {
#pragma unroll
            for (int r = 0; r < 8; r++) {
                int i = tr * 8 + r;
                float* dst = Lout + ((size_t)cid * 64 + i) * 128 + tc * 8;
                *(float4*)(dst)     = make_float4(acc[r][0], acc[r][1], acc[r][2], acc[r][3]);
                *(float4*)(dst + 4) = make_float4(acc[r][4], acc[r][5], acc[r][6], acc[r][7]);
            }
        } else {
            int c0 = tc * 8 - 128;
#pragma unroll
            for (int r = 0; r < 8; r++) {
                int i = tr * 8 + r;
                float eg = egc[i];
                float v[8];
#pragma unroll
                for (int u = 0; u < 8; u++)
                    v[u] = qst[(c0 + u) * KST + i] * eg - acc[r][u];
                float* dst = Pout + ((size_t)cid * 64 + i) * 128 + c0;
                *(float4*)(dst)     = make_float4(v[0], v[1], v[2], v[3]);
                *(float4*)(dst + 4) = make_float4(v[4], v[5], v[6], v[7]);
            }
        }
    }

    // M = keff^T @ k_cum ; U = keff^T @ v_new ; keff[i][a] = k[i][a]*egr[i]
    {
        int ta = tid >> 4;
        int te = tid & 15;
#pragma unroll
        for (int pass = 0; pass < 2; pass++) {
            float acc[8][8];
#pragma unroll
            for (int r = 0; r < 8; r++)
#pragma unroll
                for (int u = 0; u < 8; u++) acc[r][u] = 0.f;
            for (int i = 0; i < 64; i++) {
                float er = egr[i];
                float av[8];
#pragma unroll
                for (int r = 0; r < 8; r++) av[r] = kst[(ta * 8 + r) * KST + i] * er;
                float4 w0 = *(const float4*)(ws + i * 256 + pass * 128 + te * 8);
                float4 w1 = *(const float4*)(ws + i * 256 + pass * 128 + te * 8 + 4);
                float rb[8] = {w0.x, w0.y, w0.z, w0.w, w1.x, w1.y, w1.z, w1.w};
#pragma unroll
                for (int r = 0; r < 8; r++)
#pragma unroll
                    for (int u = 0; u < 8; u++) acc[r][u] += av[r] * rb[u];
            }
            float* dstb = pass ? Mout : Uout;
#pragma unroll
            for (int r = 0; r < 8; r++) {
                float* dst = dstb + ((size_t)cid * 128 + ta * 8 + r) * 128 + te * 8;
                *(float4*)(dst)     = make_float4(acc[r][0], acc[r][1], acc[r][2], acc[r][3]);
                *(float4*)(dst + 4) = make_float4(acc[r][4], acc[r][5], acc[r][6], acc[r][7]);
            }
        }
    }
    if (tid == 0) eglout[cid] = __expf(gc[63]);
}

// ---------------- Phase B: sequential scan over chunks, DV split ----------------
// Ms/Ps padded to stride 132 (132 % 32 == 4) so the 8 distinct a0 rows per warp
// hit distinct banks (was stride 128 -> 8-way conflicts on every inner load).
#define MSD 132
#define PB_SMEM ((128*MSD + 64*MSD + 128*16) * 4)

__global__ __launch_bounds__(256) void phaseB_kernel(const float* __restrict__ Pm,
        const float* __restrict__ Lm, const float* __restrict__ Mm,
        const float* __restrict__ Um, const float* __restrict__ eglv,
        float* __restrict__ core)
{
    extern __shared__ float sm[];
    float* Ms = sm;                  // 128 x MSD
    float* Ps = Ms + 128 * MSD;      // 64 x MSD
    float* Ss = Ps + 64 * MSD;       // 128 x 16

    int bh = blockIdx.x, gg = blockIdx.y;
    int b = bh >> 3, h = bh & 7;
    int tid = threadIdx.x;
    int c4g = tid & 3;
    int a0 = tid >> 2;
    int c0 = gg * 16;

    for (int i = tid; i < 128 * 16; i += 256) Ss[i] = 0.f;
    __syncthreads();

    for (int n = 0; n < 64; n++) {
        size_t cid = (size_t)bh * 64 + n;
        const float4* Mg = (const float4*)(Mm + cid * 16384);
        for (int i = tid; i < 4096; i += 256) {
            int row = i >> 5, col = (i & 31) * 4;
            *(float4*)(Ms + row * MSD + col) = Mg[i];
        }
        const float4* Pg = (const float4*)(Pm + cid * 8192);
        for (int i = tid; i < 2048; i += 256) {
            int row = i >> 5, col = (i & 31) * 4;
            *(float4*)(Ps + row * MSD + col) = Pg[i];
        }
        __syncthreads();

        // out[i][c] = L[i][c] + sum_a P[i][a] * S[a][c]   (i = a0)
        {
            float4 acc = *(const float4*)(Lm + cid * 8192 + a0 * 128 + c0 + c4g * 4);
            for (int a = 0; a < 128; a++) {
                float p = Ps[a0 * MSD + a];
                float4 s = *(const float4*)(Ss + a * 16 + c4g * 4);
                acc.x += p * s.x; acc.y += p * s.y; acc.z += p * s.z; acc.w += p * s.w;
            }
            int t = n * 64 + a0;
            *(float4*)(core + (((size_t)(b * TT + t)) * 8 + h) * 128 + c0 + c4g * 4) = acc;
        }

        // S' = egl*S + U - M@S  (rows a0 and a0+64)
        float eg = eglv[cid];
        float4 s0 = *(const float4*)(Ss + a0 * 16 + c4g * 4);
        float4 s1 = *(const float4*)(Ss + (a0 + 64) * 16 + c4g * 4);
        float4 ns0 = *(const float4*)(Um + cid * 16384 + (size_t)a0 * 128 + c0 + c4g * 4);
        float4 ns1 = *(const float4*)(Um + cid * 16384 + (size_t)(a0 + 64) * 128 + c0 + c4g * 4);
        ns0.x += eg * s0.x; ns0.y += eg * s0.y; ns0.z += eg * s0.z; ns0.w += eg * s0.w;
        ns1.x += eg * s1.x; ns1.y += eg * s1.y; ns1.z += eg * s1.z; ns1.w += eg * s1.w;
        for (int ap = 0; ap < 128; ap++) {
            float4 s = *(const float4*)(Ss + ap * 16 + c4g * 4);
            float m0 = Ms[a0 * MSD + ap];
            float m1 = Ms[(a0 + 64) * MSD + ap];
            ns0.x -= m0 * s.x; ns0.y -= m0 * s.y; ns0.z -= m0 * s.z; ns0.w -= m0 * s.w;
            ns1.x -= m1 * s.x; ns1.y -= m1 * s.y; ns1.z -= m1 * s.z; ns1.w -= m1 * s.w;
        }
        __syncthreads();
        *(float4*)(Ss + a0 * 16 + c4g * 4) = ns0;
        *(float4*)(Ss + (a0 + 64) * 16 + c4g * 4) = ns1;
        __syncthreads();
    }
}

// ---------------- gated RMSNorm * silu(z) -> bf16 hi/lo --------------------------
__global__ __launch_bounds__(128) void norm_kernel(const float* __restrict__ core,
        const float* __restrict__ qkvz, const float* __restrict__ nw,
        __nv_bfloat16* __restrict__ hh, __nv_bfloat16* __restrict__ hl)
{
    int bth = blockIdx.x;
    int d = threadIdx.x;
    float cv = core[(size_t)bth * 128 + d];
    float ss = cv * cv;
#pragma unroll
    for (int o = 16; o; o >>= 1) ss += __shfl_xor_sync(0xffffffffu, ss, o);
    __shared__ float red[4];
    if ((d & 31) == 0) red[d >> 5] = ss;
    __syncthreads();
    float tot = red[0] + red[1] + red[2] + red[3];
    float r = rsqrtf(tot * (1.f / 128.f) + 1e-6f);
    float zz = qkvz[(size_t)bth * 512 + 384 + d];
    float sz = zz / (1.f + __expf(-zz));
    float hv = nw[d] * cv * r * sz;
    __nv_bfloat16 h = __float2bfloat16_rn(hv);
    size_t o = (size_t)bth * 128 + d;
    hh[o] = h;
    hl[o] = __float2bfloat16_rn(hv - __bfloat162float(h));
}

// ---------------- launch ---------------------------------------------------------
extern "C" void kernel_launch(void* const* d_in, const int* in_sizes, int n_in,
                              void* d_out, int out_size)
{
    (void)in_sizes; (void)n_in; (void)out_size;
    const float* x    = (const float*)d_in[0];
    const float* Wq   = (const float*)d_in[1];
    const float* Wba  = (const float*)d_in[2];
    const float* cw   = (const float*)d_in[3];
    const float* dtb  = (const float*)d_in[4];
    const float* Alog = (const float*)d_in[5];
    const float* nw   = (const float*)d_in[6];
    const float* Wout = (const float*)d_in[7];
    float* out = (float*)d_out;

    float *qkvz, *bab, *convb, *gb, *betab, *Pb, *Lb, *Mb, *Ub, *eglb, *coreb;
    __nv_bfloat16 *xh, *xl, *w1h, *w1l, *w2h, *w2l, *hh, *hl;
    cudaGetSymbolAddress((void**)&qkvz,  g_qkvz);
    cudaGetSymbolAddress((void**)&bab,   g_ba);
    cudaGetSymbolAddress((void**)&convb, g_conv);
    cudaGetSymbolAddress((void**)&gb,    g_g);
    cudaGetSymbolAddress((void**)&betab, g_beta);
    cudaGetSymbolAddress((void**)&Pb,    g_P);
    cudaGetSymbolAddress((void**)&Lb,    g_L);
    cudaGetSymbolAddress((void**)&Mb,    g_M);
    cudaGetSymbolAddress((void**)&Ub,    g_U);
    cudaGetSymbolAddress((void**)&eglb,  g_egl);
    cudaGetSymbolAddress((void**)&coreb, g_core);
    cudaGetSymbolAddress((void**)&xh,  g_xh);
    cudaGetSymbolAddress((void**)&xl,  g_xl);
    cudaGetSymbolAddress((void**)&w1h, g_w1h);
    cudaGetSymbolAddress((void**)&w1l, g_w1l);
    cudaGetSymbolAddress((void**)&w2h, g_w2h);
    cudaGetSymbolAddress((void**)&w2l, g_w2l);
    cudaGetSymbolAddress((void**)&hh,  g_hh);
    cudaGetSymbolAddress((void**)&hl,  g_hl);

    cudaFuncSetAttribute(phaseA_kernel, cudaFuncAttributeMaxDynamicSharedMemorySize, PA_SMEM);
    cudaFuncSetAttribute(phaseB_kernel, cudaFuncAttributeMaxDynamicSharedMemorySize, PB_SMEM);
    cudaFuncSetAttribute(bf16gemm128, cudaFuncAttributeMaxDynamicSharedMemorySize, GEMM_SMEM);

    // 0. operand conversion (bandwidth-bound)
    cvt_split_kernel<<<(BB * TT * CC / 4) / 256, 256>>>(x, xh, xl);
    transpose_split_kernel<<<dim3(4096 / 32, CC / 32), 256>>>(Wq, w1h, w1l, CC, 4096);
    transpose_split_kernel<<<dim3(1024 / 32, CC / 32), 256>>>(Wout, w2h, w2l, CC, 1024);

    // 1. qkvz = x @ W_qkvz
    dim3 g1(4096 / 128, 8192 / 128);
    bf16gemm128<<<g1, 256, GEMM_SMEM>>>(BB * TT, 4096, CC, xh, xl, w1h, w1l, qkvz);
    // 2. ba = x @ W_ba
    ba_kernel<<<BB * TT, 256>>>(x, Wba, bab);
    // 3. conv + silu
    conv_silu_kernel<<<(BB * TT * 3072) / 256, 256>>>(qkvz, cw, convb);
    // 4. g, beta
    gbeta_kernel<<<(BB * TT * NH) / 256, 256>>>(bab, dtb, Alog, gb, betab);
    // 5. phase A
    phaseA_kernel<<<NCID, 256, PA_SMEM>>>(convb, gb, betab, Pb, Lb, Mb, Ub, eglb);
    // 6. phase B
    dim3 gB(16, 8);
    phaseB_kernel<<<gB, 256, PB_SMEM>>>(Pb, Lb, Mb, Ub, eglb, coreb);
    // 7. gated RMSNorm * silu(z) -> bf16 hi/lo
    norm_kernel<<<BB * TT * NH, 128>>>(coreb, qkvz, nw, hh, hl);
    // 8. final projection
    dim3 g2(1024 / 128, 8192 / 128);
    bf16gemm128<<<g2, 256, GEMM_SMEM>>>(BB * TT, 1024, CC, hh, hl, w2h, w2l, out);
}

// round 11
// speedup vs baseline: 1.9253x; 1.0282x over previous
#include <cuda_runtime.h>
#include <cuda_bf16.h>
#include <math.h>

// Problem constants
#define BB 2
#define TT 4096
#define CC 1024
#define NH 8
#define DD 128
#define CHK 64
#define NCHUNK 64            // T / CHK
#define NCID 1024            // BB*NH*NCHUNK

// ---------------- scratch (device globals; no allocation allowed) ----------------
__device__ float g_qkvz[(size_t)BB*TT*4096];     // x @ W_qkvz      (B,T,8,512)
__device__ float g_conv[(size_t)BB*TT*3072];     // conv+silu [q|k|v]
__device__ float g_g[(size_t)BB*TT*NH];
__device__ float g_beta[(size_t)BB*TT*NH];
__device__ float g_P[(size_t)NCID*64*128];       // qeff - attn@k_cum
__device__ float g_L[(size_t)NCID*64*128];       // attn@v_new
__device__ float g_M[(size_t)NCID*128*128];      // keff^T @ k_cum
__device__ float g_U[(size_t)NCID*128*128];      // keff^T @ v_new
__device__ float g_egl[NCID];                    // exp(g_last)
__device__ float g_core[(size_t)BB*TT*NH*DD];    // delta-rule output

// bf16 hi/lo split operands for the two big GEMMs
__device__ __nv_bfloat16 g_xh[(size_t)BB*TT*CC],  g_xl[(size_t)BB*TT*CC];
__device__ __nv_bfloat16 g_w1h[(size_t)4096*CC],  g_w1l[(size_t)4096*CC];   // W_qkvz^T [N][K]
__device__ __nv_bfloat16 g_w2h[(size_t)1024*CC],  g_w2l[(size_t)1024*CC];   // W_out^T  [N][K]
__device__ __nv_bfloat16 g_hh[(size_t)BB*TT*1024], g_hl[(size_t)BB*TT*1024];

// ---------------- split/transpose conversion kernels ----------------------------
__global__ __launch_bounds__(256) void cvt_split_kernel(const float* __restrict__ in,
        __nv_bfloat16* __restrict__ oh, __nv_bfloat16* __restrict__ ol)
{
    int i = blockIdx.x * 256 + threadIdx.x;            // indexes float4
    float4 v = ((const float4*)in)[i];
    float f[4] = {v.x, v.y, v.z, v.w};
    __nv_bfloat16 h[4], l[4];
#pragma unroll
    for (int e = 0; e < 4; e++) {
        h[e] = __float2bfloat16_rn(f[e]);
        l[e] = __float2bfloat16_rn(f[e] - __bfloat162float(h[e]));
    }
    __nv_bfloat162 h0; h0.x = h[0]; h0.y = h[1];
    __nv_bfloat162 h1; h1.x = h[2]; h1.y = h[3];
    __nv_bfloat162 l0; l0.x = l[0]; l0.y = l[1];
    __nv_bfloat162 l1; l1.x = l[2]; l1.y = l[3];
    ((__nv_bfloat162*)oh)[i * 2]     = h0;
    ((__nv_bfloat162*)oh)[i * 2 + 1] = h1;
    ((__nv_bfloat162*)ol)[i * 2]     = l0;
    ((__nv_bfloat162*)ol)[i * 2 + 1] = l1;
}

// W [K][N] f32 -> Wt [N][K] bf16 hi/lo
__global__ __launch_bounds__(256) void transpose_split_kernel(const float* __restrict__ W,
        __nv_bfloat16* __restrict__ oh, __nv_bfloat16* __restrict__ ol, int K, int N)
{
    __shared__ float tile[32][33];
    int n0 = blockIdx.x * 32, k0 = blockIdx.y * 32;
    int tx = threadIdx.x & 31, ty0 = threadIdx.x >> 5;
#pragma unroll
    for (int ty = ty0; ty < 32; ty += 8)
        tile[ty][tx] = W[(size_t)(k0 + ty) * N + n0 + tx];
    __syncthreads();
#pragma unroll
    for (int ty = ty0; ty < 32; ty += 8) {
        float v = tile[tx][ty];
        __nv_bfloat16 h = __float2bfloat16_rn(v);
        size_t o = (size_t)(n0 + ty) * K + k0 + tx;
        oh[o] = h;
        ol[o] = __float2bfloat16_rn(v - __bfloat162float(h));
    }
}

// ---------------- asm helpers ----------------------------------------------------
#define MMA_BF16(C, Ar, Br)                                                    \
    asm volatile("mma.sync.aligned.m16n8k16.row.col.f32.bf16.bf16.f32 "        \
        "{%0,%1,%2,%3}, {%4,%5,%6,%7}, {%8,%9}, {%0,%1,%2,%3};"                \
        : "+f"((C)[0]), "+f"((C)[1]), "+f"((C)[2]), "+f"((C)[3])               \
        : "r"((Ar)[0]), "r"((Ar)[1]), "r"((Ar)[2]), "r"((Ar)[3]),              \
          "r"((Br)[0]), "r"((Br)[1]))

#define LDSM4(R0, R1, R2, R3, ADDR)                                            \
    asm volatile("ldmatrix.sync.aligned.m8n8.x4.shared.b16 {%0,%1,%2,%3}, [%4];" \
        : "=r"(R0), "=r"(R1), "=r"(R2), "=r"(R3) : "r"(ADDR))

#define CP_ASYNC16(DST, SRC)                                                   \
    asm volatile("cp.async.cg.shared.global [%0], [%1], 16;" :: "r"(DST), "l"(SRC))
#define CP_COMMIT() asm volatile("cp.async.commit_group;" ::: "memory")
#define CP_WAIT0()  asm volatile("cp.async.wait_group 0;" ::: "memory")
#define CP_WAIT1()  asm volatile("cp.async.wait_group 1;" ::: "memory")

// ---------------- 3xBF16-split GEMM: C = A(MxK)@B^T(NxK), pre-split bf16 --------
// ldmatrix fragment loads + cp.async double-buffered staging, 2 blocks/SM.
// Inner loop is PRODUCT-MAJOR: all 16 AhBh tiles, then AlBh, then AhBl -- 15
// independent HMMAs between any two dependent ones (same per-tile add order,
// so bit-identical results).
#define GKS 40                                   // bf16 k-stride (80B rows, conflict-free)
#define STG_ELEM (4 * 128 * GKS)                 // elements per stage (4 arrays)
#define STG_BYTES (STG_ELEM * 2)                 // 40960 bytes
#define ARR_BYTES (128 * GKS * 2)                // 10240 bytes per array
#define GEMM_SMEM (2 * STG_BYTES)                // 81920 bytes

__global__ __launch_bounds__(256, 2) void bf16gemm128(int M, int N, int K,
        const __nv_bfloat16* __restrict__ Ah_, const __nv_bfloat16* __restrict__ Al_,
        const __nv_bfloat16* __restrict__ Bth_, const __nv_bfloat16* __restrict__ Btl_,
        float* __restrict__ Cm)
{
    extern __shared__ __nv_bfloat16 gsm[];
    unsigned smemBase = (unsigned)__cvta_generic_to_shared(gsm);

    int tid = threadIdx.x;
    int brow = blockIdx.y * 128, bcol = blockIdx.x * 128;
    int warp = tid >> 5, lane = tid & 31;
    int wm = (warp & 1) * 64, wn = (warp >> 1) * 32;
    int lr = lane >> 2, lc2 = (lane & 3) * 2;

    // staging indices: 2 chunks per thread per array
    int r0s = tid >> 2, kg0 = (tid & 3) * 8;             // u = 0
    int r1s = (tid + 256) >> 2, kg1 = (tid & 3) * 8;     // u = 1 (same kg)
    unsigned d0 = (unsigned)(r0s * GKS + kg0) * 2;
    unsigned d1 = (unsigned)(r1s * GKS + kg1) * 2;
    const __nv_bfloat16* srcA0h = Ah_  + (size_t)(brow + r0s) * K + kg0;
    const __nv_bfloat16* srcA1h = Ah_  + (size_t)(brow + r1s) * K + kg1;
    const __nv_bfloat16* srcA0l = Al_  + (size_t)(brow + r0s) * K + kg0;
    const __nv_bfloat16* srcA1l = Al_  + (size_t)(brow + r1s) * K + kg1;
    const __nv_bfloat16* srcB0h = Bth_ + (size_t)(bcol + r0s) * K + kg0;
    const __nv_bfloat16* srcB1h = Bth_ + (size_t)(bcol + r1s) * K + kg1;
    const __nv_bfloat16* srcB0l = Btl_ + (size_t)(bcol + r0s) * K + kg0;
    const __nv_bfloat16* srcB1l = Btl_ + (size_t)(bcol + r1s) * K + kg1;

    // ldmatrix per-lane byte offsets (within an array)
    unsigned aoff = (unsigned)(((wm + (lane & 15)) * GKS) + ((lane >> 4) * 8)) * 2;
    unsigned boff = (unsigned)(((wn + (lane & 7) + (((lane >> 4) & 1) * 8)) * GKS)
                               + (((lane >> 3) & 1) * 8)) * 2;

    float c[4][4][4];
#pragma unroll
    for (int mt = 0; mt < 4; mt++)
#pragma unroll
        for (int nt = 0; nt < 4; nt++)
#pragma unroll
            for (int e = 0; e < 4; e++) c[mt][nt][e] = 0.f;

    // prologue: stage k0 = 0 into buffer 0
    {
        unsigned sb = smemBase;
        CP_ASYNC16(sb + d0,                 srcA0h);
        CP_ASYNC16(sb + d1,                 srcA1h);
        CP_ASYNC16(sb + ARR_BYTES + d0,     srcA0l);
        CP_ASYNC16(sb + ARR_BYTES + d1,     srcA1l);
        CP_ASYNC16(sb + 2 * ARR_BYTES + d0, srcB0h);
        CP_ASYNC16(sb + 2 * ARR_BYTES + d1, srcB1h);
        CP_ASYNC16(sb + 3 * ARR_BYTES + d0, srcB0l);
        CP_ASYNC16(sb + 3 * ARR_BYTES + d1, srcB1l);
        CP_COMMIT();
    }

    int buf = 0;
    for (int k0 = 0; k0 < K; k0 += 32) {
        bool hasNext = (k0 + 32) < K;
        if (hasNext) {
            unsigned sb = smemBase + (buf ^ 1) * STG_BYTES;
            int kn = k0 + 32;
            CP_ASYNC16(sb + d0,                 srcA0h + kn);
            CP_ASYNC16(sb + d1,                 srcA1h + kn);
            CP_ASYNC16(sb + ARR_BYTES + d0,     srcA0l + kn);
            CP_ASYNC16(sb + ARR_BYTES + d1,     srcA1l + kn);
            CP_ASYNC16(sb + 2 * ARR_BYTES + d0, srcB0h + kn);
            CP_ASYNC16(sb + 2 * ARR_BYTES + d1, srcB1h + kn);
            CP_ASYNC16(sb + 3 * ARR_BYTES + d0, srcB0l + kn);
            CP_ASYNC16(sb + 3 * ARR_BYTES + d1, srcB1l + kn);
            CP_COMMIT();
            CP_WAIT1();
        } else {
            CP_WAIT0();
        }
        __syncthreads();

        unsigned aBh = smemBase + buf * STG_BYTES;
        unsigned aBl = aBh + ARR_BYTES;
        unsigned bBh = aBh + 2 * ARR_BYTES;
        unsigned bBl = aBh + 3 * ARR_BYTES;

#pragma unroll
        for (int kk = 0; kk < 32; kk += 16) {
            unsigned ah[4][4], al[4][4], bh[2][4], bl[2][4];
#pragma unroll
            for (int mt = 0; mt < 4; mt++) {
                unsigned off = aoff + (unsigned)(mt * 16 * GKS + kk) * 2;
                LDSM4(ah[mt][0], ah[mt][1], ah[mt][2], ah[mt][3], aBh + off);
                LDSM4(al[mt][0], al[mt][1], al[mt][2], al[mt][3], aBl + off);
            }
#pragma unroll
            for (int p = 0; p < 2; p++) {
                unsigned off = boff + (unsigned)(p * 16 * GKS + kk) * 2;
                LDSM4(bh[p][0], bh[p][1], bh[p][2], bh[p][3], bBh + off);
                LDSM4(bl[p][0], bl[p][1], bl[p][2], bl[p][3], bBl + off);
            }
            // product-major: maximize distance between dependent HMMAs
#pragma unroll
            for (int mt = 0; mt < 4; mt++)
#pragma unroll
                for (int nt = 0; nt < 4; nt++)
                    MMA_BF16(c[mt][nt], ah[mt], (&bh[nt >> 1][(nt & 1) * 2]));
#pragma unroll
            for (int mt = 0; mt < 4; mt++)
#pragma unroll
                for (int nt = 0; nt < 4; nt++)
                    MMA_BF16(c[mt][nt], al[mt], (&bh[nt >> 1][(nt & 1) * 2]));
#pragma unroll
            for (int mt = 0; mt < 4; mt++)
#pragma unroll
                for (int nt = 0; nt < 4; nt++)
                    MMA_BF16(c[mt][nt], ah[mt], (&bl[nt >> 1][(nt & 1) * 2]));
        }
        __syncthreads();
        buf ^= 1;
    }

#pragma unroll
    for (int mt = 0; mt < 4; mt++) {
        int r0 = brow + wm + mt * 16 + lr;
#pragma unroll
        for (int nt = 0; nt < 4; nt++) {
            int cn = bcol + wn + nt * 8 + lc2;
            *(float2*)(Cm + (size_t)r0 * N + cn)       = make_float2(c[mt][nt][0], c[mt][nt][1]);
            *(float2*)(Cm + (size_t)(r0 + 8) * N + cn) = make_float2(c[mt][nt][2], c[mt][nt][3]);
        }
    }
}

// ---------------- fused ba = x @ W_ba -> g, beta ---------------------------------
__global__ __launch_bounds__(256) void ba_gbeta_kernel(const float* __restrict__ x,
        const float* __restrict__ Wba, const float* __restrict__ dtb,
        const float* __restrict__ Alog, float* __restrict__ g, float* __restrict__ beta)
{
    int bt = blockIdx.x;
    __shared__ float xs[1024];
    const float* xrow = x + (size_t)bt * 1024;
    for (int i = threadIdx.x; i < 256; i += 256)
        ((float4*)xs)[i] = ((const float4*)xrow)[i];
    __syncthreads();
    int o = threadIdx.x >> 4, p = threadIdx.x & 15;
    float acc = 0.f;
    for (int k = p; k < 1024; k += 16) acc += xs[k] * Wba[(size_t)k * 16 + o];
    acc += __shfl_down_sync(0xffffffffu, acc, 8);
    acc += __shfl_down_sync(0xffffffffu, acc, 4);
    acc += __shfl_down_sync(0xffffffffu, acc, 2);
    acc += __shfl_down_sync(0xffffffffu, acc, 1);
    if (p == 0) {
        int h = o >> 1;
        if ((o & 1) == 0) {
            beta[(size_t)bt * 8 + h] = 1.f / (1.f + expf(-acc));
        } else {
            float xx = acc + dtb[h];
            float sp = (xx > 20.f) ? xx : log1pf(expf(xx));
            g[(size_t)bt * 8 + h] = -expf(Alog[h]) * sp;
        }
    }
}

// ---------------- causal depthwise conv (K=4) + silu ----------------------------
__global__ __launch_bounds__(256) void conv_silu_kernel(const float* __restrict__ qkvz,
        const float* __restrict__ cw, float* __restrict__ out)
{
    int idx = blockIdx.x * 256 + threadIdx.x;
    int ch = idx % 3072;
    int btrow = idx / 3072;
    int t = btrow & (TT - 1);
    int part = ch >> 10;
    int hc = (ch & 1023) >> 7;
    int d = ch & 127;
    int po = (part == 0) ? 0 : (part == 1) ? 128 : 256;
    float acc = 0.f;
#pragma unroll
    for (int j = 0; j < 4; j++) {
        int tt2 = t - 3 + j;
        if (tt2 >= 0) {
            float v = qkvz[(((size_t)(btrow - 3 + j)) * 8 + hc) * 512 + po + d];
            acc += v * cw[ch * 4 + j];
        }
    }
    out[(size_t)idx] = acc / (1.f + __expf(-acc));
}

// ---------------- Phase A: per-chunk local operators (register-tiled) -----------
#define KST 68
#define ASD 65
#define PA_SMEM ((128*KST*2 + 64*256 + 64*ASD + 256) * 4)

__global__ __launch_bounds__(256) void phaseA_kernel(const float* __restrict__ conv,
        const float* __restrict__ gbuf, const float* __restrict__ betabuf,
        float* __restrict__ Pout, float* __restrict__ Lout,
        float* __restrict__ Mout, float* __restrict__ Uout, float* __restrict__ eglout)
{
    extern __shared__ float sm[];
    float* kst = sm;
    float* qst = kst + 128 * KST;
    float* ws  = qst + 128 * KST;
    float* As  = ws + 64 * 256;          // 64 x ASD
    float* gc  = As + 64 * ASD;
    float* egc = gc + 64;
    float* egr = egc + 64;
    float* bts = egr + 64;

    int cid = blockIdx.x;
    int n = cid & 63, bh = cid >> 6, h = bh & 7, b = bh >> 3;
    int tid = threadIdx.x;
    int warp = tid >> 5, lane = tid & 31;
    int t0 = n * 64;

    if (tid < 64) {
        int t = t0 + tid;
        gc[tid]  = gbuf[((size_t)(b * TT + t)) * 8 + h];
        bts[tid] = betabuf[((size_t)(b * TT + t)) * 8 + h];
    }
    __syncthreads();
#pragma unroll
    for (int off = 1; off < 64; off <<= 1) {
        float v = 0.f;
        if (tid < 64 && tid >= off) v = gc[tid - off];
        __syncthreads();
        if (tid < 64 && tid >= off) gc[tid] += v;
        __syncthreads();
    }
    if (tid < 64) {
        egc[tid] = __expf(gc[tid]);
        egr[tid] = __expf(gc[63] - gc[tid]);
    }
    __syncthreads();

    for (int r = warp; r < 64; r += 8) {
        int t = t0 + r;
        const float* base = conv + ((size_t)(b * TT + t)) * 3072 + h * 128;
        float qv[4], kv[4];
        float ssq = 0.f, ssk = 0.f;
#pragma unroll
        for (int u = 0; u < 4; u++) {
            qv[u] = base[lane + u * 32];
            kv[u] = base[1024 + lane + u * 32];
            ssq += qv[u] * qv[u];
            ssk += kv[u] * kv[u];
        }
#pragma unroll
        for (int off = 16; off; off >>= 1) {
            ssq += __shfl_xor_sync(0xffffffffu, ssq, off);
            ssk += __shfl_xor_sync(0xffffffffu, ssk, off);
        }
        float rq = rsqrtf(ssq + 1e-6f) * 0.08838834764831845f;
        float rk = rsqrtf(ssk + 1e-6f);
        float bbv = bts[r], egv = egc[r];
#pragma unroll
        for (int u = 0; u < 4; u++) {
            int d = lane + u * 32;
            qst[d * KST + r] = qv[u] * rq;
            float kn = kv[u] * rk;
            kst[d * KST + r] = kn;
            ws[r * 256 + d]       = base[2048 + d] * bbv;
            ws[r * 256 + 128 + d] = kn * bbv * egv;
        }
    }
    __syncthreads();

    int ti = tid >> 4, tj = tid & 15;

    // A[i][j] = beta_i (k_i . k_j) exp(gc_i - gc_j), j < i; else 0
    {
        float acc[4][4];
#pragma unroll
        for (int r = 0; r < 4; r++)
#pragma unroll
            for (int s = 0; s < 4; s++) acc[r][s] = 0.f;
        const float* ka = kst + ti * 4;
        const float* kb = kst + tj * 4;
#pragma unroll 4
        for (int d = 0; d < 128; d++) {
            float4 a = *(const float4*)(ka + d * KST);
            float4 bq = *(const float4*)(kb + d * KST);
            float ra[4] = {a.x, a.y, a.z, a.w};
            float rb[4] = {bq.x, bq.y, bq.z, bq.w};
#pragma unroll
            for (int r = 0; r < 4; r++)
#pragma unroll
                for (int s = 0; s < 4; s++) acc[r][s] += ra[r] * rb[s];
        }
#pragma unroll
        for (int r = 0; r < 4; r++) {
            int i = ti * 4 + r;
#pragma unroll
            for (int s = 0; s < 4; s++) {
                int j = tj * 4 + s;
                As[i * ASD + j] = (j < i) ? acc[r][s] * bts[i] * __expf(gc[i] - gc[j]) : 0.f;
            }
        }
    }
    __syncthreads();

    // blocked forward substitution: ws <- (I+A)^{-1} ws
    for (int blk = 0; blk < 4; blk++) {
        if (blk) {
            int tr = tid >> 7, tc = tid & 127;
            float acc[8][2];
#pragma unroll
            for (int r = 0; r < 8; r++) { acc[r][0] = 0.f; acc[r][1] = 0.f; }
            for (int j = 0; j < blk * 16; j++) {
                float2 wv = *(const float2*)(ws + j * 256 + tc * 2);
#pragma unroll
                for (int r = 0; r < 8; r++) {
                    float a = As[(blk * 16 + tr * 8 + r) * ASD + j];
                    acc[r][0] += a * wv.x;
                    acc[r][1] += a * wv.y;
                }
            }
#pragma unroll
            for (int r = 0; r < 8; r++) {
                float* w = ws + (blk * 16 + tr * 8 + r) * 256 + tc * 2;
                w[0] -= acc[r][0];
                w[1] -= acc[r][1];
            }
            __syncthreads();
        }
        {
            int c = tid;
            int i0 = blk * 16;
            for (int i = i0 + 1; i < i0 + 16; i++) {
                float acc = 0.f;
                for (int j = i0; j < i; j++) acc += As[i * ASD + j] * ws[j * 256 + c];
                ws[i * 256 + c] -= acc;
            }
        }
        __syncthreads();
    }

    // attn[i][j] = (q_i . k_j) exp(gc_i - gc_j), j <= i; else 0 (overwrite As)
    {
        float acc[4][4];
#pragma unroll
        for (int r = 0; r < 4; r++)
#pragma unroll
            for (int s = 0; s < 4; s++) acc[r][s] = 0.f;
        const float* qa = qst + ti * 4;
        const float* kb = kst + tj * 4;
#pragma unroll 4
        for (int d = 0; d < 128; d++) {
            float4 a = *(const float4*)(qa + d * KST);
            float4 bq = *(const float4*)(kb + d * KST);
            float ra[4] = {a.x, a.y, a.z, a.w};
            float rb[4] = {bq.x, bq.y, bq.z, bq.w};
#pragma unroll
            for (int r = 0; r < 4; r++)
#pragma unroll
                for (int s = 0; s < 4; s++) acc[r][s] += ra[r] * rb[s];
        }
#pragma unroll
        for (int r = 0; r < 4; r++) {
            int i = ti * 4 + r;
#pragma unroll
            for (int s = 0; s < 4; s++) {
                int j = tj * 4 + s;
                As[i * ASD + j] = (j <= i) ? acc[r][s] * __expf(gc[i] - gc[j]) : 0.f;
            }
        }
    }
    __syncthreads();

    // [L | attn@k_cum] = attn @ ws ;  P = q*e^gc - attn@k_cum
    {
        int tr = warp;
        int tc = lane;
        float acc[8][8];
#pragma unroll
        for (int r = 0; r < 8; r++)
#pragma unroll
            for (int u = 0; u < 8; u++) acc[r][u] = 0.f;
        int jmax = tr * 8 + 8;
        for (int j = 0; j < jmax; j++) {
            float av[8];
#pragma unroll
            for (int r = 0; r < 8; r++) av[r] = As[(tr * 8 + r) * ASD + j];
            float4 w0 = *(const float4*)(ws + j * 256 + tc * 8);
            float4 w1 = *(const float4*)(ws + j * 256 + tc * 8 + 4);
            float rb[8] = {w0.x, w0.y, w0.z, w0.w, w1.x, w1.y, w1.z, w1.w};
#pragma unroll
            for (int r = 0; r < 8; r++)
#pragma unroll
                for (int u = 0; u < 8; u++) acc[r][u] += av[r] * rb[u];
        }
        if (tc < 16) {
#pragma unroll
            for (int r = 0; r < 8; r++) {
                int i = tr * 8 + r;
                float* dst = Lout + ((size_t)cid * 64 + i) * 128 + tc * 8;
                *(float4*)(dst)     = make_float4(acc[r][0], acc[r][1], acc[r][2], acc[r][3]);
                *(float4*)(dst + 4) = make_float4(acc[r][4], acc[r][5], acc[r][6], acc[r][7]);
            }
        } else {
            int c0 = tc * 8 - 128;
#pragma unroll
            for (int r = 0; r < 8; r++) {
                int i = tr * 8 + r;
                float eg = egc[i];
                float v[8];
#pragma unroll
                for (int u = 0; u < 8; u++)
                    v[u] = qst[(c0 + u) * KST + i] * eg - acc[r][u];
                float* dst = Pout + ((size_t)cid * 64 + i) * 128 + c0;
                *(float4*)(dst)     = make_float4(v[0], v[1], v[2], v[3]);
                *(float4*)(dst + 4) = make_float4(v[4], v[5], v[6], v[7]);
            }
        }
    }

    // M = keff^T @ k_cum ; U = keff^T @ v_new ; keff[i][a] = k[i][a]*egr[i]
    {
        int ta = tid >> 4;
        int te = tid & 15;
#pragma unroll
        for (int pass = 0; pass < 2; pass++) {
            float acc[8][8];
#pragma unroll
            for (int r = 0; r < 8; r++)
#pragma unroll
                for (int u = 0; u < 8; u++) acc[r][u] = 0.f;
            for (int i = 0; i < 64; i++) {
                float er = egr[i];
                float av[8];
#pragma unroll
                for (int r = 0; r < 8; r++) av[r] = kst[(ta * 8 + r) * KST + i] * er;
                float4 w0 = *(const float4*)(ws + i * 256 + pass * 128 + te * 8);
                float4 w1 = *(const float4*)(ws + i * 256 + pass * 128 + te * 8 + 4);
                float rb[8] = {w0.x, w0.y, w0.z, w0.w, w1.x, w1.y, w1.z, w1.w};
#pragma unroll
                for (int r = 0; r < 8; r++)
#pragma unroll
                    for (int u = 0; u < 8; u++) acc[r][u] += av[r] * rb[u];
            }
            float* dstb = pass ? Mout : Uout;
#pragma unroll
            for (int r = 0; r < 8; r++) {
                float* dst = dstb + ((size_t)cid * 128 + ta * 8 + r) * 128 + te * 8;
                *(float4*)(dst)     = make_float4(acc[r][0], acc[r][1], acc[r][2], acc[r][3]);
                *(float4*)(dst + 4) = make_float4(acc[r][4], acc[r][5], acc[r][6], acc[r][7]);
            }
        }
    }
    if (tid == 0) eglout[cid] = __expf(gc[63]);
}

// ---------------- Phase B: sequential scan over chunks, DV split ----------------
#define MSD 132
#define PB_SMEM ((128*MSD + 64*MSD + 128*16) * 4)

__global__ __launch_bounds__(256) void phaseB_kernel(const float* __restrict__ Pm,
        const float* __restrict__ Lm, const float* __restrict__ Mm,
        const float* __restrict__ Um, const float* __restrict__ eglv,
        float* __restrict__ core)
{
    extern __shared__ float sm[];
    float* Ms = sm;                  // 128 x MSD
    float* Ps = Ms + 128 * MSD;      // 64 x MSD
    float* Ss = Ps + 64 * MSD;       // 128 x 16

    int bh = blockIdx.x, gg = blockIdx.y;
    int b = bh >> 3, h = bh & 7;
    int tid = threadIdx.x;
    int c4g = tid & 3;
    int a0 = tid >> 2;
    int c0 = gg * 16;

    for (int i = tid; i < 128 * 16; i += 256) Ss[i] = 0.f;
    __syncthreads();

    for (int n = 0; n < 64; n++) {
        size_t cid = (size_t)bh * 64 + n;
        const float4* Mg = (const float4*)(Mm + cid * 16384);
        for (int i = tid; i < 4096; i += 256) {
            int row = i >> 5, col = (i & 31) * 4;
            *(float4*)(Ms + row * MSD + col) = Mg[i];
        }
        const float4* Pg = (const float4*)(Pm + cid * 8192);
        for (int i = tid; i < 2048; i += 256) {
            int row = i >> 5, col = (i & 31) * 4;
            *(float4*)(Ps + row * MSD + col) = Pg[i];
        }
        __syncthreads();

        // out[i][c] = L[i][c] + sum_a P[i][a] * S[a][c]   (i = a0)
        {
            float4 acc = *(const float4*)(Lm + cid * 8192 + a0 * 128 + c0 + c4g * 4);
            for (int a = 0; a < 128; a++) {
                float p = Ps[a0 * MSD + a];
                float4 s = *(const float4*)(Ss + a * 16 + c4g * 4);
                acc.x += p * s.x; acc.y += p * s.y; acc.z += p * s.z; acc.w += p * s.w;
            }
            int t = n * 64 + a0;
            *(float4*)(core + (((size_t)(b * TT + t)) * 8 + h) * 128 + c0 + c4g * 4) = acc;
        }

        // S' = egl*S + U - M@S  (rows a0 and a0+64)
        float eg = eglv[cid];
        float4 s0 = *(const float4*)(Ss + a0 * 16 + c4g * 4);
        float4 s1 = *(const float4*)(Ss + (a0 + 64) * 16 + c4g * 4);
        float4 ns0 = *(const float4*)(Um + cid * 16384 + (size_t)a0 * 128 + c0 + c4g * 4);
        float4 ns1 = *(const float4*)(Um + cid * 16384 + (size_t)(a0 + 64) * 128 + c0 + c4g * 4);
        ns0.x += eg * s0.x; ns0.y += eg * s0.y; ns0.z += eg * s0.z; ns0.w += eg * s0.w;
        ns1.x += eg * s1.x; ns1.y += eg * s1.y; ns1.z += eg * s1.z; ns1.w += eg * s1.w;
        for (int ap = 0; ap < 128; ap++) {
            float4 s = *(const float4*)(Ss + ap * 16 + c4g * 4);
            float m0 = Ms[a0 * MSD + ap];
            float m1 = Ms[(a0 + 64) * MSD + ap];
            ns0.x -= m0 * s.x; ns0.y -= m0 * s.y; ns0.z -= m0 * s.z; ns0.w -= m0 * s.w;
            ns1.x -= m1 * s.x; ns1.y -= m1 * s.y; ns1.z -= m1 * s.z; ns1.w -= m1 * s.w;
        }
        __syncthreads();
        *(float4*)(Ss + a0 * 16 + c4g * 4) = ns0;
        *(float4*)(Ss + (a0 + 64) * 16 + c4g * 4) = ns1;
        __syncthreads();
    }
}

// ---------------- gated RMSNorm * silu(z) -> bf16 hi/lo --------------------------
__global__ __launch_bounds__(128) void norm_kernel(const float* __restrict__ core,
        const float* __restrict__ qkvz, const float* __restrict__ nw,
        __nv_bfloat16* __restrict__ hh, __nv_bfloat16* __restrict__ hl)
{
    int bth = blockIdx.x;
    int d = threadIdx.x;
    float cv = core[(size_t)bth * 128 + d];
    float ss = cv * cv;
#pragma unroll
    for (int o = 16; o; o >>= 1) ss += __shfl_xor_sync(0xffffffffu, ss, o);
    __shared__ float red[4];
    if ((d & 31) == 0) red[d >> 5] = ss;
    __syncthreads();
    float tot = red[0] + red[1] + red[2] + red[3];
    float r = rsqrtf(tot * (1.f / 128.f) + 1e-6f);
    float zz = qkvz[(size_t)bth * 512 + 384 + d];
    float sz = zz / (1.f + __expf(-zz));
    float hv = nw[d] * cv * r * sz;
    __nv_bfloat16 h = __float2bfloat16_rn(hv);
    size_t o = (size_t)bth * 128 + d;
    hh[o] = h;
    hl[o] = __float2bfloat16_rn(hv - __bfloat162float(h));
}

// ---------------- launch ---------------------------------------------------------
extern "C" void kernel_launch(void* const* d_in, const int* in_sizes, int n_in,
                              void* d_out, int out_size)
{
    (void)in_sizes; (void)n_in; (void)out_size;
    const float* x    = (const float*)d_in[0];
    const float* Wq   = (const float*)d_in[1];
    const float* Wba  = (const float*)d_in[2];
    const float* cw   = (const float*)d_in[3];
    const float* dtb  = (const float*)d_in[4];
    const float* Alog = (const float*)d_in[5];
    const float* nw   = (const float*)d_in[6];
    const float* Wout = (const float*)d_in[7];
    float* out = (float*)d_out;

    float *qkvz, *convb, *gb, *betab, *Pb, *Lb, *Mb, *Ub, *eglb, *coreb;
    __nv_bfloat16 *xh, *xl, *w1h, *w1l, *w2h, *w2l, *hh, *hl;
    cudaGetSymbolAddress((void**)&qkvz,  g_qkvz);
    cudaGetSymbolAddress((void**)&convb, g_conv);
    cudaGetSymbolAddress((void**)&gb,    g_g);
    cudaGetSymbolAddress((void**)&betab, g_beta);
    cudaGetSymbolAddress((void**)&Pb,    g_P);
    cudaGetSymbolAddress((void**)&Lb,    g_L);
    cudaGetSymbolAddress((void**)&Mb,    g_M);
    cudaGetSymbolAddress((void**)&Ub,    g_U);
    cudaGetSymbolAddress((void**)&eglb,  g_egl);
    cudaGetSymbolAddress((void**)&coreb, g_core);
    cudaGetSymbolAddress((void**)&xh,  g_xh);
    cudaGetSymbolAddress((void**)&xl,  g_xl);
    cudaGetSymbolAddress((void**)&w1h, g_w1h);
    cudaGetSymbolAddress((void**)&w1l, g_w1l);
    cudaGetSymbolAddress((void**)&w2h, g_w2h);
    cudaGetSymbolAddress((void**)&w2l, g_w2l);
    cudaGetSymbolAddress((void**)&hh,  g_hh);
    cudaGetSymbolAddress((void**)&hl,  g_hl);

    cudaFuncSetAttribute(phaseA_kernel, cudaFuncAttributeMaxDynamicSharedMemorySize, PA_SMEM);
    cudaFuncSetAttribute(phaseB_kernel, cudaFuncAttributeMaxDynamicSharedMemorySize, PB_SMEM);
    cudaFuncSetAttribute(bf16gemm128, cudaFuncAttributeMaxDynamicSharedMemorySize, GEMM_SMEM);

    // 0. operand conversion (bandwidth-bound)
    cvt_split_kernel<<<(BB * TT * CC / 4) / 256, 256>>>(x, xh, xl);
    transpose_split_kernel<<<dim3(4096 / 32, CC / 32), 256>>>(Wq, w1h, w1l, CC, 4096);
    transpose_split_kernel<<<dim3(1024 / 32, CC / 32), 256>>>(Wout, w2h, w2l, CC, 1024);

    // 1. qkvz = x @ W_qkvz
    dim3 g1(4096 / 128, 8192 / 128);
    bf16gemm128<<<g1, 256, GEMM_SMEM>>>(BB * TT, 4096, CC, xh, xl, w1h, w1l, qkvz);
    // 2. ba = x @ W_ba fused with g/beta
    ba_gbeta_kernel<<<BB * TT, 256>>>(x, Wba, dtb, Alog, gb, betab);
    // 3. conv + silu
    conv_silu_kernel<<<(BB * TT * 3072) / 256, 256>>>(qkvz, cw, convb);
    // 4. phase A
    phaseA_kernel<<<NCID, 256, PA_SMEM>>>(convb, gb, betab, Pb, Lb, Mb, Ub, eglb);
    // 5. phase B
    dim3 gB(16, 8);
    phaseB_kernel<<<gB, 256, PB_SMEM>>>(Pb, Lb, Mb, Ub, eglb, coreb);
    // 6. gated RMSNorm * silu(z) -> bf16 hi/lo
    norm_kernel<<<BB * TT * NH, 128>>>(coreb, qkvz, nw, hh, hl);
    // 7. final projection
    dim3 g2(1024 / 128, 8192 / 128);
    bf16gemm128<<<g2, 256, GEMM_SMEM>>>(BB * TT, 1024, CC, hh, hl, w2h, w2l, out);
}